// round 3
// baseline (speedup 1.0000x reference)
#include <cuda_runtime.h>
#include <cuda_bf16.h>
#include <math.h>

#define NN 50000
#define EE 800000
#define ET (EE + NN)   // edges + self loops
#define FIN0 128
#define KP 264         // A smem row pitch (bf16) : conflict-free fragment loads
#define KB 20          // B smem row pitch (bf16)

// ---------------- scratch (device globals; no allocation allowed) ----------------
__device__ float d_T1[128 * 512];     // weight_d @ H_d_base
__device__ float d_M[128 * 16];       // combined dual weight
__device__ int   d_deg[NN];
__device__ int   d_rowoff[NN + 1];
__device__ int   d_cursor[NN];
__device__ float d_dis[NN];
__device__ int   d_csr[ET];
__device__ float d_xw[NN * 16];
__device__ float d_dual[NN * 16];
__device__ float d_h0[NN * 16];
__device__ float d_h1[NN * 256];      // per-layer transformed features
__device__ float d_bufA[NN * 256];
__device__ float d_bufB[NN * 256];
__device__ float d_sa[NN * 16];
__device__ float d_da[NN * 16];
__device__ __nv_bfloat16 d_WThi[256 * 256];  // W^T split hi  [n][k]
__device__ __nv_bfloat16 d_WTlo[256 * 256];  // W^T split lo  [n][k]

// ---------------- init ----------------
__global__ void k_init() {
    int i = blockIdx.x * blockDim.x + threadIdx.x;
    if (i < NN) { d_deg[i] = 1; d_cursor[i] = 0; }   // deg starts at 1 (self loop)
}

// ---------------- combined dual weight: M = Wd @ Hd @ Wr ----------------
__global__ void k_gemm1(const float* __restrict__ wd, const float* __restrict__ hd) {
    int idx = blockIdx.x * blockDim.x + threadIdx.x;  // 128*512
    if (idx >= 128 * 512) return;
    int i = idx >> 9, j = idx & 511;
    float a = 0.f;
    for (int k = 0; k < 512; k++) a += wd[i * 512 + k] * hd[k * 512 + j];
    d_T1[idx] = a;
}

__global__ void k_gemm2(const float* __restrict__ wr) {
    int idx = blockIdx.x * blockDim.x + threadIdx.x;  // 128*16
    if (idx >= 128 * 16) return;
    int i = idx >> 4, j = idx & 15;
    float a = 0.f;
    for (int k = 0; k < 512; k++) a += d_T1[i * 512 + k] * wr[k * 16 + j];
    d_M[idx] = a;
}

// ---------------- degree count ----------------
__global__ void k_count(const int* __restrict__ dst) {
    int e = blockIdx.x * blockDim.x + threadIdx.x;
    if (e < EE) atomicAdd(&d_deg[dst[e]], 1);
}

// ---------------- warp-shuffle scan (+ fused rsqrt degree) ----------------
__global__ void k_scan() {  // one block, 1024 threads
    __shared__ int warp_sums[32];
    int t = threadIdx.x;
    const int S = 49;                       // 1024*49 >= NN
    int b0 = t * S;
    int sum = 0;
    for (int i = 0; i < S; i++) {
        int idx = b0 + i;
        if (idx < NN) sum += d_deg[idx];
    }
    int lane = t & 31, w = t >> 5;
    int v = sum;
#pragma unroll
    for (int off = 1; off < 32; off <<= 1) {
        int u = __shfl_up_sync(0xffffffffu, v, off);
        if (lane >= off) v += u;
    }
    if (lane == 31) warp_sums[w] = v;
    __syncthreads();
    if (w == 0) {
        int ws = warp_sums[lane];
#pragma unroll
        for (int off = 1; off < 32; off <<= 1) {
            int u = __shfl_up_sync(0xffffffffu, ws, off);
            if (lane >= off) ws += u;
        }
        warp_sums[lane] = ws;
    }
    __syncthreads();
    int ex = v - sum + (w > 0 ? warp_sums[w - 1] : 0);
    int run = ex;
    for (int i = 0; i < S; i++) {
        int idx = b0 + i;
        if (idx < NN) {
            int dg = d_deg[idx];
            run += dg;
            d_rowoff[idx + 1] = run;
            d_dis[idx] = rsqrtf((float)dg);
        }
    }
    if (t == 0) d_rowoff[0] = 0;
}

__global__ void k_scatter(const int* __restrict__ ei) {
    int e = blockIdx.x * blockDim.x + threadIdx.x;
    if (e >= ET) return;
    int s, dd;
    if (e < EE) { s = ei[e]; dd = ei[EE + e]; }
    else        { s = dd = e - EE; }
    int p = atomicAdd(&d_cursor[dd], 1);
    d_csr[d_rowoff[dd] + p] = s;
}

// ---------------- GCN feature transform + dual (fused) ----------------
__global__ void k_xw_dual(const float* __restrict__ x, const float* __restrict__ Wg) {
    int idx = blockIdx.x * blockDim.x + threadIdx.x;  // NN*16
    if (idx >= NN * 16) return;
    int n = idx >> 4, j = idx & 15;
    float a = 0.f, b = 0.f;
    const float* xr = x + n * FIN0;
    for (int k = 0; k < FIN0; k++) {
        float xv = xr[k];
        a += xv * Wg[k * 16 + j];
        b += xv * d_M[k * 16 + j];
    }
    d_xw[idx] = a;
    d_dual[idx] = b;
}

// ---------------- GCN aggregation + dual + elu -> h0 ----------------
__global__ void k_gcn_agg(const float* __restrict__ bg) {
    int g = (blockIdx.x * blockDim.x + threadIdx.x) >> 4;
    int j = threadIdx.x & 15;
    if (g >= NN) return;
    int beg = d_rowoff[g], end = d_rowoff[g + 1];
    float acc = 0.f;
    for (int e = beg; e < end; e++) {
        int s = d_csr[e];
        acc += d_dis[s] * d_xw[s * 16 + j];
    }
    float v = acc * d_dis[g] + bg[j] + d_dual[g * 16 + j];
    d_h0[g * 16 + j] = v > 0.f ? v : (__expf(v) - 1.f);
}

// ---------------- GAT layer-1 transform (FIN=16, FFMA; cheap) ----------------
__global__ void __launch_bounds__(128, 8)
k_transform16(const float* __restrict__ hin, const float* __restrict__ W,
              const float* __restrict__ asrc, const float* __restrict__ adst) {
    __shared__ float s[16][16];
    int tid = threadIdx.x;
    int nb = blockIdx.x * 16;
    const float4* hin4 = (const float4*)(hin + nb * 16);
    float4* s4 = (float4*)s;
    for (int t = tid; t < 16 * 16 / 4; t += 128) s4[t] = hin4[t];
    __syncthreads();

    int cg = tid & 63;   // col group: cols [4*cg, 4*cg+4)
    int ng = tid >> 6;   // node group: nodes [8*ng, 8*ng+8)
    const float4* W4 = (const float4*)W;
    float4 acc[8];
#pragma unroll
    for (int r = 0; r < 8; r++) acc[r] = make_float4(0.f, 0.f, 0.f, 0.f);

#pragma unroll
    for (int k = 0; k < 16; k++) {
        float4 w = W4[k * 64 + cg];
#pragma unroll
        for (int r = 0; r < 8; r++) {
            float sv = s[ng * 8 + r][k];
            acc[r].x += sv * w.x; acc[r].y += sv * w.y;
            acc[r].z += sv * w.z; acc[r].w += sv * w.w;
        }
    }

    float4 as4 = ((const float4*)asrc)[cg];
    float4 ad4 = ((const float4*)adst)[cg];
#pragma unroll
    for (int r = 0; r < 8; r++) {
        int n = nb + ng * 8 + r;
        if (n >= NN) break;
        ((float4*)(d_h1 + n * 256))[cg] = acc[r];
        float vs = acc[r].x * as4.x + acc[r].y * as4.y + acc[r].z * as4.z + acc[r].w * as4.w;
        float vd = acc[r].x * ad4.x + acc[r].y * ad4.y + acc[r].z * ad4.z + acc[r].w * ad4.w;
        vs += __shfl_down_sync(0xffffffffu, vs, 2, 4);
        vs += __shfl_down_sync(0xffffffffu, vs, 1, 4);
        vd += __shfl_down_sync(0xffffffffu, vd, 2, 4);
        vd += __shfl_down_sync(0xffffffffu, vd, 1, 4);
        if ((cg & 3) == 0) {
            int h = cg >> 2;
            d_sa[n * 16 + h] = vs;
            d_da[n * 16 + h] = vd;
        }
    }
}

// ---------------- W prep: transpose + bf16 split ----------------
__global__ void k_prepW(const float* __restrict__ W) {
    int idx = blockIdx.x * blockDim.x + threadIdx.x;  // 65536
    if (idx >= 256 * 256) return;
    int n = idx >> 8, k = idx & 255;
    float w = W[k * 256 + n];
    __nv_bfloat16 h = __float2bfloat16_rn(w);
    d_WThi[n * 256 + k] = h;
    d_WTlo[n * 256 + k] = __float2bfloat16_rn(w - __bfloat162float(h));
}

// ---------------- tensor-core transform: d_h1 = hin @ W (bf16x3 split) ----------------
#define MMA_BF16(C, A0, A1, A2, A3, B0, B1)                                  \
    asm volatile(                                                            \
        "mma.sync.aligned.m16n8k16.row.col.f32.bf16.bf16.f32 "               \
        "{%0,%1,%2,%3}, {%4,%5,%6,%7}, {%8,%9}, {%0,%1,%2,%3};\n"            \
        : "+f"(C[0]), "+f"(C[1]), "+f"(C[2]), "+f"(C[3])                     \
        : "r"(A0), "r"(A1), "r"(A2), "r"(A3), "r"(B0), "r"(B1))

__global__ void __launch_bounds__(256)
k_transform_mma(const float* __restrict__ hin) {
    extern __shared__ __nv_bfloat16 sm[];
    __nv_bfloat16* sAhi = sm;                       // 32*KP
    __nv_bfloat16* sAlo = sAhi + 32 * KP;
    __nv_bfloat16* sBhi = sAlo + 32 * KP;           // 256*KB
    __nv_bfloat16* sBlo = sBhi + 256 * KB;

    int tid = threadIdx.x, lane = tid & 31, warp = tid >> 5;
    int nb = blockIdx.x * 32;

    // stage A tile (32 nodes x 256), split hi/lo
    for (int i = tid; i < 32 * 64; i += 256) {
        int row = i >> 6, c4 = i & 63;
        int node = nb + row;
        float4 v = make_float4(0.f, 0.f, 0.f, 0.f);
        if (node < NN) v = ((const float4*)(hin + (size_t)node * 256))[c4];
        int base = row * KP + c4 * 4;
        float f[4] = {v.x, v.y, v.z, v.w};
#pragma unroll
        for (int j = 0; j < 4; j++) {
            __nv_bfloat16 h = __float2bfloat16_rn(f[j]);
            sAhi[base + j] = h;
            sAlo[base + j] = __float2bfloat16_rn(f[j] - __bfloat162float(h));
        }
    }

    int mbase = (warp >> 2) << 4;     // 0 or 16
    int nbase = (warp & 3) << 6;      // n quarter
    int arow = mbase + (lane >> 2);
    int acol = (lane & 3) * 2;
    int brow_off = lane >> 2;         // n offset within tile
    int bcol = (lane & 3) * 2;

    float c[8][4];
#pragma unroll
    for (int t = 0; t < 8; t++)
#pragma unroll
        for (int j = 0; j < 4; j++) c[t][j] = 0.f;

    const uint2* gBhi = (const uint2*)d_WThi;  // [n][k] : 64 uint2 per row
    const uint2* gBlo = (const uint2*)d_WTlo;

    for (int kc = 0; kc < 16; kc++) {
        __syncthreads();
        {   // stage B chunk: thread t handles n = t (16 k-values, hi+lo)
            int n = tid;
            const uint2* gh = gBhi + n * 64 + kc * 4;
            const uint2* gl = gBlo + n * 64 + kc * 4;
            __nv_bfloat16* rh = sBhi + n * KB;
            __nv_bfloat16* rl = sBlo + n * KB;
#pragma unroll
            for (int j = 0; j < 4; j++) {
                ((uint2*)rh)[j] = gh[j];
                ((uint2*)rl)[j] = gl[j];
            }
        }
        __syncthreads();

        int k0 = kc * 16;
        unsigned ahi[4], alo[4];
        ahi[0] = *(const unsigned*)&sAhi[arow * KP + k0 + acol];
        ahi[1] = *(const unsigned*)&sAhi[(arow + 8) * KP + k0 + acol];
        ahi[2] = *(const unsigned*)&sAhi[arow * KP + k0 + acol + 8];
        ahi[3] = *(const unsigned*)&sAhi[(arow + 8) * KP + k0 + acol + 8];
        alo[0] = *(const unsigned*)&sAlo[arow * KP + k0 + acol];
        alo[1] = *(const unsigned*)&sAlo[(arow + 8) * KP + k0 + acol];
        alo[2] = *(const unsigned*)&sAlo[arow * KP + k0 + acol + 8];
        alo[3] = *(const unsigned*)&sAlo[(arow + 8) * KP + k0 + acol + 8];

#pragma unroll
        for (int t = 0; t < 8; t++) {
            int n = nbase + t * 8 + brow_off;
            unsigned bh0 = *(const unsigned*)&sBhi[n * KB + bcol];
            unsigned bh1 = *(const unsigned*)&sBhi[n * KB + bcol + 8];
            unsigned bl0 = *(const unsigned*)&sBlo[n * KB + bcol];
            unsigned bl1 = *(const unsigned*)&sBlo[n * KB + bcol + 8];
            MMA_BF16(c[t], ahi[0], ahi[1], ahi[2], ahi[3], bh0, bh1);
            MMA_BF16(c[t], alo[0], alo[1], alo[2], alo[3], bh0, bh1);
            MMA_BF16(c[t], ahi[0], ahi[1], ahi[2], ahi[3], bl0, bl1);
        }
    }

    // epilogue: write h1
    int r0 = nb + mbase + (lane >> 2);
    int r1 = r0 + 8;
#pragma unroll
    for (int t = 0; t < 8; t++) {
        int col = nbase + t * 8 + (lane & 3) * 2;
        if (r0 < NN) *(float2*)&d_h1[(size_t)r0 * 256 + col] = make_float2(c[t][0], c[t][1]);
        if (r1 < NN) *(float2*)&d_h1[(size_t)r1 * 256 + col] = make_float2(c[t][2], c[t][3]);
    }
}
#define SMEM_MMA ((2 * 32 * KP + 2 * 256 * KB) * 2)

// ---------------- attention dots from h1 ----------------
__global__ void k_attdots(const float* __restrict__ as, const float* __restrict__ ad) {
    int n = blockIdx.x * 8 + (threadIdx.x >> 5);
    if (n >= NN) return;
    int lane = threadIdx.x & 31;
    const float4* hp = (const float4*)(d_h1 + (size_t)n * 256 + lane * 8);
    float4 h0 = hp[0], h1v = hp[1];
    const float4* ap = (const float4*)(as + lane * 8);
    float4 a0 = ap[0], a1 = ap[1];
    const float4* dp = (const float4*)(ad + lane * 8);
    float4 e0 = dp[0], e1 = dp[1];
    float vs = h0.x * a0.x + h0.y * a0.y + h0.z * a0.z + h0.w * a0.w
             + h1v.x * a1.x + h1v.y * a1.y + h1v.z * a1.z + h1v.w * a1.w;
    float vd = h0.x * e0.x + h0.y * e0.y + h0.z * e0.z + h0.w * e0.w
             + h1v.x * e1.x + h1v.y * e1.y + h1v.z * e1.z + h1v.w * e1.w;
    vs += __shfl_down_sync(0xffffffffu, vs, 1, 2);
    vd += __shfl_down_sync(0xffffffffu, vd, 1, 2);
    if (!(lane & 1)) {
        d_sa[n * 16 + (lane >> 1)] = vs;
        d_da[n * 16 + (lane >> 1)] = vd;
    }
}

// ---------------- GAT aggregation: per-dst softmax + weighted sum + bias + elu ----------------
__global__ void k_gat_agg(const float* __restrict__ b, float* __restrict__ out) {
    int n = (blockIdx.x * blockDim.x + threadIdx.x) >> 5;
    if (n >= NN) return;
    int lane = threadIdx.x & 31;
    int hlane = lane & 15;
    float da_l = d_da[n * 16 + hlane];
    int beg = d_rowoff[n], end = d_rowoff[n + 1];

    // pass 1: per-head max; both half-warps work (2 edges per trip)
    float m = -1e30f;
    for (int e = beg + (lane >> 4); e < end; e += 2) {
        int s = d_csr[e];
        float l = d_sa[s * 16 + hlane] + da_l;
        l = l > 0.f ? l : 0.2f * l;
        m = fmaxf(m, l);
    }
    m = fmaxf(m, __shfl_xor_sync(0xffffffffu, m, 16));
    float mh = __shfl_sync(0xffffffffu, m, lane >> 1);   // lane owns head lane/2

    // pass 2: exp-sum + weighted accumulate (lane owns channels [8*lane, 8*lane+8))
    float z = 0.f;
    float acc[8];
#pragma unroll
    for (int i = 0; i < 8; i++) acc[i] = 0.f;
    for (int e = beg; e < end; e++) {
        int s = d_csr[e];
        float l = d_sa[s * 16 + hlane] + da_l;
        l = l > 0.f ? l : 0.2f * l;
        float ev = __expf(__shfl_sync(0xffffffffu, l, lane >> 1) - mh);
        z += ev;
        const float4* hp = (const float4*)(d_h1 + s * 256 + lane * 8);
        float4 v0 = hp[0], v1 = hp[1];
        acc[0] += ev * v0.x; acc[1] += ev * v0.y; acc[2] += ev * v0.z; acc[3] += ev * v0.w;
        acc[4] += ev * v1.x; acc[5] += ev * v1.y; acc[6] += ev * v1.z; acc[7] += ev * v1.w;
    }
    float invz = 1.f / (z + 1e-16f);
#pragma unroll
    for (int i = 0; i < 8; i++) {
        float v = acc[i] * invz + b[lane * 8 + i];
        out[n * 256 + lane * 8 + i] = v > 0.f ? v : (__expf(v) - 1.f);
    }
}

// ---------------- final: concat(h[user], h[item]) @ Wdnn -> log_softmax ----------------
__global__ void k_final(const float* __restrict__ h, const int* __restrict__ ui,
                        const int* __restrict__ ii, const float* __restrict__ Wd,
                        float* __restrict__ out) {
    int p = (blockIdx.x * blockDim.x + threadIdx.x) >> 5;
    if (p >= 1024) return;
    int lane = threadIdx.x & 31;
    int u = ui[p], it = ii[p];
    float a0 = 0.f, a1 = 0.f;
    for (int k = lane; k < 256; k += 32) {
        float v = h[u * 256 + k];
        a0 += v * Wd[k * 2 + 0];
        a1 += v * Wd[k * 2 + 1];
        float w = h[it * 256 + k];
        a0 += w * Wd[(256 + k) * 2 + 0];
        a1 += w * Wd[(256 + k) * 2 + 1];
    }
#pragma unroll
    for (int off = 16; off >= 1; off >>= 1) {
        a0 += __shfl_down_sync(0xffffffffu, a0, off);
        a1 += __shfl_down_sync(0xffffffffu, a1, off);
    }
    if (lane == 0) {
        float mx = fmaxf(a0, a1);
        float lse = mx + __logf(__expf(a0 - mx) + __expf(a1 - mx));
        out[p * 2 + 0] = a0 - lse;
        out[p * 2 + 1] = a1 - lse;
    }
}

// ---------------- launcher ----------------
extern "C" void kernel_launch(void* const* d_in, const int* in_sizes, int n_in,
                              void* d_out, int out_size) {
    const float* x    = (const float*)d_in[0];
    const int*   ei   = (const int*)d_in[1];
    const float* Hd   = (const float*)d_in[2];
    const int*   ui   = (const int*)d_in[3];
    const int*   ii   = (const int*)d_in[4];
    const float* Wg   = (const float*)d_in[5];
    const float* bg   = (const float*)d_in[6];
    const float* W1   = (const float*)d_in[7];
    const float* a1s  = (const float*)d_in[8];
    const float* a1d  = (const float*)d_in[9];
    const float* b1   = (const float*)d_in[10];
    const float* W2   = (const float*)d_in[11];
    const float* a2s  = (const float*)d_in[12];
    const float* a2d  = (const float*)d_in[13];
    const float* b2   = (const float*)d_in[14];
    const float* W3   = (const float*)d_in[15];
    const float* a3s  = (const float*)d_in[16];
    const float* a3d  = (const float*)d_in[17];
    const float* b3   = (const float*)d_in[18];
    const float* wd   = (const float*)d_in[19];
    const float* wr   = (const float*)d_in[20];
    const float* wdnn = (const float*)d_in[21];
    float* out = (float*)d_out;

    void *p_h0, *p_bufA, *p_bufB;
    cudaGetSymbolAddress(&p_h0, d_h0);
    cudaGetSymbolAddress(&p_bufA, d_bufA);
    cudaGetSymbolAddress(&p_bufB, d_bufB);
    float* h0   = (float*)p_h0;
    float* bufA = (float*)p_bufA;
    float* bufB = (float*)p_bufB;

    cudaFuncSetAttribute(k_transform_mma,
                         cudaFuncAttributeMaxDynamicSharedMemorySize, SMEM_MMA);

    k_init<<<(NN + 255) / 256, 256>>>();
    k_gemm1<<<(128 * 512 + 255) / 256, 256>>>(wd, Hd);
    k_gemm2<<<(128 * 16 + 255) / 256, 256>>>(wr);
    k_count<<<(EE + 255) / 256, 256>>>(ei + EE);
    k_scan<<<1, 1024>>>();
    k_scatter<<<(ET + 255) / 256, 256>>>(ei);

    k_xw_dual<<<(NN * 16 + 255) / 256, 256>>>(x, Wg);
    k_gcn_agg<<<(NN * 16 + 255) / 256, 256>>>(bg);

    // GAT layer 1: h0[N,16] -> bufA[N,256]  (FFMA path, fused att dots)
    k_transform16<<<NN / 16, 128>>>(h0, W1, a1s, a1d);
    k_gat_agg<<<(NN * 32 + 255) / 256, 256>>>(b1, bufA);

    // GAT layer 2: bufA -> bufB  (tensor cores, bf16x3)
    k_prepW<<<(256 * 256 + 255) / 256, 256>>>(W2);
    k_transform_mma<<<(NN + 31) / 32, 256, SMEM_MMA>>>(bufA);
    k_attdots<<<NN / 8, 256>>>(a2s, a2d);
    k_gat_agg<<<(NN * 32 + 255) / 256, 256>>>(b2, bufB);

    // GAT layer 3: bufB -> bufA
    k_prepW<<<(256 * 256 + 255) / 256, 256>>>(W3);
    k_transform_mma<<<(NN + 31) / 32, 256, SMEM_MMA>>>(bufB);
    k_attdots<<<NN / 8, 256>>>(a3s, a3d);
    k_gat_agg<<<(NN * 32 + 255) / 256, 256>>>(b3, bufA);

    k_final<<<(1024 * 32 + 255) / 256, 256>>>(bufA, ui, ii, wdnn, out);
}

// round 4
// speedup vs baseline: 1.6202x; 1.6202x over previous
#include <cuda_runtime.h>
#include <cuda_bf16.h>
#include <math.h>

#define NN 50000
#define NP 50048          // padded to 128
#define EE 800000
#define ET (EE + NN)      // edges + self loops
#define FIN0 128
#define PIT 264           // smem row pitch (bf16): 33*16B -> LDSM conflict-free

// ---------------- scratch (device globals; no allocation allowed) ----------------
__device__ float d_T1[128 * 512];
__device__ float d_M[128 * 16];
__device__ int   d_deg[NN];
__device__ int   d_rowoff[NN + 1];
__device__ int   d_cursor[NN];
__device__ float d_dis[NN];
__device__ int   d_csr[ET];
__device__ float d_xw[NN * 16];
__device__ float d_dual[NN * 16];
__device__ float d_h0[NN * 16];
__device__ float d_h1[NP * 256];
__device__ float d_bufA[NN * 256];
__device__ float d_sa[NN * 16];
__device__ float d_da[NN * 16];
__device__ __nv_bfloat16 d_Ahi[NP * 256];    // split input activations for MMA
__device__ __nv_bfloat16 d_Alo[NP * 256];
__device__ __nv_bfloat16 d_WThi[256 * 256];  // W^T split hi  [n][k]
__device__ __nv_bfloat16 d_WTlo[256 * 256];

static __device__ __forceinline__ unsigned pack2(__nv_bfloat16 a, __nv_bfloat16 b) {
    unsigned short ua = *reinterpret_cast<unsigned short*>(&a);
    unsigned short ub = *reinterpret_cast<unsigned short*>(&b);
    return (unsigned)ua | ((unsigned)ub << 16);
}

// ---------------- init ----------------
__global__ void k_init() {
    int i = blockIdx.x * blockDim.x + threadIdx.x;
    if (i < NN) { d_deg[i] = 1; d_cursor[i] = 0; }
}

// ---------------- combined dual weight: M = Wd @ Hd @ Wr ----------------
__global__ void k_gemm1(const float* __restrict__ wd, const float* __restrict__ hd) {
    int idx = blockIdx.x * blockDim.x + threadIdx.x;
    if (idx >= 128 * 512) return;
    int i = idx >> 9, j = idx & 511;
    float a = 0.f;
    for (int k = 0; k < 512; k++) a += wd[i * 512 + k] * hd[k * 512 + j];
    d_T1[idx] = a;
}

__global__ void k_gemm2(const float* __restrict__ wr) {
    int idx = blockIdx.x * blockDim.x + threadIdx.x;
    if (idx >= 128 * 16) return;
    int i = idx >> 4, j = idx & 15;
    float a = 0.f;
    for (int k = 0; k < 512; k++) a += d_T1[i * 512 + k] * wr[k * 16 + j];
    d_M[idx] = a;
}

// ---------------- degree count ----------------
__global__ void k_count(const int* __restrict__ dst) {
    int e = blockIdx.x * blockDim.x + threadIdx.x;
    if (e < EE) atomicAdd(&d_deg[dst[e]], 1);
}

// ---------------- warp-shuffle scan (+ fused rsqrt degree) ----------------
__global__ void k_scan() {
    __shared__ int warp_sums[32];
    int t = threadIdx.x;
    const int S = 49;
    int b0 = t * S;
    int sum = 0;
    for (int i = 0; i < S; i++) {
        int idx = b0 + i;
        if (idx < NN) sum += d_deg[idx];
    }
    int lane = t & 31, w = t >> 5;
    int v = sum;
#pragma unroll
    for (int off = 1; off < 32; off <<= 1) {
        int u = __shfl_up_sync(0xffffffffu, v, off);
        if (lane >= off) v += u;
    }
    if (lane == 31) warp_sums[w] = v;
    __syncthreads();
    if (w == 0) {
        int ws = warp_sums[lane];
#pragma unroll
        for (int off = 1; off < 32; off <<= 1) {
            int u = __shfl_up_sync(0xffffffffu, ws, off);
            if (lane >= off) ws += u;
        }
        warp_sums[lane] = ws;
    }
    __syncthreads();
    int ex = v - sum + (w > 0 ? warp_sums[w - 1] : 0);
    int run = ex;
    for (int i = 0; i < S; i++) {
        int idx = b0 + i;
        if (idx < NN) {
            int dg = d_deg[idx];
            run += dg;
            d_rowoff[idx + 1] = run;
            d_dis[idx] = rsqrtf((float)dg);
        }
    }
    if (t == 0) d_rowoff[0] = 0;
}

__global__ void k_scatter(const int* __restrict__ ei) {
    int e = blockIdx.x * blockDim.x + threadIdx.x;
    if (e >= ET) return;
    int s, dd;
    if (e < EE) { s = ei[e]; dd = ei[EE + e]; }
    else        { s = dd = e - EE; }
    int p = atomicAdd(&d_cursor[dd], 1);
    d_csr[d_rowoff[dd] + p] = s;
}

// ---------------- GCN feature transform + dual (fused) ----------------
__global__ void k_xw_dual(const float* __restrict__ x, const float* __restrict__ Wg) {
    int idx = blockIdx.x * blockDim.x + threadIdx.x;
    if (idx >= NN * 16) return;
    int n = idx >> 4, j = idx & 15;
    float a = 0.f, b = 0.f;
    const float* xr = x + n * FIN0;
    for (int k = 0; k < FIN0; k++) {
        float xv = xr[k];
        a += xv * Wg[k * 16 + j];
        b += xv * d_M[k * 16 + j];
    }
    d_xw[idx] = a;
    d_dual[idx] = b;
}

// ---------------- GCN aggregation + dual + elu -> h0 ----------------
__global__ void k_gcn_agg(const float* __restrict__ bg) {
    int g = (blockIdx.x * blockDim.x + threadIdx.x) >> 4;
    int j = threadIdx.x & 15;
    if (g >= NN) return;
    int beg = d_rowoff[g], end = d_rowoff[g + 1];
    float acc = 0.f;
    for (int e = beg; e < end; e++) {
        int s = d_csr[e];
        acc += d_dis[s] * d_xw[s * 16 + j];
    }
    float v = acc * d_dis[g] + bg[j] + d_dual[g * 16 + j];
    d_h0[g * 16 + j] = v > 0.f ? v : (__expf(v) - 1.f);
}

// ---------------- GAT layer-1 transform (FIN=16, FFMA; cheap) ----------------
__global__ void __launch_bounds__(128, 8)
k_transform16(const float* __restrict__ hin, const float* __restrict__ W,
              const float* __restrict__ asrc, const float* __restrict__ adst) {
    __shared__ float s[16][16];
    int tid = threadIdx.x;
    int nb = blockIdx.x * 16;
    const float4* hin4 = (const float4*)(hin + nb * 16);
    float4* s4 = (float4*)s;
    for (int t = tid; t < 16 * 16 / 4; t += 128) s4[t] = hin4[t];
    __syncthreads();

    int cg = tid & 63;
    int ng = tid >> 6;
    const float4* W4 = (const float4*)W;
    float4 acc[8];
#pragma unroll
    for (int r = 0; r < 8; r++) acc[r] = make_float4(0.f, 0.f, 0.f, 0.f);

#pragma unroll
    for (int k = 0; k < 16; k++) {
        float4 w = W4[k * 64 + cg];
#pragma unroll
        for (int r = 0; r < 8; r++) {
            float sv = s[ng * 8 + r][k];
            acc[r].x += sv * w.x; acc[r].y += sv * w.y;
            acc[r].z += sv * w.z; acc[r].w += sv * w.w;
        }
    }

    float4 as4 = ((const float4*)asrc)[cg];
    float4 ad4 = ((const float4*)adst)[cg];
#pragma unroll
    for (int r = 0; r < 8; r++) {
        int n = nb + ng * 8 + r;
        if (n >= NN) break;
        ((float4*)(d_h1 + (size_t)n * 256))[cg] = acc[r];
        float vs = acc[r].x * as4.x + acc[r].y * as4.y + acc[r].z * as4.z + acc[r].w * as4.w;
        float vd = acc[r].x * ad4.x + acc[r].y * ad4.y + acc[r].z * ad4.z + acc[r].w * ad4.w;
        vs += __shfl_down_sync(0xffffffffu, vs, 2, 4);
        vs += __shfl_down_sync(0xffffffffu, vs, 1, 4);
        vd += __shfl_down_sync(0xffffffffu, vd, 2, 4);
        vd += __shfl_down_sync(0xffffffffu, vd, 1, 4);
        if ((cg & 3) == 0) {
            int h = cg >> 2;
            d_sa[n * 16 + h] = vs;
            d_da[n * 16 + h] = vd;
        }
    }
}

// ---------------- W prep: transpose + bf16 split ----------------
__global__ void k_prepW(const float* __restrict__ W) {
    int idx = blockIdx.x * blockDim.x + threadIdx.x;
    if (idx >= 256 * 256) return;
    int n = idx >> 8, k = idx & 255;
    float w = W[k * 256 + n];
    __nv_bfloat16 h = __float2bfloat16_rn(w);
    d_WThi[n * 256 + k] = h;
    d_WTlo[n * 256 + k] = __float2bfloat16_rn(w - __bfloat162float(h));
}

// ---------------- tensor-core transform (bf16x3, ldmatrix, 1 barrier) ----------------
#define MMA_BF16(C, A0, A1, A2, A3, B0, B1)                                  \
    asm volatile(                                                            \
        "mma.sync.aligned.m16n8k16.row.col.f32.bf16.bf16.f32 "               \
        "{%0,%1,%2,%3}, {%4,%5,%6,%7}, {%8,%9}, {%0,%1,%2,%3};\n"            \
        : "+f"(C[0]), "+f"(C[1]), "+f"(C[2]), "+f"(C[3])                     \
        : "r"(A0), "r"(A1), "r"(A2), "r"(A3), "r"(B0), "r"(B1))

#define LDSM4(R0, R1, R2, R3, ADDR)                                          \
    asm volatile("ldmatrix.sync.aligned.m8n8.x4.shared.b16 {%0,%1,%2,%3}, [%4];" \
        : "=r"(R0), "=r"(R1), "=r"(R2), "=r"(R3) : "r"(ADDR))

__global__ void __launch_bounds__(256, 1)
k_transform_mma() {
    extern __shared__ __nv_bfloat16 sm[];
    __nv_bfloat16* sAhi = sm;                       // 128 x PIT
    __nv_bfloat16* sAlo = sAhi + 128 * PIT;
    __nv_bfloat16* sBhi = sAlo + 128 * PIT;         // 64 x PIT
    __nv_bfloat16* sBlo = sBhi + 64 * PIT;

    int tid = threadIdx.x, lane = tid & 31, warp = tid >> 5;
    int m0 = blockIdx.x * 128;
    int n0 = blockIdx.y * 64;

    // stage A tile and B slice (once)
    {
        const uint4* gH = (const uint4*)(d_Ahi + (size_t)m0 * 256);
        const uint4* gL = (const uint4*)(d_Alo + (size_t)m0 * 256);
        for (int i = tid; i < 128 * 32; i += 256) {
            int r = i >> 5, c = i & 31;
            *(uint4*)(sAhi + r * PIT + c * 8) = gH[r * 32 + c];
            *(uint4*)(sAlo + r * PIT + c * 8) = gL[r * 32 + c];
        }
        const uint4* bH = (const uint4*)(d_WThi + (size_t)n0 * 256);
        const uint4* bL = (const uint4*)(d_WTlo + (size_t)n0 * 256);
        for (int i = tid; i < 64 * 32; i += 256) {
            int r = i >> 5, c = i & 31;
            *(uint4*)(sBhi + r * PIT + c * 8) = bH[r * 32 + c];
            *(uint4*)(sBlo + r * PIT + c * 8) = bL[r * 32 + c];
        }
    }
    __syncthreads();

    float c[8][4];
#pragma unroll
    for (int t = 0; t < 8; t++)
#pragma unroll
        for (int j = 0; j < 4; j++) c[t][j] = 0.f;

    int rA = warp * 16 + (lane & 15);
    int kOff = (lane >> 4) << 3;     // 0 or 8
    unsigned aHiB = (unsigned)__cvta_generic_to_shared(sAhi + rA * PIT + kOff);
    unsigned aLoB = (unsigned)__cvta_generic_to_shared(sAlo + rA * PIT + kOff);
    int rB = lane & 15;
    unsigned bHiB = (unsigned)__cvta_generic_to_shared(sBhi + rB * PIT + kOff);
    unsigned bLoB = (unsigned)__cvta_generic_to_shared(sBlo + rB * PIT + kOff);

#pragma unroll 4
    for (int kc = 0; kc < 16; kc++) {
        unsigned ka = kc * 32;   // bytes (16 bf16)
        unsigned ah0, ah1, ah2, ah3, al0, al1, al2, al3;
        LDSM4(ah0, ah1, ah2, ah3, aHiB + ka);
        LDSM4(al0, al1, al2, al3, aLoB + ka);
        unsigned ahv[4] = {ah0, ah1, ah2, ah3};
        unsigned alv[4] = {al0, al1, al2, al3};
#pragma unroll
        for (int p = 0; p < 4; p++) {
            unsigned boff = (unsigned)(p * 16 * PIT * 2) + ka;
            unsigned bh0, bh1, bh2, bh3, bl0, bl1, bl2, bl3;
            LDSM4(bh0, bh1, bh2, bh3, bHiB + boff);
            LDSM4(bl0, bl1, bl2, bl3, bLoB + boff);
            // mats: 0 = n0-7/k0-7, 1 = n8-15/k0-7, 2 = n0-7/k8-15, 3 = n8-15/k8-15
            MMA_BF16(c[2 * p],     ahv[0], ahv[1], ahv[2], ahv[3], bh0, bh2);
            MMA_BF16(c[2 * p],     alv[0], alv[1], alv[2], alv[3], bh0, bh2);
            MMA_BF16(c[2 * p],     ahv[0], ahv[1], ahv[2], ahv[3], bl0, bl2);
            MMA_BF16(c[2 * p + 1], ahv[0], ahv[1], ahv[2], ahv[3], bh1, bh3);
            MMA_BF16(c[2 * p + 1], alv[0], alv[1], alv[2], alv[3], bh1, bh3);
            MMA_BF16(c[2 * p + 1], ahv[0], ahv[1], ahv[2], ahv[3], bl1, bl3);
        }
    }

    // epilogue: write fp32 h1
    int row0 = m0 + warp * 16 + (lane >> 2);
    int col0 = n0 + (lane & 3) * 2;
#pragma unroll
    for (int t = 0; t < 8; t++) {
        *(float2*)&d_h1[(size_t)row0 * 256 + col0 + t * 8] = make_float2(c[t][0], c[t][1]);
        *(float2*)&d_h1[(size_t)(row0 + 8) * 256 + col0 + t * 8] = make_float2(c[t][2], c[t][3]);
    }
}
#define SMEM_MMA ((2 * 128 * PIT + 2 * 64 * PIT) * 2)

// ---------------- attention dots from h1 ----------------
__global__ void k_attdots(const float* __restrict__ as, const float* __restrict__ ad) {
    int n = blockIdx.x * 8 + (threadIdx.x >> 5);
    if (n >= NN) return;
    int lane = threadIdx.x & 31;
    const float4* hp = (const float4*)(d_h1 + (size_t)n * 256 + lane * 8);
    float4 h0 = hp[0], h1v = hp[1];
    const float4* ap = (const float4*)(as + lane * 8);
    float4 a0 = ap[0], a1 = ap[1];
    const float4* dp = (const float4*)(ad + lane * 8);
    float4 e0 = dp[0], e1 = dp[1];
    float vs = h0.x * a0.x + h0.y * a0.y + h0.z * a0.z + h0.w * a0.w
             + h1v.x * a1.x + h1v.y * a1.y + h1v.z * a1.z + h1v.w * a1.w;
    float vd = h0.x * e0.x + h0.y * e0.y + h0.z * e0.z + h0.w * e0.w
             + h1v.x * e1.x + h1v.y * e1.y + h1v.z * e1.z + h1v.w * e1.w;
    vs += __shfl_down_sync(0xffffffffu, vs, 1, 2);
    vd += __shfl_down_sync(0xffffffffu, vd, 1, 2);
    if (!(lane & 1)) {
        d_sa[n * 16 + (lane >> 1)] = vs;
        d_da[n * 16 + (lane >> 1)] = vd;
    }
}

// ---------------- GAT aggregation (fp32 out OR split-bf16 out) ----------------
template <bool SPLIT>
__global__ void k_gat_agg(const float* __restrict__ b, float* __restrict__ outf) {
    int n = (blockIdx.x * blockDim.x + threadIdx.x) >> 5;
    if (n >= NN) return;
    int lane = threadIdx.x & 31;
    int hlane = lane & 15;
    float da_l = d_da[n * 16 + hlane];
    int beg = d_rowoff[n], end = d_rowoff[n + 1];

    float m = -1e30f;
    for (int e = beg + (lane >> 4); e < end; e += 2) {
        int s = d_csr[e];
        float l = d_sa[s * 16 + hlane] + da_l;
        l = l > 0.f ? l : 0.2f * l;
        m = fmaxf(m, l);
    }
    m = fmaxf(m, __shfl_xor_sync(0xffffffffu, m, 16));
    float mh = __shfl_sync(0xffffffffu, m, lane >> 1);

    float z = 0.f;
    float acc[8];
#pragma unroll
    for (int i = 0; i < 8; i++) acc[i] = 0.f;
    for (int e = beg; e < end; e++) {
        int s = d_csr[e];
        float l = d_sa[s * 16 + hlane] + da_l;
        l = l > 0.f ? l : 0.2f * l;
        float ev = __expf(__shfl_sync(0xffffffffu, l, lane >> 1) - mh);
        z += ev;
        const float4* hp = (const float4*)(d_h1 + (size_t)s * 256 + lane * 8);
        float4 v0 = hp[0], v1 = hp[1];
        acc[0] += ev * v0.x; acc[1] += ev * v0.y; acc[2] += ev * v0.z; acc[3] += ev * v0.w;
        acc[4] += ev * v1.x; acc[5] += ev * v1.y; acc[6] += ev * v1.z; acc[7] += ev * v1.w;
    }
    float invz = 1.f / (z + 1e-16f);
    float vo[8];
#pragma unroll
    for (int i = 0; i < 8; i++) {
        float v = acc[i] * invz + b[lane * 8 + i];
        vo[i] = v > 0.f ? v : (__expf(v) - 1.f);
    }
    if (SPLIT) {
        unsigned hi[4], lo[4];
#pragma unroll
        for (int i = 0; i < 4; i++) {
            __nv_bfloat16 h0 = __float2bfloat16_rn(vo[2 * i]);
            __nv_bfloat16 h1 = __float2bfloat16_rn(vo[2 * i + 1]);
            hi[i] = pack2(h0, h1);
            lo[i] = pack2(__float2bfloat16_rn(vo[2 * i] - __bfloat162float(h0)),
                          __float2bfloat16_rn(vo[2 * i + 1] - __bfloat162float(h1)));
        }
        *(uint4*)&d_Ahi[(size_t)n * 256 + lane * 8] = make_uint4(hi[0], hi[1], hi[2], hi[3]);
        *(uint4*)&d_Alo[(size_t)n * 256 + lane * 8] = make_uint4(lo[0], lo[1], lo[2], lo[3]);
    } else {
        *(float4*)&outf[(size_t)n * 256 + lane * 8] = make_float4(vo[0], vo[1], vo[2], vo[3]);
        *(float4*)&outf[(size_t)n * 256 + lane * 8 + 4] = make_float4(vo[4], vo[5], vo[6], vo[7]);
    }
}

// ---------------- final ----------------
__global__ void k_final(const float* __restrict__ h, const int* __restrict__ ui,
                        const int* __restrict__ ii, const float* __restrict__ Wd,
                        float* __restrict__ out) {
    int p = (blockIdx.x * blockDim.x + threadIdx.x) >> 5;
    if (p >= 1024) return;
    int lane = threadIdx.x & 31;
    int u = ui[p], it = ii[p];
    float a0 = 0.f, a1 = 0.f;
    for (int k = lane; k < 256; k += 32) {
        float v = h[u * 256 + k];
        a0 += v * Wd[k * 2 + 0];
        a1 += v * Wd[k * 2 + 1];
        float w = h[it * 256 + k];
        a0 += w * Wd[(256 + k) * 2 + 0];
        a1 += w * Wd[(256 + k) * 2 + 1];
    }
#pragma unroll
    for (int off = 16; off >= 1; off >>= 1) {
        a0 += __shfl_down_sync(0xffffffffu, a0, off);
        a1 += __shfl_down_sync(0xffffffffu, a1, off);
    }
    if (lane == 0) {
        float mx = fmaxf(a0, a1);
        float lse = mx + __logf(__expf(a0 - mx) + __expf(a1 - mx));
        out[p * 2 + 0] = a0 - lse;
        out[p * 2 + 1] = a1 - lse;
    }
}

// ---------------- launcher ----------------
extern "C" void kernel_launch(void* const* d_in, const int* in_sizes, int n_in,
                              void* d_out, int out_size) {
    const float* x    = (const float*)d_in[0];
    const int*   ei   = (const int*)d_in[1];
    const float* Hd   = (const float*)d_in[2];
    const int*   ui   = (const int*)d_in[3];
    const int*   ii   = (const int*)d_in[4];
    const float* Wg   = (const float*)d_in[5];
    const float* bg   = (const float*)d_in[6];
    const float* W1   = (const float*)d_in[7];
    const float* a1s  = (const float*)d_in[8];
    const float* a1d  = (const float*)d_in[9];
    const float* b1   = (const float*)d_in[10];
    const float* W2   = (const float*)d_in[11];
    const float* a2s  = (const float*)d_in[12];
    const float* a2d  = (const float*)d_in[13];
    const float* b2   = (const float*)d_in[14];
    const float* W3   = (const float*)d_in[15];
    const float* a3s  = (const float*)d_in[16];
    const float* a3d  = (const float*)d_in[17];
    const float* b3   = (const float*)d_in[18];
    const float* wd   = (const float*)d_in[19];
    const float* wr   = (const float*)d_in[20];
    const float* wdnn = (const float*)d_in[21];
    float* out = (float*)d_out;

    void *p_h0, *p_bufA;
    cudaGetSymbolAddress(&p_h0, d_h0);
    cudaGetSymbolAddress(&p_bufA, d_bufA);
    float* h0   = (float*)p_h0;
    float* bufA = (float*)p_bufA;

    cudaFuncSetAttribute(k_transform_mma,
                         cudaFuncAttributeMaxDynamicSharedMemorySize, SMEM_MMA);

    k_init<<<(NN + 255) / 256, 256>>>();
    k_gemm1<<<(128 * 512 + 255) / 256, 256>>>(wd, Hd);
    k_gemm2<<<(128 * 16 + 255) / 256, 256>>>(wr);
    k_count<<<(EE + 255) / 256, 256>>>(ei + EE);
    k_scan<<<1, 1024>>>();
    k_scatter<<<(ET + 255) / 256, 256>>>(ei);

    k_xw_dual<<<(NN * 16 + 255) / 256, 256>>>(x, Wg);
    k_gcn_agg<<<(NN * 16 + 255) / 256, 256>>>(bg);

    // GAT layer 1: h0[N,16] -> split bf16 (input to layer-2 MMA)
    k_transform16<<<NN / 16, 128>>>(h0, W1, a1s, a1d);
    k_gat_agg<true><<<(NN * 32 + 255) / 256, 256>>>(b1, nullptr);

    // GAT layer 2 (tensor cores)
    k_prepW<<<(256 * 256 + 255) / 256, 256>>>(W2);
    k_transform_mma<<<dim3(NP / 128, 4), 256, SMEM_MMA>>>();
    k_attdots<<<(NN + 7) / 8, 256>>>(a2s, a2d);
    k_gat_agg<true><<<(NN * 32 + 255) / 256, 256>>>(b2, nullptr);

    // GAT layer 3 (tensor cores)
    k_prepW<<<(256 * 256 + 255) / 256, 256>>>(W3);
    k_transform_mma<<<dim3(NP / 128, 4), 256, SMEM_MMA>>>();
    k_attdots<<<(NN + 7) / 8, 256>>>(a3s, a3d);
    k_gat_agg<false><<<(NN * 32 + 255) / 256, 256>>>(b3, bufA);

    k_final<<<(1024 * 32 + 255) / 256, 256>>>(bufA, ui, ii, wdnn, out);
}

// round 5
// speedup vs baseline: 1.9509x; 1.2041x over previous
#include <cuda_runtime.h>
#include <cuda_bf16.h>
#include <cuda_fp16.h>
#include <math.h>

#define NN 50000
#define NP 50048          // padded to 128
#define EE 800000
#define ET (EE + NN)      // edges + self loops
#define PIT 264           // smem row pitch (bf16): 33*16B -> LDSM conflict-free

// ---------------- scratch (device globals; no allocation allowed) ----------------
__device__ float d_T1[128 * 512];
__device__ float d_M[128 * 16];
__device__ int   d_deg[NN];
__device__ int   d_rowoff[NN + 1];
__device__ int   d_cursor[NN];
__device__ float d_dis[NN];
__device__ int   d_csr[ET];
__device__ float d_xw[NN * 16];
__device__ float d_dual[NN * 16];
__device__ float d_h0[NN * 16];
__device__ __half d_h1h[NP * 256];           // fp16 transformed features (agg gather)
__device__ float d_bufA[NN * 256];
__device__ float d_sa[NN * 16];
__device__ float d_da[NN * 16];
__device__ __nv_bfloat16 d_Ahi[NP * 256];    // split input activations for MMA
__device__ __nv_bfloat16 d_Alo[NP * 256];
__device__ __nv_bfloat16 d_W2hi[256 * 256];  // W2^T split [n][k]
__device__ __nv_bfloat16 d_W2lo[256 * 256];
__device__ __nv_bfloat16 d_W3hi[256 * 256];
__device__ __nv_bfloat16 d_W3lo[256 * 256];

static __device__ __forceinline__ unsigned pack2(__nv_bfloat16 a, __nv_bfloat16 b) {
    unsigned short ua = *reinterpret_cast<unsigned short*>(&a);
    unsigned short ub = *reinterpret_cast<unsigned short*>(&b);
    return (unsigned)ua | ((unsigned)ub << 16);
}

// ---------------- init (+ zero gemm accumulators) ----------------
__global__ void k_init() {
    int i = blockIdx.x * blockDim.x + threadIdx.x;
    if (i < NN) { d_deg[i] = 1; d_cursor[i] = 0; }
    if (i < 128 * 512) d_T1[i] = 0.f;
    if (i < 128 * 16) d_M[i] = 0.f;
}

// ---------------- combined dual weight: M = Wd @ Hd @ Wr (k-split + atomics) ----------------
__global__ void k_gemm1(const float* __restrict__ wd, const float* __restrict__ hd) {
    int idx = blockIdx.x * blockDim.x + threadIdx.x;  // 4 * 65536
    if (idx >= 4 * 128 * 512) return;
    int kc = idx >> 16;
    int r = idx & 65535;
    int i = r >> 9, j = r & 511;
    float a = 0.f;
    int k0 = kc * 128;
    for (int k = k0; k < k0 + 128; k++) a += wd[i * 512 + k] * hd[k * 512 + j];
    atomicAdd(&d_T1[r], a);
}

__global__ void k_gemm2(const float* __restrict__ wr) {
    int idx = blockIdx.x * blockDim.x + threadIdx.x;  // 4 * 2048
    if (idx >= 4 * 128 * 16) return;
    int kc = idx >> 11;
    int r = idx & 2047;
    int i = r >> 4, j = r & 15;
    float a = 0.f;
    int k0 = kc * 128;
    for (int k = k0; k < k0 + 128; k++) a += d_T1[i * 512 + k] * wr[k * 16 + j];
    atomicAdd(&d_M[r], a);
}

// ---------------- degree count ----------------
__global__ void k_count(const int* __restrict__ dst) {
    int e = blockIdx.x * blockDim.x + threadIdx.x;
    if (e < EE) atomicAdd(&d_deg[dst[e]], 1);
}

// ---------------- warp-shuffle scan (+ fused rsqrt degree) ----------------
__global__ void k_scan() {
    __shared__ int warp_sums[32];
    int t = threadIdx.x;
    const int S = 49;
    int b0 = t * S;
    int sum = 0;
    for (int i = 0; i < S; i++) {
        int idx = b0 + i;
        if (idx < NN) sum += d_deg[idx];
    }
    int lane = t & 31, w = t >> 5;
    int v = sum;
#pragma unroll
    for (int off = 1; off < 32; off <<= 1) {
        int u = __shfl_up_sync(0xffffffffu, v, off);
        if (lane >= off) v += u;
    }
    if (lane == 31) warp_sums[w] = v;
    __syncthreads();
    if (w == 0) {
        int ws = warp_sums[lane];
#pragma unroll
        for (int off = 1; off < 32; off <<= 1) {
            int u = __shfl_up_sync(0xffffffffu, ws, off);
            if (lane >= off) ws += u;
        }
        warp_sums[lane] = ws;
    }
    __syncthreads();
    int ex = v - sum + (w > 0 ? warp_sums[w - 1] : 0);
    int run = ex;
    for (int i = 0; i < S; i++) {
        int idx = b0 + i;
        if (idx < NN) {
            int dg = d_deg[idx];
            run += dg;
            d_rowoff[idx + 1] = run;
            d_dis[idx] = rsqrtf((float)dg);
        }
    }
    if (t == 0) d_rowoff[0] = 0;
}

__global__ void k_scatter(const int* __restrict__ ei) {
    int e = blockIdx.x * blockDim.x + threadIdx.x;
    if (e >= ET) return;
    int s, dd;
    if (e < EE) { s = ei[e]; dd = ei[EE + e]; }
    else        { s = dd = e - EE; }
    int p = atomicAdd(&d_cursor[dd], 1);
    d_csr[d_rowoff[dd] + p] = s;
}

// ---------------- GCN feature transform + dual (smem staged) ----------------
__global__ void __launch_bounds__(256)
k_xw_dual(const float* __restrict__ x, const float* __restrict__ Wg) {
    __shared__ float sx[16][132];
    int tid = threadIdx.x;
    int nb = blockIdx.x * 16;
    const float4* xs = (const float4*)(x + (size_t)nb * 128);
    for (int i = tid; i < 512; i += 256) {
        float4 v = xs[i];
        int r = i >> 5, c = (i & 31) * 4;
        sx[r][c] = v.x; sx[r][c + 1] = v.y; sx[r][c + 2] = v.z; sx[r][c + 3] = v.w;
    }
    __syncthreads();
    int nl = tid >> 4, j = tid & 15;
    float a = 0.f, b = 0.f;
#pragma unroll 4
    for (int k = 0; k < 128; k++) {
        float xv = sx[nl][k];
        a += xv * Wg[k * 16 + j];
        b += xv * d_M[k * 16 + j];
    }
    int n = nb + nl;
    d_xw[n * 16 + j] = a;
    d_dual[n * 16 + j] = b;
}

// ---------------- GCN aggregation + dual + elu -> h0 ----------------
__global__ void k_gcn_agg(const float* __restrict__ bg) {
    int g = (blockIdx.x * blockDim.x + threadIdx.x) >> 4;
    int j = threadIdx.x & 15;
    if (g >= NN) return;
    int beg = d_rowoff[g], end = d_rowoff[g + 1];
    float acc = 0.f;
    for (int e = beg; e < end; e++) {
        int s = d_csr[e];
        acc += d_dis[s] * d_xw[s * 16 + j];
    }
    float v = acc * d_dis[g] + bg[j] + d_dual[g * 16 + j];
    d_h0[g * 16 + j] = v > 0.f ? v : (__expf(v) - 1.f);
}

// ---------------- GAT layer-1 transform (FIN=16, FFMA; writes fp16 h1) ----------------
__global__ void __launch_bounds__(128, 8)
k_transform16(const float* __restrict__ hin, const float* __restrict__ W,
              const float* __restrict__ asrc, const float* __restrict__ adst) {
    __shared__ float s[16][16];
    int tid = threadIdx.x;
    int nb = blockIdx.x * 16;
    const float4* hin4 = (const float4*)(hin + nb * 16);
    float4* s4 = (float4*)s;
    for (int t = tid; t < 16 * 16 / 4; t += 128) s4[t] = hin4[t];
    __syncthreads();

    int cg = tid & 63;
    int ng = tid >> 6;
    const float4* W4 = (const float4*)W;
    float4 acc[8];
#pragma unroll
    for (int r = 0; r < 8; r++) acc[r] = make_float4(0.f, 0.f, 0.f, 0.f);

#pragma unroll
    for (int k = 0; k < 16; k++) {
        float4 w = W4[k * 64 + cg];
#pragma unroll
        for (int r = 0; r < 8; r++) {
            float sv = s[ng * 8 + r][k];
            acc[r].x += sv * w.x; acc[r].y += sv * w.y;
            acc[r].z += sv * w.z; acc[r].w += sv * w.w;
        }
    }

    float4 as4 = ((const float4*)asrc)[cg];
    float4 ad4 = ((const float4*)adst)[cg];
#pragma unroll
    for (int r = 0; r < 8; r++) {
        int n = nb + ng * 8 + r;
        if (n >= NN) break;
        __half2 p0 = __floats2half2_rn(acc[r].x, acc[r].y);
        __half2 p1 = __floats2half2_rn(acc[r].z, acc[r].w);
        *(__half2*)&d_h1h[(size_t)n * 256 + cg * 4] = p0;
        *(__half2*)&d_h1h[(size_t)n * 256 + cg * 4 + 2] = p1;
        float vs = acc[r].x * as4.x + acc[r].y * as4.y + acc[r].z * as4.z + acc[r].w * as4.w;
        float vd = acc[r].x * ad4.x + acc[r].y * ad4.y + acc[r].z * ad4.z + acc[r].w * ad4.w;
        vs += __shfl_down_sync(0xffffffffu, vs, 2, 4);
        vs += __shfl_down_sync(0xffffffffu, vs, 1, 4);
        vd += __shfl_down_sync(0xffffffffu, vd, 2, 4);
        vd += __shfl_down_sync(0xffffffffu, vd, 1, 4);
        if ((cg & 3) == 0) {
            int h = cg >> 2;
            d_sa[n * 16 + h] = vs;
            d_da[n * 16 + h] = vd;
        }
    }
}

// ---------------- W prep: transpose + bf16 split for W2 and W3 ----------------
__global__ void k_prepW(const float* __restrict__ W2, const float* __restrict__ W3) {
    int idx = blockIdx.x * blockDim.x + threadIdx.x;
    if (idx >= 2 * 256 * 256) return;
    int sel = idx >> 16;
    int r = idx & 65535;
    int n = r >> 8, k = r & 255;
    float w = (sel ? W3 : W2)[k * 256 + n];
    __nv_bfloat16 h = __float2bfloat16_rn(w);
    __nv_bfloat16 l = __float2bfloat16_rn(w - __bfloat162float(h));
    if (sel) { d_W3hi[r] = h; d_W3lo[r] = l; }
    else     { d_W2hi[r] = h; d_W2lo[r] = l; }
}

// ---------------- tensor-core transform (bf16x3) + fused attention dots ----------------
#define MMA_BF16(C, A0, A1, A2, A3, B0, B1)                                  \
    asm volatile(                                                            \
        "mma.sync.aligned.m16n8k16.row.col.f32.bf16.bf16.f32 "               \
        "{%0,%1,%2,%3}, {%4,%5,%6,%7}, {%8,%9}, {%0,%1,%2,%3};\n"            \
        : "+f"(C[0]), "+f"(C[1]), "+f"(C[2]), "+f"(C[3])                     \
        : "r"(A0), "r"(A1), "r"(A2), "r"(A3), "r"(B0), "r"(B1))

#define LDSM4(R0, R1, R2, R3, ADDR)                                          \
    asm volatile("ldmatrix.sync.aligned.m8n8.x4.shared.b16 {%0,%1,%2,%3}, [%4];" \
        : "=r"(R0), "=r"(R1), "=r"(R2), "=r"(R3) : "r"(ADDR))

__global__ void __launch_bounds__(256, 1)
k_transform_mma(const __nv_bfloat16* __restrict__ Bhi, const __nv_bfloat16* __restrict__ Blo,
                const float* __restrict__ as_, const float* __restrict__ ad_) {
    extern __shared__ __nv_bfloat16 sm[];
    __nv_bfloat16* sAhi = sm;                       // 128 x PIT
    __nv_bfloat16* sAlo = sAhi + 128 * PIT;
    __nv_bfloat16* sBhi = sAlo + 128 * PIT;         // 64 x PIT
    __nv_bfloat16* sBlo = sBhi + 64 * PIT;

    int tid = threadIdx.x, lane = tid & 31, warp = tid >> 5;
    int m0 = blockIdx.x * 128;
    int n0 = blockIdx.y * 64;

    {
        const uint4* gH = (const uint4*)(d_Ahi + (size_t)m0 * 256);
        const uint4* gL = (const uint4*)(d_Alo + (size_t)m0 * 256);
        for (int i = tid; i < 128 * 32; i += 256) {
            int r = i >> 5, c = i & 31;
            *(uint4*)(sAhi + r * PIT + c * 8) = gH[r * 32 + c];
            *(uint4*)(sAlo + r * PIT + c * 8) = gL[r * 32 + c];
        }
        const uint4* bH = (const uint4*)(Bhi + (size_t)n0 * 256);
        const uint4* bL = (const uint4*)(Blo + (size_t)n0 * 256);
        for (int i = tid; i < 64 * 32; i += 256) {
            int r = i >> 5, c = i & 31;
            *(uint4*)(sBhi + r * PIT + c * 8) = bH[r * 32 + c];
            *(uint4*)(sBlo + r * PIT + c * 8) = bL[r * 32 + c];
        }
    }
    __syncthreads();

    float c[8][4];
#pragma unroll
    for (int t = 0; t < 8; t++)
#pragma unroll
        for (int j = 0; j < 4; j++) c[t][j] = 0.f;

    int rA = warp * 16 + (lane & 15);
    int kOff = (lane >> 4) << 3;
    unsigned aHiB = (unsigned)__cvta_generic_to_shared(sAhi + rA * PIT + kOff);
    unsigned aLoB = (unsigned)__cvta_generic_to_shared(sAlo + rA * PIT + kOff);
    int rB = lane & 15;
    unsigned bHiB = (unsigned)__cvta_generic_to_shared(sBhi + rB * PIT + kOff);
    unsigned bLoB = (unsigned)__cvta_generic_to_shared(sBlo + rB * PIT + kOff);

#pragma unroll 4
    for (int kc = 0; kc < 16; kc++) {
        unsigned ka = kc * 32;
        unsigned ah0, ah1, ah2, ah3, al0, al1, al2, al3;
        LDSM4(ah0, ah1, ah2, ah3, aHiB + ka);
        LDSM4(al0, al1, al2, al3, aLoB + ka);
        unsigned ahv[4] = {ah0, ah1, ah2, ah3};
        unsigned alv[4] = {al0, al1, al2, al3};
#pragma unroll
        for (int p = 0; p < 4; p++) {
            unsigned boff = (unsigned)(p * 16 * PIT * 2) + ka;
            unsigned bh0, bh1, bh2, bh3, bl0, bl1, bl2, bl3;
            LDSM4(bh0, bh1, bh2, bh3, bHiB + boff);
            LDSM4(bl0, bl1, bl2, bl3, bLoB + boff);
            MMA_BF16(c[2 * p],     ahv[0], ahv[1], ahv[2], ahv[3], bh0, bh2);
            MMA_BF16(c[2 * p],     alv[0], alv[1], alv[2], alv[3], bh0, bh2);
            MMA_BF16(c[2 * p],     ahv[0], ahv[1], ahv[2], ahv[3], bl0, bl2);
            MMA_BF16(c[2 * p + 1], ahv[0], ahv[1], ahv[2], ahv[3], bh1, bh3);
            MMA_BF16(c[2 * p + 1], alv[0], alv[1], alv[2], alv[3], bh1, bh3);
            MMA_BF16(c[2 * p + 1], ahv[0], ahv[1], ahv[2], ahv[3], bl1, bl3);
        }
    }

    // epilogue: fp16 h1 + fused attention dots (block slice = 4 whole heads)
    int row0 = m0 + warp * 16 + (lane >> 2);
    int row1 = row0 + 8;
    int cbase = (lane & 3) * 2;
    float vs0[4] = {0, 0, 0, 0}, vd0[4] = {0, 0, 0, 0};
    float vs1[4] = {0, 0, 0, 0}, vd1[4] = {0, 0, 0, 0};
#pragma unroll
    for (int t = 0; t < 8; t++) {
        int col = n0 + t * 8 + cbase;
        *(__half2*)&d_h1h[(size_t)row0 * 256 + col] = __floats2half2_rn(c[t][0], c[t][1]);
        *(__half2*)&d_h1h[(size_t)row1 * 256 + col] = __floats2half2_rn(c[t][2], c[t][3]);
        float2 a2 = *(const float2*)&as_[col];
        float2 d2 = *(const float2*)&ad_[col];
        int hh = t >> 1;
        vs0[hh] += c[t][0] * a2.x + c[t][1] * a2.y;
        vd0[hh] += c[t][0] * d2.x + c[t][1] * d2.y;
        vs1[hh] += c[t][2] * a2.x + c[t][3] * a2.y;
        vd1[hh] += c[t][2] * d2.x + c[t][3] * d2.y;
    }
#pragma unroll
    for (int hh = 0; hh < 4; hh++) {
        vs0[hh] += __shfl_down_sync(0xffffffffu, vs0[hh], 2, 4);
        vs0[hh] += __shfl_down_sync(0xffffffffu, vs0[hh], 1, 4);
        vd0[hh] += __shfl_down_sync(0xffffffffu, vd0[hh], 2, 4);
        vd0[hh] += __shfl_down_sync(0xffffffffu, vd0[hh], 1, 4);
        vs1[hh] += __shfl_down_sync(0xffffffffu, vs1[hh], 2, 4);
        vs1[hh] += __shfl_down_sync(0xffffffffu, vs1[hh], 1, 4);
        vd1[hh] += __shfl_down_sync(0xffffffffu, vd1[hh], 2, 4);
        vd1[hh] += __shfl_down_sync(0xffffffffu, vd1[hh], 1, 4);
    }
    if ((lane & 3) == 0) {
        int H0 = blockIdx.y * 4;
        if (row0 < NN) {
#pragma unroll
            for (int hh = 0; hh < 4; hh++) {
                d_sa[row0 * 16 + H0 + hh] = vs0[hh];
                d_da[row0 * 16 + H0 + hh] = vd0[hh];
            }
        }
        if (row1 < NN) {
#pragma unroll
            for (int hh = 0; hh < 4; hh++) {
                d_sa[row1 * 16 + H0 + hh] = vs1[hh];
                d_da[row1 * 16 + H0 + hh] = vd1[hh];
            }
        }
    }
}
#define SMEM_MMA ((2 * 128 * PIT + 2 * 64 * PIT) * 2)

// ---------------- GAT aggregation (fp16 gather; fp32 out OR split-bf16 out) ----------------
template <bool SPLIT>
__global__ void k_gat_agg(const float* __restrict__ b, float* __restrict__ outf) {
    int n = (blockIdx.x * blockDim.x + threadIdx.x) >> 5;
    if (n >= NN) return;
    int lane = threadIdx.x & 31;
    int hlane = lane & 15;
    float da_l = d_da[n * 16 + hlane];
    int beg = d_rowoff[n], end = d_rowoff[n + 1];

    float m = -1e30f;
    for (int e = beg + (lane >> 4); e < end; e += 2) {
        int s = d_csr[e];
        float l = d_sa[s * 16 + hlane] + da_l;
        l = l > 0.f ? l : 0.2f * l;
        m = fmaxf(m, l);
    }
    m = fmaxf(m, __shfl_xor_sync(0xffffffffu, m, 16));
    float mh = __shfl_sync(0xffffffffu, m, lane >> 1);

    float z = 0.f;
    float acc[8];
#pragma unroll
    for (int i = 0; i < 8; i++) acc[i] = 0.f;
    for (int e = beg; e < end; e++) {
        int s = d_csr[e];
        float l = d_sa[s * 16 + hlane] + da_l;
        l = l > 0.f ? l : 0.2f * l;
        float ev = __expf(__shfl_sync(0xffffffffu, l, lane >> 1) - mh);
        z += ev;
        uint4 hv = *(const uint4*)(d_h1h + (size_t)s * 256 + lane * 8);
        float2 f0 = __half22float2(*(__half2*)&hv.x);
        float2 f1 = __half22float2(*(__half2*)&hv.y);
        float2 f2 = __half22float2(*(__half2*)&hv.z);
        float2 f3 = __half22float2(*(__half2*)&hv.w);
        acc[0] += ev * f0.x; acc[1] += ev * f0.y; acc[2] += ev * f1.x; acc[3] += ev * f1.y;
        acc[4] += ev * f2.x; acc[5] += ev * f2.y; acc[6] += ev * f3.x; acc[7] += ev * f3.y;
    }
    float invz = 1.f / (z + 1e-16f);
    float vo[8];
#pragma unroll
    for (int i = 0; i < 8; i++) {
        float v = acc[i] * invz + b[lane * 8 + i];
        vo[i] = v > 0.f ? v : (__expf(v) - 1.f);
    }
    if (SPLIT) {
        unsigned hi[4], lo[4];
#pragma unroll
        for (int i = 0; i < 4; i++) {
            __nv_bfloat16 h0 = __float2bfloat16_rn(vo[2 * i]);
            __nv_bfloat16 h1 = __float2bfloat16_rn(vo[2 * i + 1]);
            hi[i] = pack2(h0, h1);
            lo[i] = pack2(__float2bfloat16_rn(vo[2 * i] - __bfloat162float(h0)),
                          __float2bfloat16_rn(vo[2 * i + 1] - __bfloat162float(h1)));
        }
        *(uint4*)&d_Ahi[(size_t)n * 256 + lane * 8] = make_uint4(hi[0], hi[1], hi[2], hi[3]);
        *(uint4*)&d_Alo[(size_t)n * 256 + lane * 8] = make_uint4(lo[0], lo[1], lo[2], lo[3]);
    } else {
        *(float4*)&outf[(size_t)n * 256 + lane * 8] = make_float4(vo[0], vo[1], vo[2], vo[3]);
        *(float4*)&outf[(size_t)n * 256 + lane * 8 + 4] = make_float4(vo[4], vo[5], vo[6], vo[7]);
    }
}

// ---------------- final ----------------
__global__ void k_final(const float* __restrict__ h, const int* __restrict__ ui,
                        const int* __restrict__ ii, const float* __restrict__ Wd,
                        float* __restrict__ out) {
    int p = (blockIdx.x * blockDim.x + threadIdx.x) >> 5;
    if (p >= 1024) return;
    int lane = threadIdx.x & 31;
    int u = ui[p], it = ii[p];
    float a0 = 0.f, a1 = 0.f;
    for (int k = lane; k < 256; k += 32) {
        float v = h[u * 256 + k];
        a0 += v * Wd[k * 2 + 0];
        a1 += v * Wd[k * 2 + 1];
        float w = h[it * 256 + k];
        a0 += w * Wd[(256 + k) * 2 + 0];
        a1 += w * Wd[(256 + k) * 2 + 1];
    }
#pragma unroll
    for (int off = 16; off >= 1; off >>= 1) {
        a0 += __shfl_down_sync(0xffffffffu, a0, off);
        a1 += __shfl_down_sync(0xffffffffu, a1, off);
    }
    if (lane == 0) {
        float mx = fmaxf(a0, a1);
        float lse = mx + __logf(__expf(a0 - mx) + __expf(a1 - mx));
        out[p * 2 + 0] = a0 - lse;
        out[p * 2 + 1] = a1 - lse;
    }
}

// ---------------- launcher ----------------
extern "C" void kernel_launch(void* const* d_in, const int* in_sizes, int n_in,
                              void* d_out, int out_size) {
    const float* x    = (const float*)d_in[0];
    const int*   ei   = (const int*)d_in[1];
    const float* Hd   = (const float*)d_in[2];
    const int*   ui   = (const int*)d_in[3];
    const int*   ii   = (const int*)d_in[4];
    const float* Wg   = (const float*)d_in[5];
    const float* bg   = (const float*)d_in[6];
    const float* W1   = (const float*)d_in[7];
    const float* a1s  = (const float*)d_in[8];
    const float* a1d  = (const float*)d_in[9];
    const float* b1   = (const float*)d_in[10];
    const float* W2   = (const float*)d_in[11];
    const float* a2s  = (const float*)d_in[12];
    const float* a2d  = (const float*)d_in[13];
    const float* b2   = (const float*)d_in[14];
    const float* W3   = (const float*)d_in[15];
    const float* a3s  = (const float*)d_in[16];
    const float* a3d  = (const float*)d_in[17];
    const float* b3   = (const float*)d_in[18];
    const float* wd   = (const float*)d_in[19];
    const float* wr   = (const float*)d_in[20];
    const float* wdnn = (const float*)d_in[21];
    float* out = (float*)d_out;

    void *p_h0, *p_bufA, *p_w2hi, *p_w2lo, *p_w3hi, *p_w3lo;
    cudaGetSymbolAddress(&p_h0, d_h0);
    cudaGetSymbolAddress(&p_bufA, d_bufA);
    cudaGetSymbolAddress(&p_w2hi, d_W2hi);
    cudaGetSymbolAddress(&p_w2lo, d_W2lo);
    cudaGetSymbolAddress(&p_w3hi, d_W3hi);
    cudaGetSymbolAddress(&p_w3lo, d_W3lo);
    float* h0   = (float*)p_h0;
    float* bufA = (float*)p_bufA;

    cudaFuncSetAttribute(k_transform_mma,
                         cudaFuncAttributeMaxDynamicSharedMemorySize, SMEM_MMA);

    k_init<<<(128 * 512 + 255) / 256, 256>>>();
    k_prepW<<<(2 * 256 * 256 + 255) / 256, 256>>>(W2, W3);
    k_gemm1<<<(4 * 128 * 512 + 255) / 256, 256>>>(wd, Hd);
    k_gemm2<<<(4 * 128 * 16 + 255) / 256, 256>>>(wr);
    k_count<<<(EE + 255) / 256, 256>>>(ei + EE);
    k_scan<<<1, 1024>>>();
    k_scatter<<<(ET + 255) / 256, 256>>>(ei);

    k_xw_dual<<<NN / 16, 256>>>(x, Wg);
    k_gcn_agg<<<(NN * 16 + 255) / 256, 256>>>(bg);

    // GAT layer 1
    k_transform16<<<NN / 16, 128>>>(h0, W1, a1s, a1d);
    k_gat_agg<true><<<(NN * 32 + 255) / 256, 256>>>(b1, nullptr);

    // GAT layer 2 (tensor cores, fused att dots)
    k_transform_mma<<<dim3(NP / 128, 4), 256, SMEM_MMA>>>(
        (const __nv_bfloat16*)p_w2hi, (const __nv_bfloat16*)p_w2lo, a2s, a2d);
    k_gat_agg<true><<<(NN * 32 + 255) / 256, 256>>>(b2, nullptr);

    // GAT layer 3
    k_transform_mma<<<dim3(NP / 128, 4), 256, SMEM_MMA>>>(
        (const __nv_bfloat16*)p_w3hi, (const __nv_bfloat16*)p_w3lo, a3s, a3d);
    k_gat_agg<false><<<(NN * 32 + 255) / 256, 256>>>(b3, bufA);

    k_final<<<(1024 * 32 + 255) / 256, 256>>>(bufA, ui, ii, wdnn, out);
}

// round 6
// speedup vs baseline: 2.0765x; 1.0644x over previous
#include <cuda_runtime.h>
#include <cuda_bf16.h>
#include <cuda_fp16.h>
#include <math.h>

#define NN 50000
#define NP 50048          // padded to 128
#define EE 800000
#define ET (EE + NN)      // edges + self loops
#define PIT 264           // smem row pitch (bf16): 33*16B -> LDSM conflict-free

// ---------------- scratch (device globals; no allocation allowed) ----------------
__device__ float d_T2[512 * 16];             // Hd @ Wr
__device__ float d_M[128 * 16];              // Wd @ T2
__device__ int   d_deg[NN];
__device__ int   d_rowoff[NN + 1];
__device__ int   d_cursor[NN];
__device__ float d_dis[NN];
__device__ int   d_csr[ET];
__device__ float d_xw[NN * 16];
__device__ float d_dual[NN * 16];
__device__ float d_h0[NN * 16];
__device__ __half d_h1h[NP * 256];           // fp16 transformed features (agg gather)
__device__ float d_bufA[NN * 256];
__device__ float d_sa[NN * 16];
__device__ float d_da[NN * 16];
__device__ __nv_bfloat16 d_Ahi[NP * 256];    // split input activations for MMA
__device__ __nv_bfloat16 d_Alo[NP * 256];
__device__ __nv_bfloat16 d_W2hi[256 * 256];  // W2^T split [n][k]
__device__ __nv_bfloat16 d_W2lo[256 * 256];
__device__ __nv_bfloat16 d_W3hi[256 * 256];
__device__ __nv_bfloat16 d_W3lo[256 * 256];

static __device__ __forceinline__ unsigned pack2(__nv_bfloat16 a, __nv_bfloat16 b) {
    unsigned short ua = *reinterpret_cast<unsigned short*>(&a);
    unsigned short ub = *reinterpret_cast<unsigned short*>(&b);
    return (unsigned)ua | ((unsigned)ub << 16);
}

// ---------------- init (+ zero gemm accumulators) ----------------
__global__ void k_init() {
    int i = blockIdx.x * blockDim.x + threadIdx.x;
    if (i < NN) { d_deg[i] = 1; d_cursor[i] = 0; }
    if (i < 512 * 16) d_T2[i] = 0.f;
    if (i < 128 * 16) d_M[i] = 0.f;
}

// ---------------- dual weight, reassociated: T2 = Hd @ Wr ; M = Wd @ T2 ----------------
__global__ void k_gemmA(const float* __restrict__ hd, const float* __restrict__ wr) {
    int idx = blockIdx.x * blockDim.x + threadIdx.x;   // 4 * 8192
    if (idx >= 4 * 512 * 16) return;
    int kc = idx >> 13;
    int r = idx & 8191;
    int i = r >> 4, j = r & 15;
    float a = 0.f;
    int k0 = kc * 128;
#pragma unroll 4
    for (int k = k0; k < k0 + 128; k++) a += hd[i * 512 + k] * wr[k * 16 + j];
    atomicAdd(&d_T2[r], a);
}

__global__ void k_gemmB(const float* __restrict__ wd) {
    int idx = blockIdx.x * blockDim.x + threadIdx.x;   // 8 * 2048
    if (idx >= 8 * 128 * 16) return;
    int kc = idx >> 11;
    int r = idx & 2047;
    int i = r >> 4, j = r & 15;
    float a = 0.f;
    int k0 = kc * 64;
#pragma unroll 4
    for (int k = k0; k < k0 + 64; k++) a += wd[i * 512 + k] * d_T2[k * 16 + j];
    atomicAdd(&d_M[r], a);
}

// ---------------- degree count ----------------
__global__ void k_count(const int* __restrict__ dst) {
    int e = blockIdx.x * blockDim.x + threadIdx.x;
    if (e < EE) atomicAdd(&d_deg[dst[e]], 1);
}

// ---------------- warp-shuffle scan (+ fused rsqrt degree) ----------------
__global__ void k_scan() {
    __shared__ int warp_sums[32];
    int t = threadIdx.x;
    const int S = 49;
    int b0 = t * S;
    int sum = 0;
    for (int i = 0; i < S; i++) {
        int idx = b0 + i;
        if (idx < NN) sum += d_deg[idx];
    }
    int lane = t & 31, w = t >> 5;
    int v = sum;
#pragma unroll
    for (int off = 1; off < 32; off <<= 1) {
        int u = __shfl_up_sync(0xffffffffu, v, off);
        if (lane >= off) v += u;
    }
    if (lane == 31) warp_sums[w] = v;
    __syncthreads();
    if (w == 0) {
        int ws = warp_sums[lane];
#pragma unroll
        for (int off = 1; off < 32; off <<= 1) {
            int u = __shfl_up_sync(0xffffffffu, ws, off);
            if (lane >= off) ws += u;
        }
        warp_sums[lane] = ws;
    }
    __syncthreads();
    int ex = v - sum + (w > 0 ? warp_sums[w - 1] : 0);
    int run = ex;
    for (int i = 0; i < S; i++) {
        int idx = b0 + i;
        if (idx < NN) {
            int dg = d_deg[idx];
            run += dg;
            d_rowoff[idx + 1] = run;
            d_dis[idx] = rsqrtf((float)dg);
        }
    }
    if (t == 0) d_rowoff[0] = 0;
}

__global__ void k_scatter(const int* __restrict__ ei) {
    int e = blockIdx.x * blockDim.x + threadIdx.x;
    if (e >= ET) return;
    int s, dd;
    if (e < EE) { s = ei[e]; dd = ei[EE + e]; }
    else        { s = dd = e - EE; }
    int p = atomicAdd(&d_cursor[dd], 1);
    d_csr[d_rowoff[dd] + p] = s;
}

// ---------------- GCN feature transform + dual (smem staged) ----------------
__global__ void __launch_bounds__(256)
k_xw_dual(const float* __restrict__ x, const float* __restrict__ Wg) {
    __shared__ float sx[16][132];
    int tid = threadIdx.x;
    int nb = blockIdx.x * 16;
    const float4* xs = (const float4*)(x + (size_t)nb * 128);
    for (int i = tid; i < 512; i += 256) {
        float4 v = xs[i];
        int r = i >> 5, c = (i & 31) * 4;
        sx[r][c] = v.x; sx[r][c + 1] = v.y; sx[r][c + 2] = v.z; sx[r][c + 3] = v.w;
    }
    __syncthreads();
    int nl = tid >> 4, j = tid & 15;
    float a = 0.f, b = 0.f;
#pragma unroll 4
    for (int k = 0; k < 128; k++) {
        float xv = sx[nl][k];
        a += xv * Wg[k * 16 + j];
        b += xv * d_M[k * 16 + j];
    }
    int n = nb + nl;
    d_xw[n * 16 + j] = a;
    d_dual[n * 16 + j] = b;
}

// ---------------- GCN aggregation + dual + elu -> h0 ----------------
__global__ void k_gcn_agg(const float* __restrict__ bg) {
    int g = (blockIdx.x * blockDim.x + threadIdx.x) >> 4;
    int j = threadIdx.x & 15;
    if (g >= NN) return;
    int beg = d_rowoff[g], end = d_rowoff[g + 1];
    float acc = 0.f;
    for (int e = beg; e < end; e++) {
        int s = d_csr[e];
        acc += d_dis[s] * d_xw[s * 16 + j];
    }
    float v = acc * d_dis[g] + bg[j] + d_dual[g * 16 + j];
    d_h0[g * 16 + j] = v > 0.f ? v : (__expf(v) - 1.f);
}

// ---------------- GAT layer-1 transform (FIN=16, FFMA; writes fp16 h1) ----------------
__global__ void __launch_bounds__(128, 8)
k_transform16(const float* __restrict__ hin, const float* __restrict__ W,
              const float* __restrict__ asrc, const float* __restrict__ adst) {
    __shared__ float s[16][16];
    int tid = threadIdx.x;
    int nb = blockIdx.x * 16;
    const float4* hin4 = (const float4*)(hin + nb * 16);
    float4* s4 = (float4*)s;
    for (int t = tid; t < 16 * 16 / 4; t += 128) s4[t] = hin4[t];
    __syncthreads();

    int cg = tid & 63;
    int ng = tid >> 6;
    const float4* W4 = (const float4*)W;
    float4 acc[8];
#pragma unroll
    for (int r = 0; r < 8; r++) acc[r] = make_float4(0.f, 0.f, 0.f, 0.f);

#pragma unroll
    for (int k = 0; k < 16; k++) {
        float4 w = W4[k * 64 + cg];
#pragma unroll
        for (int r = 0; r < 8; r++) {
            float sv = s[ng * 8 + r][k];
            acc[r].x += sv * w.x; acc[r].y += sv * w.y;
            acc[r].z += sv * w.z; acc[r].w += sv * w.w;
        }
    }

    float4 as4 = ((const float4*)asrc)[cg];
    float4 ad4 = ((const float4*)adst)[cg];
#pragma unroll
    for (int r = 0; r < 8; r++) {
        int n = nb + ng * 8 + r;
        if (n >= NN) break;
        __half2 p0 = __floats2half2_rn(acc[r].x, acc[r].y);
        __half2 p1 = __floats2half2_rn(acc[r].z, acc[r].w);
        *(__half2*)&d_h1h[(size_t)n * 256 + cg * 4] = p0;
        *(__half2*)&d_h1h[(size_t)n * 256 + cg * 4 + 2] = p1;
        float vs = acc[r].x * as4.x + acc[r].y * as4.y + acc[r].z * as4.z + acc[r].w * as4.w;
        float vd = acc[r].x * ad4.x + acc[r].y * ad4.y + acc[r].z * ad4.z + acc[r].w * ad4.w;
        vs += __shfl_down_sync(0xffffffffu, vs, 2, 4);
        vs += __shfl_down_sync(0xffffffffu, vs, 1, 4);
        vd += __shfl_down_sync(0xffffffffu, vd, 2, 4);
        vd += __shfl_down_sync(0xffffffffu, vd, 1, 4);
        if ((cg & 3) == 0) {
            int h = cg >> 2;
            d_sa[n * 16 + h] = vs;
            d_da[n * 16 + h] = vd;
        }
    }
}

// ---------------- W prep: transpose + bf16 split for W2 and W3 ----------------
__global__ void k_prepW(const float* __restrict__ W2, const float* __restrict__ W3) {
    int idx = blockIdx.x * blockDim.x + threadIdx.x;
    if (idx >= 2 * 256 * 256) return;
    int sel = idx >> 16;
    int r = idx & 65535;
    int n = r >> 8, k = r & 255;
    float w = (sel ? W3 : W2)[k * 256 + n];
    __nv_bfloat16 h = __float2bfloat16_rn(w);
    __nv_bfloat16 l = __float2bfloat16_rn(w - __bfloat162float(h));
    if (sel) { d_W3hi[r] = h; d_W3lo[r] = l; }
    else     { d_W2hi[r] = h; d_W2lo[r] = l; }
}

// ---------------- tensor-core transform (bf16x3) + fused attention dots ----------------
#define MMA_BF16(C, A0, A1, A2, A3, B0, B1)                                  \
    asm volatile(                                                            \
        "mma.sync.aligned.m16n8k16.row.col.f32.bf16.bf16.f32 "               \
        "{%0,%1,%2,%3}, {%4,%5,%6,%7}, {%8,%9}, {%0,%1,%2,%3};\n"            \
        : "+f"(C[0]), "+f"(C[1]), "+f"(C[2]), "+f"(C[3])                     \
        : "r"(A0), "r"(A1), "r"(A2), "r"(A3), "r"(B0), "r"(B1))

#define LDSM4(R0, R1, R2, R3, ADDR)                                          \
    asm volatile("ldmatrix.sync.aligned.m8n8.x4.shared.b16 {%0,%1,%2,%3}, [%4];" \
        : "=r"(R0), "=r"(R1), "=r"(R2), "=r"(R3) : "r"(ADDR))

__global__ void __launch_bounds__(256, 1)
k_transform_mma(const __nv_bfloat16* __restrict__ Bhi, const __nv_bfloat16* __restrict__ Blo,
                const float* __restrict__ as_, const float* __restrict__ ad_) {
    extern __shared__ __nv_bfloat16 sm[];
    __nv_bfloat16* sAhi = sm;                       // 128 x PIT
    __nv_bfloat16* sAlo = sAhi + 128 * PIT;
    __nv_bfloat16* sBhi = sAlo + 128 * PIT;         // 64 x PIT
    __nv_bfloat16* sBlo = sBhi + 64 * PIT;

    int tid = threadIdx.x, lane = tid & 31, warp = tid >> 5;
    int m0 = blockIdx.x * 128;
    int n0 = blockIdx.y * 64;

    {
        const uint4* gH = (const uint4*)(d_Ahi + (size_t)m0 * 256);
        const uint4* gL = (const uint4*)(d_Alo + (size_t)m0 * 256);
        for (int i = tid; i < 128 * 32; i += 256) {
            int r = i >> 5, c = i & 31;
            *(uint4*)(sAhi + r * PIT + c * 8) = gH[r * 32 + c];
            *(uint4*)(sAlo + r * PIT + c * 8) = gL[r * 32 + c];
        }
        const uint4* bH = (const uint4*)(Bhi + (size_t)n0 * 256);
        const uint4* bL = (const uint4*)(Blo + (size_t)n0 * 256);
        for (int i = tid; i < 64 * 32; i += 256) {
            int r = i >> 5, c = i & 31;
            *(uint4*)(sBhi + r * PIT + c * 8) = bH[r * 32 + c];
            *(uint4*)(sBlo + r * PIT + c * 8) = bL[r * 32 + c];
        }
    }
    __syncthreads();

    float c[8][4];
#pragma unroll
    for (int t = 0; t < 8; t++)
#pragma unroll
        for (int j = 0; j < 4; j++) c[t][j] = 0.f;

    int rA = warp * 16 + (lane & 15);
    int kOff = (lane >> 4) << 3;
    unsigned aHiB = (unsigned)__cvta_generic_to_shared(sAhi + rA * PIT + kOff);
    unsigned aLoB = (unsigned)__cvta_generic_to_shared(sAlo + rA * PIT + kOff);
    int rB = lane & 15;
    unsigned bHiB = (unsigned)__cvta_generic_to_shared(sBhi + rB * PIT + kOff);
    unsigned bLoB = (unsigned)__cvta_generic_to_shared(sBlo + rB * PIT + kOff);

#pragma unroll 4
    for (int kc = 0; kc < 16; kc++) {
        unsigned ka = kc * 32;
        unsigned ah0, ah1, ah2, ah3, al0, al1, al2, al3;
        LDSM4(ah0, ah1, ah2, ah3, aHiB + ka);
        LDSM4(al0, al1, al2, al3, aLoB + ka);
        unsigned ahv[4] = {ah0, ah1, ah2, ah3};
        unsigned alv[4] = {al0, al1, al2, al3};
#pragma unroll
        for (int p = 0; p < 4; p++) {
            unsigned boff = (unsigned)(p * 16 * PIT * 2) + ka;
            unsigned bh0, bh1, bh2, bh3, bl0, bl1, bl2, bl3;
            LDSM4(bh0, bh1, bh2, bh3, bHiB + boff);
            LDSM4(bl0, bl1, bl2, bl3, bLoB + boff);
            MMA_BF16(c[2 * p],     ahv[0], ahv[1], ahv[2], ahv[3], bh0, bh2);
            MMA_BF16(c[2 * p],     alv[0], alv[1], alv[2], alv[3], bh0, bh2);
            MMA_BF16(c[2 * p],     ahv[0], ahv[1], ahv[2], ahv[3], bl0, bl2);
            MMA_BF16(c[2 * p + 1], ahv[0], ahv[1], ahv[2], ahv[3], bh1, bh3);
            MMA_BF16(c[2 * p + 1], alv[0], alv[1], alv[2], alv[3], bh1, bh3);
            MMA_BF16(c[2 * p + 1], ahv[0], ahv[1], ahv[2], ahv[3], bl1, bl3);
        }
    }

    // epilogue: fp16 h1 + fused attention dots (block slice = 4 whole heads)
    int row0 = m0 + warp * 16 + (lane >> 2);
    int row1 = row0 + 8;
    int cbase = (lane & 3) * 2;
    float vs0[4] = {0, 0, 0, 0}, vd0[4] = {0, 0, 0, 0};
    float vs1[4] = {0, 0, 0, 0}, vd1[4] = {0, 0, 0, 0};
#pragma unroll
    for (int t = 0; t < 8; t++) {
        int col = n0 + t * 8 + cbase;
        *(__half2*)&d_h1h[(size_t)row0 * 256 + col] = __floats2half2_rn(c[t][0], c[t][1]);
        *(__half2*)&d_h1h[(size_t)row1 * 256 + col] = __floats2half2_rn(c[t][2], c[t][3]);
        float2 a2 = *(const float2*)&as_[col];
        float2 d2 = *(const float2*)&ad_[col];
        int hh = t >> 1;
        vs0[hh] += c[t][0] * a2.x + c[t][1] * a2.y;
        vd0[hh] += c[t][0] * d2.x + c[t][1] * d2.y;
        vs1[hh] += c[t][2] * a2.x + c[t][3] * a2.y;
        vd1[hh] += c[t][2] * d2.x + c[t][3] * d2.y;
    }
#pragma unroll
    for (int hh = 0; hh < 4; hh++) {
        vs0[hh] += __shfl_down_sync(0xffffffffu, vs0[hh], 2, 4);
        vs0[hh] += __shfl_down_sync(0xffffffffu, vs0[hh], 1, 4);
        vd0[hh] += __shfl_down_sync(0xffffffffu, vd0[hh], 2, 4);
        vd0[hh] += __shfl_down_sync(0xffffffffu, vd0[hh], 1, 4);
        vs1[hh] += __shfl_down_sync(0xffffffffu, vs1[hh], 2, 4);
        vs1[hh] += __shfl_down_sync(0xffffffffu, vs1[hh], 1, 4);
        vd1[hh] += __shfl_down_sync(0xffffffffu, vd1[hh], 2, 4);
        vd1[hh] += __shfl_down_sync(0xffffffffu, vd1[hh], 1, 4);
    }
    if ((lane & 3) == 0) {
        int H0 = blockIdx.y * 4;
        if (row0 < NN) {
#pragma unroll
            for (int hh = 0; hh < 4; hh++) {
                d_sa[row0 * 16 + H0 + hh] = vs0[hh];
                d_da[row0 * 16 + H0 + hh] = vd0[hh];
            }
        }
        if (row1 < NN) {
#pragma unroll
            for (int hh = 0; hh < 4; hh++) {
                d_sa[row1 * 16 + H0 + hh] = vs1[hh];
                d_da[row1 * 16 + H0 + hh] = vd1[hh];
            }
        }
    }
}
#define SMEM_MMA ((2 * 128 * PIT + 2 * 64 * PIT) * 2)

// ---------------- GAT aggregation: single-pass online softmax ----------------
template <bool SPLIT>
__global__ void k_gat_agg(const float* __restrict__ b, float* __restrict__ outf) {
    int n = (blockIdx.x * blockDim.x + threadIdx.x) >> 5;
    if (n >= NN) return;
    int lane = threadIdx.x & 31;
    int hd = lane >> 1;                 // head owned by this lane's channels
    float da_l = d_da[n * 16 + hd];
    int beg = d_rowoff[n], end = d_rowoff[n + 1];

    float m = -1e30f, z = 0.f;
    float acc[8];
#pragma unroll
    for (int i = 0; i < 8; i++) acc[i] = 0.f;

    for (int e = beg; e < end; e++) {
        int s = d_csr[e];
        float l = d_sa[s * 16 + hd] + da_l;
        l = l > 0.f ? l : 0.2f * l;
        if (l > m) {
            float sc = __expf(m - l);
            z *= sc;
#pragma unroll
            for (int i = 0; i < 8; i++) acc[i] *= sc;
            m = l;
        }
        float ev = __expf(l - m);
        z += ev;
        uint4 hv = *(const uint4*)(d_h1h + (size_t)s * 256 + lane * 8);
        float2 f0 = __half22float2(*(__half2*)&hv.x);
        float2 f1 = __half22float2(*(__half2*)&hv.y);
        float2 f2 = __half22float2(*(__half2*)&hv.z);
        float2 f3 = __half22float2(*(__half2*)&hv.w);
        acc[0] += ev * f0.x; acc[1] += ev * f0.y; acc[2] += ev * f1.x; acc[3] += ev * f1.y;
        acc[4] += ev * f2.x; acc[5] += ev * f2.y; acc[6] += ev * f3.x; acc[7] += ev * f3.y;
    }
    float invz = 1.f / (z + 1e-16f);
    float vo[8];
#pragma unroll
    for (int i = 0; i < 8; i++) {
        float v = acc[i] * invz + b[lane * 8 + i];
        vo[i] = v > 0.f ? v : (__expf(v) - 1.f);
    }
    if (SPLIT) {
        unsigned hi[4], lo[4];
#pragma unroll
        for (int i = 0; i < 4; i++) {
            __nv_bfloat16 h0 = __float2bfloat16_rn(vo[2 * i]);
            __nv_bfloat16 h1 = __float2bfloat16_rn(vo[2 * i + 1]);
            hi[i] = pack2(h0, h1);
            lo[i] = pack2(__float2bfloat16_rn(vo[2 * i] - __bfloat162float(h0)),
                          __float2bfloat16_rn(vo[2 * i + 1] - __bfloat162float(h1)));
        }
        *(uint4*)&d_Ahi[(size_t)n * 256 + lane * 8] = make_uint4(hi[0], hi[1], hi[2], hi[3]);
        *(uint4*)&d_Alo[(size_t)n * 256 + lane * 8] = make_uint4(lo[0], lo[1], lo[2], lo[3]);
    } else {
        *(float4*)&outf[(size_t)n * 256 + lane * 8] = make_float4(vo[0], vo[1], vo[2], vo[3]);
        *(float4*)&outf[(size_t)n * 256 + lane * 8 + 4] = make_float4(vo[4], vo[5], vo[6], vo[7]);
    }
}

// ---------------- final ----------------
__global__ void k_final(const float* __restrict__ h, const int* __restrict__ ui,
                        const int* __restrict__ ii, const float* __restrict__ Wd,
                        float* __restrict__ out) {
    int p = (blockIdx.x * blockDim.x + threadIdx.x) >> 5;
    if (p >= 1024) return;
    int lane = threadIdx.x & 31;
    int u = ui[p], it = ii[p];
    float a0 = 0.f, a1 = 0.f;
    for (int k = lane; k < 256; k += 32) {
        float v = h[u * 256 + k];
        a0 += v * Wd[k * 2 + 0];
        a1 += v * Wd[k * 2 + 1];
        float w = h[it * 256 + k];
        a0 += w * Wd[(256 + k) * 2 + 0];
        a1 += w * Wd[(256 + k) * 2 + 1];
    }
#pragma unroll
    for (int off = 16; off >= 1; off >>= 1) {
        a0 += __shfl_down_sync(0xffffffffu, a0, off);
        a1 += __shfl_down_sync(0xffffffffu, a1, off);
    }
    if (lane == 0) {
        float mx = fmaxf(a0, a1);
        float lse = mx + __logf(__expf(a0 - mx) + __expf(a1 - mx));
        out[p * 2 + 0] = a0 - lse;
        out[p * 2 + 1] = a1 - lse;
    }
}

// ---------------- launcher ----------------
extern "C" void kernel_launch(void* const* d_in, const int* in_sizes, int n_in,
                              void* d_out, int out_size) {
    const float* x    = (const float*)d_in[0];
    const int*   ei   = (const int*)d_in[1];
    const float* Hd   = (const float*)d_in[2];
    const int*   ui   = (const int*)d_in[3];
    const int*   ii   = (const int*)d_in[4];
    const float* Wg   = (const float*)d_in[5];
    const float* bg   = (const float*)d_in[6];
    const float* W1   = (const float*)d_in[7];
    const float* a1s  = (const float*)d_in[8];
    const float* a1d  = (const float*)d_in[9];
    const float* b1   = (const float*)d_in[10];
    const float* W2   = (const float*)d_in[11];
    const float* a2s  = (const float*)d_in[12];
    const float* a2d  = (const float*)d_in[13];
    const float* b2   = (const float*)d_in[14];
    const float* W3   = (const float*)d_in[15];
    const float* a3s  = (const float*)d_in[16];
    const float* a3d  = (const float*)d_in[17];
    const float* b3   = (const float*)d_in[18];
    const float* wd   = (const float*)d_in[19];
    const float* wr   = (const float*)d_in[20];
    const float* wdnn = (const float*)d_in[21];
    float* out = (float*)d_out;

    void *p_h0, *p_bufA, *p_w2hi, *p_w2lo, *p_w3hi, *p_w3lo;
    cudaGetSymbolAddress(&p_h0, d_h0);
    cudaGetSymbolAddress(&p_bufA, d_bufA);
    cudaGetSymbolAddress(&p_w2hi, d_W2hi);
    cudaGetSymbolAddress(&p_w2lo, d_W2lo);
    cudaGetSymbolAddress(&p_w3hi, d_W3hi);
    cudaGetSymbolAddress(&p_w3lo, d_W3lo);
    float* h0   = (float*)p_h0;
    float* bufA = (float*)p_bufA;

    cudaFuncSetAttribute(k_transform_mma,
                         cudaFuncAttributeMaxDynamicSharedMemorySize, SMEM_MMA);

    k_init<<<(NN + 255) / 256, 256>>>();
    k_prepW<<<(2 * 256 * 256 + 255) / 256, 256>>>(W2, W3);
    k_gemmA<<<(4 * 512 * 16 + 255) / 256, 256>>>(Hd, wr);
    k_gemmB<<<(8 * 128 * 16 + 255) / 256, 256>>>(wd);
    k_count<<<(EE + 255) / 256, 256>>>(ei + EE);
    k_scan<<<1, 1024>>>();
    k_scatter<<<(ET + 255) / 256, 256>>>(ei);

    k_xw_dual<<<NN / 16, 256>>>(x, Wg);
    k_gcn_agg<<<(NN * 16 + 255) / 256, 256>>>(bg);

    // GAT layer 1
    k_transform16<<<NN / 16, 128>>>(h0, W1, a1s, a1d);
    k_gat_agg<true><<<(NN * 32 + 255) / 256, 256>>>(b1, nullptr);

    // GAT layer 2 (tensor cores, fused att dots)
    k_transform_mma<<<dim3(NP / 128, 4), 256, SMEM_MMA>>>(
        (const __nv_bfloat16*)p_w2hi, (const __nv_bfloat16*)p_w2lo, a2s, a2d);
    k_gat_agg<true><<<(NN * 32 + 255) / 256, 256>>>(b2, nullptr);

    // GAT layer 3
    k_transform_mma<<<dim3(NP / 128, 4), 256, SMEM_MMA>>>(
        (const __nv_bfloat16*)p_w3hi, (const __nv_bfloat16*)p_w3lo, a3s, a3d);
    k_gat_agg<false><<<(NN * 32 + 255) / 256, 256>>>(b3, bufA);

    k_final<<<(1024 * 32 + 255) / 256, 256>>>(bufA, ui, ii, wdnn, out);
}

// round 7
// speedup vs baseline: 2.1508x; 1.0358x over previous
#include <cuda_runtime.h>
#include <cuda_bf16.h>
#include <cuda_fp16.h>
#include <math.h>

#define NN 50000
#define NP 50048          // padded to 128
#define EE 800000
#define ET (EE + NN)      // edges + self loops
#define PIT 264           // smem row pitch (bf16): 33*16B -> LDSM conflict-free

// ---------------- scratch (device globals; no allocation allowed) ----------------
__device__ float d_T2[512 * 16];             // Hd @ Wr
__device__ float d_M[128 * 16];              // Wd @ T2
__device__ int   d_deg[NN];
__device__ int   d_rowoff[NN + 1];
__device__ int   d_cursor[NN];
__device__ float d_dis[NN];
__device__ int   d_csr[ET];
__device__ float d_xw[NN * 16];
__device__ float d_dual[NN * 16];
__device__ float d_h0[NN * 16];
__device__ __half d_h1h[NP * 256];           // fp16 transformed features (agg gather)
__device__ float d_bufA[NN * 256];
__device__ float d_sa[NN * 16];
__device__ float d_da[NN * 16];
__device__ __nv_bfloat16 d_Ahi[NP * 256];    // split input activations for MMA
__device__ __nv_bfloat16 d_Alo[NP * 256];
__device__ __nv_bfloat16 d_W2hi[256 * 256];  // W2^T split [n][k]
__device__ __nv_bfloat16 d_W2lo[256 * 256];
__device__ __nv_bfloat16 d_W3hi[256 * 256];
__device__ __nv_bfloat16 d_W3lo[256 * 256];

static __device__ __forceinline__ unsigned pack2(__nv_bfloat16 a, __nv_bfloat16 b) {
    unsigned short ua = *reinterpret_cast<unsigned short*>(&a);
    unsigned short ub = *reinterpret_cast<unsigned short*>(&b);
    return (unsigned)ua | ((unsigned)ub << 16);
}

// ---------------- init ----------------
__global__ void k_init() {
    int i = blockIdx.x * blockDim.x + threadIdx.x;
    if (i < NN) { d_deg[i] = 1; d_cursor[i] = 0; }
}

// ---------------- dual weight: warp-per-output, no atomics ----------------
// T2[512,16] = Hd[512,512] @ Wr[512,16]
__global__ void k_gemmA(const float* __restrict__ hd, const float* __restrict__ wr) {
    int w = (blockIdx.x * blockDim.x + threadIdx.x) >> 5;
    if (w >= 512 * 16) return;
    int lane = threadIdx.x & 31;
    int i = w >> 4, j = w & 15;
    float a = 0.f;
#pragma unroll
    for (int kk = 0; kk < 16; kk++) {
        int k = lane + kk * 32;
        a += hd[i * 512 + k] * wr[k * 16 + j];
    }
#pragma unroll
    for (int off = 16; off >= 1; off >>= 1)
        a += __shfl_down_sync(0xffffffffu, a, off);
    if (lane == 0) d_T2[w] = a;
}

// M[128,16] = Wd[128,512] @ T2[512,16]
__global__ void k_gemmB(const float* __restrict__ wd) {
    int w = (blockIdx.x * blockDim.x + threadIdx.x) >> 5;
    if (w >= 128 * 16) return;
    int lane = threadIdx.x & 31;
    int i = w >> 4, j = w & 15;
    float a = 0.f;
#pragma unroll
    for (int kk = 0; kk < 16; kk++) {
        int k = lane + kk * 32;
        a += wd[i * 512 + k] * d_T2[k * 16 + j];
    }
#pragma unroll
    for (int off = 16; off >= 1; off >>= 1)
        a += __shfl_down_sync(0xffffffffu, a, off);
    if (lane == 0) d_M[w] = a;
}

// ---------------- degree count (4 edges/thread) ----------------
__global__ void k_count(const int* __restrict__ dst) {
    int t = blockIdx.x * blockDim.x + threadIdx.x;
    int e0 = t * 4;
    if (e0 + 3 < EE) {
        int4 d4 = *(const int4*)(dst + e0);
        atomicAdd(&d_deg[d4.x], 1);
        atomicAdd(&d_deg[d4.y], 1);
        atomicAdd(&d_deg[d4.z], 1);
        atomicAdd(&d_deg[d4.w], 1);
    } else {
        for (int e = e0; e < EE; e++) atomicAdd(&d_deg[dst[e]], 1);
    }
}

// ---------------- warp-shuffle scan (+ fused rsqrt degree) ----------------
__global__ void k_scan() {
    __shared__ int warp_sums[32];
    int t = threadIdx.x;
    const int S = 49;
    int b0 = t * S;
    int sum = 0;
    for (int i = 0; i < S; i++) {
        int idx = b0 + i;
        if (idx < NN) sum += d_deg[idx];
    }
    int lane = t & 31, w = t >> 5;
    int v = sum;
#pragma unroll
    for (int off = 1; off < 32; off <<= 1) {
        int u = __shfl_up_sync(0xffffffffu, v, off);
        if (lane >= off) v += u;
    }
    if (lane == 31) warp_sums[w] = v;
    __syncthreads();
    if (w == 0) {
        int ws = warp_sums[lane];
#pragma unroll
        for (int off = 1; off < 32; off <<= 1) {
            int u = __shfl_up_sync(0xffffffffu, ws, off);
            if (lane >= off) ws += u;
        }
        warp_sums[lane] = ws;
    }
    __syncthreads();
    int ex = v - sum + (w > 0 ? warp_sums[w - 1] : 0);
    int run = ex;
    for (int i = 0; i < S; i++) {
        int idx = b0 + i;
        if (idx < NN) {
            int dg = d_deg[idx];
            run += dg;
            d_rowoff[idx + 1] = run;
            d_dis[idx] = rsqrtf((float)dg);
        }
    }
    if (t == 0) d_rowoff[0] = 0;
}

__global__ void k_scatter(const int* __restrict__ ei) {
    int e = blockIdx.x * blockDim.x + threadIdx.x;
    if (e >= ET) return;
    int s, dd;
    if (e < EE) { s = ei[e]; dd = ei[EE + e]; }
    else        { s = dd = e - EE; }
    int p = atomicAdd(&d_cursor[dd], 1);
    d_csr[d_rowoff[dd] + p] = s;
}

// ---------------- GCN feature transform + dual (smem staged) ----------------
__global__ void __launch_bounds__(256)
k_xw_dual(const float* __restrict__ x, const float* __restrict__ Wg) {
    __shared__ float sx[16][132];
    int tid = threadIdx.x;
    int nb = blockIdx.x * 16;
    const float4* xs = (const float4*)(x + (size_t)nb * 128);
    for (int i = tid; i < 512; i += 256) {
        float4 v = xs[i];
        int r = i >> 5, c = (i & 31) * 4;
        sx[r][c] = v.x; sx[r][c + 1] = v.y; sx[r][c + 2] = v.z; sx[r][c + 3] = v.w;
    }
    __syncthreads();
    int nl = tid >> 4, j = tid & 15;
    float a = 0.f, b = 0.f;
#pragma unroll 4
    for (int k = 0; k < 128; k++) {
        float xv = sx[nl][k];
        a += xv * Wg[k * 16 + j];
        b += xv * d_M[k * 16 + j];
    }
    int n = nb + nl;
    d_xw[n * 16 + j] = a;
    d_dual[n * 16 + j] = b;
}

// ---------------- GCN aggregation + dual + elu -> h0 ----------------
__global__ void k_gcn_agg(const float* __restrict__ bg) {
    int g = (blockIdx.x * blockDim.x + threadIdx.x) >> 4;
    int j = threadIdx.x & 15;
    if (g >= NN) return;
    int beg = d_rowoff[g], end = d_rowoff[g + 1];
    float acc = 0.f;
    for (int e = beg; e < end; e++) {
        int s = d_csr[e];
        acc += d_dis[s] * d_xw[s * 16 + j];
    }
    float v = acc * d_dis[g] + bg[j] + d_dual[g * 16 + j];
    d_h0[g * 16 + j] = v > 0.f ? v : (__expf(v) - 1.f);
}

// ---------------- GAT layer-1 transform (FIN=16, FFMA; writes fp16 h1) ----------------
__global__ void __launch_bounds__(128, 8)
k_transform16(const float* __restrict__ hin, const float* __restrict__ W,
              const float* __restrict__ asrc, const float* __restrict__ adst) {
    __shared__ float s[16][16];
    int tid = threadIdx.x;
    int nb = blockIdx.x * 16;
    const float4* hin4 = (const float4*)(hin + nb * 16);
    float4* s4 = (float4*)s;
    for (int t = tid; t < 16 * 16 / 4; t += 128) s4[t] = hin4[t];
    __syncthreads();

    int cg = tid & 63;
    int ng = tid >> 6;
    const float4* W4 = (const float4*)W;
    float4 acc[8];
#pragma unroll
    for (int r = 0; r < 8; r++) acc[r] = make_float4(0.f, 0.f, 0.f, 0.f);

#pragma unroll
    for (int k = 0; k < 16; k++) {
        float4 w = W4[k * 64 + cg];
#pragma unroll
        for (int r = 0; r < 8; r++) {
            float sv = s[ng * 8 + r][k];
            acc[r].x += sv * w.x; acc[r].y += sv * w.y;
            acc[r].z += sv * w.z; acc[r].w += sv * w.w;
        }
    }

    float4 as4 = ((const float4*)asrc)[cg];
    float4 ad4 = ((const float4*)adst)[cg];
#pragma unroll
    for (int r = 0; r < 8; r++) {
        int n = nb + ng * 8 + r;
        if (n >= NN) break;
        __half2 p0 = __floats2half2_rn(acc[r].x, acc[r].y);
        __half2 p1 = __floats2half2_rn(acc[r].z, acc[r].w);
        *(__half2*)&d_h1h[(size_t)n * 256 + cg * 4] = p0;
        *(__half2*)&d_h1h[(size_t)n * 256 + cg * 4 + 2] = p1;
        float vs = acc[r].x * as4.x + acc[r].y * as4.y + acc[r].z * as4.z + acc[r].w * as4.w;
        float vd = acc[r].x * ad4.x + acc[r].y * ad4.y + acc[r].z * ad4.z + acc[r].w * ad4.w;
        vs += __shfl_down_sync(0xffffffffu, vs, 2, 4);
        vs += __shfl_down_sync(0xffffffffu, vs, 1, 4);
        vd += __shfl_down_sync(0xffffffffu, vd, 2, 4);
        vd += __shfl_down_sync(0xffffffffu, vd, 1, 4);
        if ((cg & 3) == 0) {
            int h = cg >> 2;
            d_sa[n * 16 + h] = vs;
            d_da[n * 16 + h] = vd;
        }
    }
}

// ---------------- W prep: transpose + bf16 split for W2 and W3 ----------------
__global__ void k_prepW(const float* __restrict__ W2, const float* __restrict__ W3) {
    int idx = blockIdx.x * blockDim.x + threadIdx.x;
    if (idx >= 2 * 256 * 256) return;
    int sel = idx >> 16;
    int r = idx & 65535;
    int n = r >> 8, k = r & 255;
    float w = (sel ? W3 : W2)[k * 256 + n];
    __nv_bfloat16 h = __float2bfloat16_rn(w);
    __nv_bfloat16 l = __float2bfloat16_rn(w - __bfloat162float(h));
    if (sel) { d_W3hi[r] = h; d_W3lo[r] = l; }
    else     { d_W2hi[r] = h; d_W2lo[r] = l; }
}

// ---------------- tensor-core transform (bf16x3) + fused attention dots ----------------
#define MMA_BF16(C, A0, A1, A2, A3, B0, B1)                                  \
    asm volatile(                                                            \
        "mma.sync.aligned.m16n8k16.row.col.f32.bf16.bf16.f32 "               \
        "{%0,%1,%2,%3}, {%4,%5,%6,%7}, {%8,%9}, {%0,%1,%2,%3};\n"            \
        : "+f"(C[0]), "+f"(C[1]), "+f"(C[2]), "+f"(C[3])                     \
        : "r"(A0), "r"(A1), "r"(A2), "r"(A3), "r"(B0), "r"(B1))

#define LDSM4(R0, R1, R2, R3, ADDR)                                          \
    asm volatile("ldmatrix.sync.aligned.m8n8.x4.shared.b16 {%0,%1,%2,%3}, [%4];" \
        : "=r"(R0), "=r"(R1), "=r"(R2), "=r"(R3) : "r"(ADDR))

__global__ void __launch_bounds__(256, 1)
k_transform_mma(const __nv_bfloat16* __restrict__ Bhi, const __nv_bfloat16* __restrict__ Blo,
                const float* __restrict__ as_, const float* __restrict__ ad_) {
    extern __shared__ __nv_bfloat16 sm[];
    __nv_bfloat16* sAhi = sm;                       // 128 x PIT
    __nv_bfloat16* sAlo = sAhi + 128 * PIT;
    __nv_bfloat16* sBhi = sAlo + 128 * PIT;         // 64 x PIT
    __nv_bfloat16* sBlo = sBhi + 64 * PIT;

    int tid = threadIdx.x, lane = tid & 31, warp = tid >> 5;
    int m0 = blockIdx.x * 128;
    int n0 = blockIdx.y * 64;

    {
        const uint4* gH = (const uint4*)(d_Ahi + (size_t)m0 * 256);
        const uint4* gL = (const uint4*)(d_Alo + (size_t)m0 * 256);
        for (int i = tid; i < 128 * 32; i += 256) {
            int r = i >> 5, c = i & 31;
            *(uint4*)(sAhi + r * PIT + c * 8) = gH[r * 32 + c];
            *(uint4*)(sAlo + r * PIT + c * 8) = gL[r * 32 + c];
        }
        const uint4* bH = (const uint4*)(Bhi + (size_t)n0 * 256);
        const uint4* bL = (const uint4*)(Blo + (size_t)n0 * 256);
        for (int i = tid; i < 64 * 32; i += 256) {
            int r = i >> 5, c = i & 31;
            *(uint4*)(sBhi + r * PIT + c * 8) = bH[r * 32 + c];
            *(uint4*)(sBlo + r * PIT + c * 8) = bL[r * 32 + c];
        }
    }
    __syncthreads();

    float c[8][4];
#pragma unroll
    for (int t = 0; t < 8; t++)
#pragma unroll
        for (int j = 0; j < 4; j++) c[t][j] = 0.f;

    int rA = warp * 16 + (lane & 15);
    int kOff = (lane >> 4) << 3;
    unsigned aHiB = (unsigned)__cvta_generic_to_shared(sAhi + rA * PIT + kOff);
    unsigned aLoB = (unsigned)__cvta_generic_to_shared(sAlo + rA * PIT + kOff);
    int rB = lane & 15;
    unsigned bHiB = (unsigned)__cvta_generic_to_shared(sBhi + rB * PIT + kOff);
    unsigned bLoB = (unsigned)__cvta_generic_to_shared(sBlo + rB * PIT + kOff);

#pragma unroll 4
    for (int kc = 0; kc < 16; kc++) {
        unsigned ka = kc * 32;
        unsigned ah0, ah1, ah2, ah3, al0, al1, al2, al3;
        LDSM4(ah0, ah1, ah2, ah3, aHiB + ka);
        LDSM4(al0, al1, al2, al3, aLoB + ka);
        unsigned ahv[4] = {ah0, ah1, ah2, ah3};
        unsigned alv[4] = {al0, al1, al2, al3};
#pragma unroll
        for (int p = 0; p < 4; p++) {
            unsigned boff = (unsigned)(p * 16 * PIT * 2) + ka;
            unsigned bh0, bh1, bh2, bh3, bl0, bl1, bl2, bl3;
            LDSM4(bh0, bh1, bh2, bh3, bHiB + boff);
            LDSM4(bl0, bl1, bl2, bl3, bLoB + boff);
            MMA_BF16(c[2 * p],     ahv[0], ahv[1], ahv[2], ahv[3], bh0, bh2);
            MMA_BF16(c[2 * p],     alv[0], alv[1], alv[2], alv[3], bh0, bh2);
            MMA_BF16(c[2 * p],     ahv[0], ahv[1], ahv[2], ahv[3], bl0, bl2);
            MMA_BF16(c[2 * p + 1], ahv[0], ahv[1], ahv[2], ahv[3], bh1, bh3);
            MMA_BF16(c[2 * p + 1], alv[0], alv[1], alv[2], alv[3], bh1, bh3);
            MMA_BF16(c[2 * p + 1], ahv[0], ahv[1], ahv[2], ahv[3], bl1, bl3);
        }
    }

    // epilogue: fp16 h1 + fused attention dots (block slice = 4 whole heads)
    int row0 = m0 + warp * 16 + (lane >> 2);
    int row1 = row0 + 8;
    int cbase = (lane & 3) * 2;
    float vs0[4] = {0, 0, 0, 0}, vd0[4] = {0, 0, 0, 0};
    float vs1[4] = {0, 0, 0, 0}, vd1[4] = {0, 0, 0, 0};
#pragma unroll
    for (int t = 0; t < 8; t++) {
        int col = n0 + t * 8 + cbase;
        *(__half2*)&d_h1h[(size_t)row0 * 256 + col] = __floats2half2_rn(c[t][0], c[t][1]);
        *(__half2*)&d_h1h[(size_t)row1 * 256 + col] = __floats2half2_rn(c[t][2], c[t][3]);
        float2 a2 = *(const float2*)&as_[col];
        float2 d2 = *(const float2*)&ad_[col];
        int hh = t >> 1;
        vs0[hh] += c[t][0] * a2.x + c[t][1] * a2.y;
        vd0[hh] += c[t][0] * d2.x + c[t][1] * d2.y;
        vs1[hh] += c[t][2] * a2.x + c[t][3] * a2.y;
        vd1[hh] += c[t][2] * d2.x + c[t][3] * d2.y;
    }
#pragma unroll
    for (int hh = 0; hh < 4; hh++) {
        vs0[hh] += __shfl_down_sync(0xffffffffu, vs0[hh], 2, 4);
        vs0[hh] += __shfl_down_sync(0xffffffffu, vs0[hh], 1, 4);
        vd0[hh] += __shfl_down_sync(0xffffffffu, vd0[hh], 2, 4);
        vd0[hh] += __shfl_down_sync(0xffffffffu, vd0[hh], 1, 4);
        vs1[hh] += __shfl_down_sync(0xffffffffu, vs1[hh], 2, 4);
        vs1[hh] += __shfl_down_sync(0xffffffffu, vs1[hh], 1, 4);
        vd1[hh] += __shfl_down_sync(0xffffffffu, vd1[hh], 2, 4);
        vd1[hh] += __shfl_down_sync(0xffffffffu, vd1[hh], 1, 4);
    }
    if ((lane & 3) == 0) {
        int H0 = blockIdx.y * 4;
        if (row0 < NN) {
#pragma unroll
            for (int hh = 0; hh < 4; hh++) {
                d_sa[row0 * 16 + H0 + hh] = vs0[hh];
                d_da[row0 * 16 + H0 + hh] = vd0[hh];
            }
        }
        if (row1 < NN) {
#pragma unroll
            for (int hh = 0; hh < 4; hh++) {
                d_sa[row1 * 16 + H0 + hh] = vs1[hh];
                d_da[row1 * 16 + H0 + hh] = vd1[hh];
            }
        }
    }
}
#define SMEM_MMA ((2 * 128 * PIT + 2 * 64 * PIT) * 2)

// ---------------- GAT aggregation: branchless online softmax, 2-edge pipeline ----------------
template <bool SPLIT>
__global__ void k_gat_agg(const float* __restrict__ b, float* __restrict__ outf) {
    int n = (blockIdx.x * blockDim.x + threadIdx.x) >> 5;
    if (n >= NN) return;
    int lane = threadIdx.x & 31;
    int hd = lane >> 1;
    float da_l = d_da[n * 16 + hd];
    int beg = d_rowoff[n], end = d_rowoff[n + 1];

    float m = -1e30f, z = 0.f;
    float acc[8];
#pragma unroll
    for (int i = 0; i < 8; i++) acc[i] = 0.f;

    int e = beg;
    for (; e + 1 < end; e += 2) {
        int s0 = d_csr[e], s1 = d_csr[e + 1];
        float l0 = d_sa[s0 * 16 + hd] + da_l;
        float l1 = d_sa[s1 * 16 + hd] + da_l;
        uint4 hv0 = *(const uint4*)(d_h1h + (size_t)s0 * 256 + lane * 8);
        uint4 hv1 = *(const uint4*)(d_h1h + (size_t)s1 * 256 + lane * 8);
        l0 = l0 > 0.f ? l0 : 0.2f * l0;
        l1 = l1 > 0.f ? l1 : 0.2f * l1;
        float nm = fmaxf(m, fmaxf(l0, l1));
        float sc = __expf(m - nm);
        float e0 = __expf(l0 - nm);
        float e1 = __expf(l1 - nm);
        m = nm;
        z = z * sc + e0 + e1;
        float2 f0 = __half22float2(*(__half2*)&hv0.x);
        float2 f1 = __half22float2(*(__half2*)&hv0.y);
        float2 f2 = __half22float2(*(__half2*)&hv0.z);
        float2 f3 = __half22float2(*(__half2*)&hv0.w);
        float2 g0 = __half22float2(*(__half2*)&hv1.x);
        float2 g1 = __half22float2(*(__half2*)&hv1.y);
        float2 g2 = __half22float2(*(__half2*)&hv1.z);
        float2 g3 = __half22float2(*(__half2*)&hv1.w);
        acc[0] = acc[0] * sc + e0 * f0.x + e1 * g0.x;
        acc[1] = acc[1] * sc + e0 * f0.y + e1 * g0.y;
        acc[2] = acc[2] * sc + e0 * f1.x + e1 * g1.x;
        acc[3] = acc[3] * sc + e0 * f1.y + e1 * g1.y;
        acc[4] = acc[4] * sc + e0 * f2.x + e1 * g2.x;
        acc[5] = acc[5] * sc + e0 * f2.y + e1 * g2.y;
        acc[6] = acc[6] * sc + e0 * f3.x + e1 * g3.x;
        acc[7] = acc[7] * sc + e0 * f3.y + e1 * g3.y;
    }
    if (e < end) {
        int s0 = d_csr[e];
        float l0 = d_sa[s0 * 16 + hd] + da_l;
        uint4 hv0 = *(const uint4*)(d_h1h + (size_t)s0 * 256 + lane * 8);
        l0 = l0 > 0.f ? l0 : 0.2f * l0;
        float nm = fmaxf(m, l0);
        float sc = __expf(m - nm);
        float e0 = __expf(l0 - nm);
        m = nm;
        z = z * sc + e0;
        float2 f0 = __half22float2(*(__half2*)&hv0.x);
        float2 f1 = __half22float2(*(__half2*)&hv0.y);
        float2 f2 = __half22float2(*(__half2*)&hv0.z);
        float2 f3 = __half22float2(*(__half2*)&hv0.w);
        acc[0] = acc[0] * sc + e0 * f0.x;
        acc[1] = acc[1] * sc + e0 * f0.y;
        acc[2] = acc[2] * sc + e0 * f1.x;
        acc[3] = acc[3] * sc + e0 * f1.y;
        acc[4] = acc[4] * sc + e0 * f2.x;
        acc[5] = acc[5] * sc + e0 * f2.y;
        acc[6] = acc[6] * sc + e0 * f3.x;
        acc[7] = acc[7] * sc + e0 * f3.y;
    }

    float invz = 1.f / (z + 1e-16f);
    float vo[8];
#pragma unroll
    for (int i = 0; i < 8; i++) {
        float v = acc[i] * invz + b[lane * 8 + i];
        vo[i] = v > 0.f ? v : (__expf(v) - 1.f);
    }
    if (SPLIT) {
        unsigned hi[4], lo[4];
#pragma unroll
        for (int i = 0; i < 4; i++) {
            __nv_bfloat16 h0 = __float2bfloat16_rn(vo[2 * i]);
            __nv_bfloat16 h1 = __float2bfloat16_rn(vo[2 * i + 1]);
            hi[i] = pack2(h0, h1);
            lo[i] = pack2(__float2bfloat16_rn(vo[2 * i] - __bfloat162float(h0)),
                          __float2bfloat16_rn(vo[2 * i + 1] - __bfloat162float(h1)));
        }
        *(uint4*)&d_Ahi[(size_t)n * 256 + lane * 8] = make_uint4(hi[0], hi[1], hi[2], hi[3]);
        *(uint4*)&d_Alo[(size_t)n * 256 + lane * 8] = make_uint4(lo[0], lo[1], lo[2], lo[3]);
    } else {
        *(float4*)&outf[(size_t)n * 256 + lane * 8] = make_float4(vo[0], vo[1], vo[2], vo[3]);
        *(float4*)&outf[(size_t)n * 256 + lane * 8 + 4] = make_float4(vo[4], vo[5], vo[6], vo[7]);
    }
}

// ---------------- final ----------------
__global__ void k_final(const float* __restrict__ h, const int* __restrict__ ui,
                        const int* __restrict__ ii, const float* __restrict__ Wd,
                        float* __restrict__ out) {
    int p = (blockIdx.x * blockDim.x + threadIdx.x) >> 5;
    if (p >= 1024) return;
    int lane = threadIdx.x & 31;
    int u = ui[p], it = ii[p];
    float a0 = 0.f, a1 = 0.f;
    for (int k = lane; k < 256; k += 32) {
        float v = h[u * 256 + k];
        a0 += v * Wd[k * 2 + 0];
        a1 += v * Wd[k * 2 + 1];
        float w = h[it * 256 + k];
        a0 += w * Wd[(256 + k) * 2 + 0];
        a1 += w * Wd[(256 + k) * 2 + 1];
    }
#pragma unroll
    for (int off = 16; off >= 1; off >>= 1) {
        a0 += __shfl_down_sync(0xffffffffu, a0, off);
        a1 += __shfl_down_sync(0xffffffffu, a1, off);
    }
    if (lane == 0) {
        float mx = fmaxf(a0, a1);
        float lse = mx + __logf(__expf(a0 - mx) + __expf(a1 - mx));
        out[p * 2 + 0] = a0 - lse;
        out[p * 2 + 1] = a1 - lse;
    }
}

// ---------------- launcher ----------------
extern "C" void kernel_launch(void* const* d_in, const int* in_sizes, int n_in,
                              void* d_out, int out_size) {
    const float* x    = (const float*)d_in[0];
    const int*   ei   = (const int*)d_in[1];
    const float* Hd   = (const float*)d_in[2];
    const int*   ui   = (const int*)d_in[3];
    const int*   ii   = (const int*)d_in[4];
    const float* Wg   = (const float*)d_in[5];
    const float* bg   = (const float*)d_in[6];
    const float* W1   = (const float*)d_in[7];
    const float* a1s  = (const float*)d_in[8];
    const float* a1d  = (const float*)d_in[9];
    const float* b1   = (const float*)d_in[10];
    const float* W2   = (const float*)d_in[11];
    const float* a2s  = (const float*)d_in[12];
    const float* a2d  = (const float*)d_in[13];
    const float* b2   = (const float*)d_in[14];
    const float* W3   = (const float*)d_in[15];
    const float* a3s  = (const float*)d_in[16];
    const float* a3d  = (const float*)d_in[17];
    const float* b3   = (const float*)d_in[18];
    const float* wd   = (const float*)d_in[19];
    const float* wr   = (const float*)d_in[20];
    const float* wdnn = (const float*)d_in[21];
    float* out = (float*)d_out;

    void *p_h0, *p_bufA, *p_w2hi, *p_w2lo, *p_w3hi, *p_w3lo;
    cudaGetSymbolAddress(&p_h0, d_h0);
    cudaGetSymbolAddress(&p_bufA, d_bufA);
    cudaGetSymbolAddress(&p_w2hi, d_W2hi);
    cudaGetSymbolAddress(&p_w2lo, d_W2lo);
    cudaGetSymbolAddress(&p_w3hi, d_W3hi);
    cudaGetSymbolAddress(&p_w3lo, d_W3lo);
    float* h0   = (float*)p_h0;
    float* bufA = (float*)p_bufA;

    cudaFuncSetAttribute(k_transform_mma,
                         cudaFuncAttributeMaxDynamicSharedMemorySize, SMEM_MMA);

    k_init<<<(NN + 255) / 256, 256>>>();
    k_prepW<<<(2 * 256 * 256 + 255) / 256, 256>>>(W2, W3);
    k_gemmA<<<(512 * 16 * 32 + 255) / 256, 256>>>(Hd, wr);
    k_gemmB<<<(128 * 16 * 32 + 255) / 256, 256>>>(wd);
    k_count<<<(EE / 4 + 255) / 256, 256>>>(ei + EE);
    k_scan<<<1, 1024>>>();
    k_scatter<<<(ET + 255) / 256, 256>>>(ei);

    k_xw_dual<<<NN / 16, 256>>>(x, Wg);
    k_gcn_agg<<<(NN * 16 + 255) / 256, 256>>>(bg);

    // GAT layer 1
    k_transform16<<<NN / 16, 128>>>(h0, W1, a1s, a1d);
    k_gat_agg<true><<<(NN * 32 + 255) / 256, 256>>>(b1, nullptr);

    // GAT layer 2 (tensor cores, fused att dots)
    k_transform_mma<<<dim3(NP / 128, 4), 256, SMEM_MMA>>>(
        (const __nv_bfloat16*)p_w2hi, (const __nv_bfloat16*)p_w2lo, a2s, a2d);
    k_gat_agg<true><<<(NN * 32 + 255) / 256, 256>>>(b2, nullptr);

    // GAT layer 3
    k_transform_mma<<<dim3(NP / 128, 4), 256, SMEM_MMA>>>(
        (const __nv_bfloat16*)p_w3hi, (const __nv_bfloat16*)p_w3lo, a3s, a3d);
    k_gat_agg<false><<<(NN * 32 + 255) / 256, 256>>>(b3, bufA);

    k_final<<<(1024 * 32 + 255) / 256, 256>>>(bufA, ui, ii, wdnn, out);
}

// round 8
// speedup vs baseline: 2.3395x; 1.0877x over previous
#include <cuda_runtime.h>
#include <cuda_bf16.h>
#include <cuda_fp16.h>
#include <math.h>

#define NN 50000
#define NP 50048          // padded to 128
#define EE 800000
#define ET (EE + NN)      // edges + self loops
#define PIT 264           // smem row pitch (bf16): 33*16B -> LDSM conflict-free

// ---------------- scratch (device globals; no allocation allowed) ----------------
__device__ float d_T2[512 * 16];             // Hd @ Wr
__device__ float d_M[128 * 16];              // Wd @ T2
__device__ int   d_deg[NN];
__device__ int   d_rowoff[NN + 1];
__device__ int   d_cursor[NN];
__device__ float d_dis[NN];
__device__ int   d_csr[ET];
__device__ float d_xw[NN * 16];
__device__ float d_dual[NN * 16];
__device__ float d_h0[NN * 16];
__device__ __half d_h1h[NP * 256];           // fp16 transformed features (agg gather)
__device__ float d_bufA[NN * 256];
__device__ float d_sa[NN * 16];
__device__ float d_da[NN * 16];
__device__ __nv_bfloat16 d_Ahi[NP * 256];    // split input activations for MMA
__device__ __nv_bfloat16 d_Alo[NP * 256];
__device__ __nv_bfloat16 d_W2hi[256 * 256];  // W2^T split [n][k]
__device__ __nv_bfloat16 d_W2lo[256 * 256];
__device__ __nv_bfloat16 d_W3hi[256 * 256];
__device__ __nv_bfloat16 d_W3lo[256 * 256];

static __device__ __forceinline__ unsigned pack2(__nv_bfloat16 a, __nv_bfloat16 b) {
    unsigned short ua = *reinterpret_cast<unsigned short*>(&a);
    unsigned short ub = *reinterpret_cast<unsigned short*>(&b);
    return (unsigned)ua | ((unsigned)ub << 16);
}

// ---------------- init ----------------
__global__ void k_init() {
    int i = blockIdx.x * blockDim.x + threadIdx.x;
    if (i < NN) { d_deg[i] = 1; d_cursor[i] = 0; }
}

// ---------------- dual weight: warp-per-output, no atomics ----------------
__global__ void k_gemmA(const float* __restrict__ hd, const float* __restrict__ wr) {
    int w = (blockIdx.x * blockDim.x + threadIdx.x) >> 5;
    if (w >= 512 * 16) return;
    int lane = threadIdx.x & 31;
    int i = w >> 4, j = w & 15;
    float a = 0.f;
#pragma unroll
    for (int kk = 0; kk < 16; kk++) {
        int k = lane + kk * 32;
        a += hd[i * 512 + k] * wr[k * 16 + j];
    }
#pragma unroll
    for (int off = 16; off >= 1; off >>= 1)
        a += __shfl_down_sync(0xffffffffu, a, off);
    if (lane == 0) d_T2[w] = a;
}

__global__ void k_gemmB(const float* __restrict__ wd) {
    int w = (blockIdx.x * blockDim.x + threadIdx.x) >> 5;
    if (w >= 128 * 16) return;
    int lane = threadIdx.x & 31;
    int i = w >> 4, j = w & 15;
    float a = 0.f;
#pragma unroll
    for (int kk = 0; kk < 16; kk++) {
        int k = lane + kk * 32;
        a += wd[i * 512 + k] * d_T2[k * 16 + j];
    }
#pragma unroll
    for (int off = 16; off >= 1; off >>= 1)
        a += __shfl_down_sync(0xffffffffu, a, off);
    if (lane == 0) d_M[w] = a;
}

// ---------------- degree count (4 edges/thread) ----------------
__global__ void k_count(const int* __restrict__ dst) {
    int t = blockIdx.x * blockDim.x + threadIdx.x;
    int e0 = t * 4;
    if (e0 + 3 < EE) {
        int4 d4 = *(const int4*)(dst + e0);
        atomicAdd(&d_deg[d4.x], 1);
        atomicAdd(&d_deg[d4.y], 1);
        atomicAdd(&d_deg[d4.z], 1);
        atomicAdd(&d_deg[d4.w], 1);
    } else {
        for (int e = e0; e < EE; e++) atomicAdd(&d_deg[dst[e]], 1);
    }
}

// ---------------- warp-shuffle scan (+ fused rsqrt degree) ----------------
__global__ void k_scan() {
    __shared__ int warp_sums[32];
    int t = threadIdx.x;
    const int S = 49;
    int b0 = t * S;
    int sum = 0;
    for (int i = 0; i < S; i++) {
        int idx = b0 + i;
        if (idx < NN) sum += d_deg[idx];
    }
    int lane = t & 31, w = t >> 5;
    int v = sum;
#pragma unroll
    for (int off = 1; off < 32; off <<= 1) {
        int u = __shfl_up_sync(0xffffffffu, v, off);
        if (lane >= off) v += u;
    }
    if (lane == 31) warp_sums[w] = v;
    __syncthreads();
    if (w == 0) {
        int ws = warp_sums[lane];
#pragma unroll
        for (int off = 1; off < 32; off <<= 1) {
            int u = __shfl_up_sync(0xffffffffu, ws, off);
            if (lane >= off) ws += u;
        }
        warp_sums[lane] = ws;
    }
    __syncthreads();
    int ex = v - sum + (w > 0 ? warp_sums[w - 1] : 0);
    int run = ex;
    for (int i = 0; i < S; i++) {
        int idx = b0 + i;
        if (idx < NN) {
            int dg = d_deg[idx];
            run += dg;
            d_rowoff[idx + 1] = run;
            d_dis[idx] = rsqrtf((float)dg);
        }
    }
    if (t == 0) d_rowoff[0] = 0;
}

__global__ void k_scatter(const int* __restrict__ ei) {
    int e = blockIdx.x * blockDim.x + threadIdx.x;
    if (e >= ET) return;
    int s, dd;
    if (e < EE) { s = ei[e]; dd = ei[EE + e]; }
    else        { s = dd = e - EE; }
    int p = atomicAdd(&d_cursor[dd], 1);
    d_csr[d_rowoff[dd] + p] = s;
}

// ---------------- GCN feature transform + dual (smem staged) ----------------
__global__ void __launch_bounds__(256)
k_xw_dual(const float* __restrict__ x, const float* __restrict__ Wg) {
    __shared__ float sx[16][132];
    int tid = threadIdx.x;
    int nb = blockIdx.x * 16;
    const float4* xs = (const float4*)(x + (size_t)nb * 128);
    for (int i = tid; i < 512; i += 256) {
        float4 v = xs[i];
        int r = i >> 5, c = (i & 31) * 4;
        sx[r][c] = v.x; sx[r][c + 1] = v.y; sx[r][c + 2] = v.z; sx[r][c + 3] = v.w;
    }
    __syncthreads();
    int nl = tid >> 4, j = tid & 15;
    float a = 0.f, b = 0.f;
#pragma unroll 4
    for (int k = 0; k < 128; k++) {
        float xv = sx[nl][k];
        a += xv * Wg[k * 16 + j];
        b += xv * d_M[k * 16 + j];
    }
    int n = nb + nl;
    d_xw[n * 16 + j] = a;
    d_dual[n * 16 + j] = b;
}

// ---------------- GCN aggregation + dual + elu -> h0 ----------------
__global__ void k_gcn_agg(const float* __restrict__ bg) {
    int g = (blockIdx.x * blockDim.x + threadIdx.x) >> 4;
    int j = threadIdx.x & 15;
    if (g >= NN) return;
    int beg = d_rowoff[g], end = d_rowoff[g + 1];
    float acc = 0.f;
    for (int e = beg; e < end; e++) {
        int s = d_csr[e];
        acc += d_dis[s] * d_xw[s * 16 + j];
    }
    float v = acc * d_dis[g] + bg[j] + d_dual[g * 16 + j];
    d_h0[g * 16 + j] = v > 0.f ? v : (__expf(v) - 1.f);
}

// ---------------- GAT layer-1 transform (FIN=16, FFMA; writes fp16 h1) ----------------
__global__ void __launch_bounds__(128, 8)
k_transform16(const float* __restrict__ hin, const float* __restrict__ W,
              const float* __restrict__ asrc, const float* __restrict__ adst) {
    __shared__ float s[16][16];
    int tid = threadIdx.x;
    int nb = blockIdx.x * 16;
    const float4* hin4 = (const float4*)(hin + nb * 16);
    float4* s4 = (float4*)s;
    for (int t = tid; t < 16 * 16 / 4; t += 128) s4[t] = hin4[t];
    __syncthreads();

    int cg = tid & 63;
    int ng = tid >> 6;
    const float4* W4 = (const float4*)W;
    float4 acc[8];
#pragma unroll
    for (int r = 0; r < 8; r++) acc[r] = make_float4(0.f, 0.f, 0.f, 0.f);

#pragma unroll
    for (int k = 0; k < 16; k++) {
        float4 w = W4[k * 64 + cg];
#pragma unroll
        for (int r = 0; r < 8; r++) {
            float sv = s[ng * 8 + r][k];
            acc[r].x += sv * w.x; acc[r].y += sv * w.y;
            acc[r].z += sv * w.z; acc[r].w += sv * w.w;
        }
    }

    float4 as4 = ((const float4*)asrc)[cg];
    float4 ad4 = ((const float4*)adst)[cg];
#pragma unroll
    for (int r = 0; r < 8; r++) {
        int n = nb + ng * 8 + r;
        if (n >= NN) break;
        __half2 p0 = __floats2half2_rn(acc[r].x, acc[r].y);
        __half2 p1 = __floats2half2_rn(acc[r].z, acc[r].w);
        *(__half2*)&d_h1h[(size_t)n * 256 + cg * 4] = p0;
        *(__half2*)&d_h1h[(size_t)n * 256 + cg * 4 + 2] = p1;
        float vs = acc[r].x * as4.x + acc[r].y * as4.y + acc[r].z * as4.z + acc[r].w * as4.w;
        float vd = acc[r].x * ad4.x + acc[r].y * ad4.y + acc[r].z * ad4.z + acc[r].w * ad4.w;
        vs += __shfl_down_sync(0xffffffffu, vs, 2, 4);
        vs += __shfl_down_sync(0xffffffffu, vs, 1, 4);
        vd += __shfl_down_sync(0xffffffffu, vd, 2, 4);
        vd += __shfl_down_sync(0xffffffffu, vd, 1, 4);
        if ((cg & 3) == 0) {
            int h = cg >> 2;
            d_sa[n * 16 + h] = vs;
            d_da[n * 16 + h] = vd;
        }
    }
}

// ---------------- W prep: transpose + bf16 split for W2 and W3 ----------------
__global__ void k_prepW(const float* __restrict__ W2, const float* __restrict__ W3) {
    int idx = blockIdx.x * blockDim.x + threadIdx.x;
    if (idx >= 2 * 256 * 256) return;
    int sel = idx >> 16;
    int r = idx & 65535;
    int n = r >> 8, k = r & 255;
    float w = (sel ? W3 : W2)[k * 256 + n];
    __nv_bfloat16 h = __float2bfloat16_rn(w);
    __nv_bfloat16 l = __float2bfloat16_rn(w - __bfloat162float(h));
    if (sel) { d_W3hi[r] = h; d_W3lo[r] = l; }
    else     { d_W2hi[r] = h; d_W2lo[r] = l; }
}

// ---------------- tensor-core transform (bf16x3) + fused attention dots ----------------
#define MMA_BF16(C, A0, A1, A2, A3, B0, B1)                                  \
    asm volatile(                                                            \
        "mma.sync.aligned.m16n8k16.row.col.f32.bf16.bf16.f32 "               \
        "{%0,%1,%2,%3}, {%4,%5,%6,%7}, {%8,%9}, {%0,%1,%2,%3};\n"            \
        : "+f"(C[0]), "+f"(C[1]), "+f"(C[2]), "+f"(C[3])                     \
        : "r"(A0), "r"(A1), "r"(A2), "r"(A3), "r"(B0), "r"(B1))

#define LDSM4(R0, R1, R2, R3, ADDR)                                          \
    asm volatile("ldmatrix.sync.aligned.m8n8.x4.shared.b16 {%0,%1,%2,%3}, [%4];" \
        : "=r"(R0), "=r"(R1), "=r"(R2), "=r"(R3) : "r"(ADDR))

__global__ void __launch_bounds__(256, 1)
k_transform_mma(const __nv_bfloat16* __restrict__ Bhi, const __nv_bfloat16* __restrict__ Blo,
                const float* __restrict__ as_, const float* __restrict__ ad_) {
    extern __shared__ __nv_bfloat16 sm[];
    __nv_bfloat16* sAhi = sm;                       // 128 x PIT
    __nv_bfloat16* sAlo = sAhi + 128 * PIT;
    __nv_bfloat16* sBhi = sAlo + 128 * PIT;         // 64 x PIT
    __nv_bfloat16* sBlo = sBhi + 64 * PIT;

    int tid = threadIdx.x, lane = tid & 31, warp = tid >> 5;
    int m0 = blockIdx.x * 128;
    int n0 = blockIdx.y * 64;

    {
        const uint4* gH = (const uint4*)(d_Ahi + (size_t)m0 * 256);
        const uint4* gL = (const uint4*)(d_Alo + (size_t)m0 * 256);
        for (int i = tid; i < 128 * 32; i += 256) {
            int r = i >> 5, c = i & 31;
            *(uint4*)(sAhi + r * PIT + c * 8) = gH[r * 32 + c];
            *(uint4*)(sAlo + r * PIT + c * 8) = gL[r * 32 + c];
        }
        const uint4* bH = (const uint4*)(Bhi + (size_t)n0 * 256);
        const uint4* bL = (const uint4*)(Blo + (size_t)n0 * 256);
        for (int i = tid; i < 64 * 32; i += 256) {
            int r = i >> 5, c = i & 31;
            *(uint4*)(sBhi + r * PIT + c * 8) = bH[r * 32 + c];
            *(uint4*)(sBlo + r * PIT + c * 8) = bL[r * 32 + c];
        }
    }
    __syncthreads();

    float c[8][4];
#pragma unroll
    for (int t = 0; t < 8; t++)
#pragma unroll
        for (int j = 0; j < 4; j++) c[t][j] = 0.f;

    int rA = warp * 16 + (lane & 15);
    int kOff = (lane >> 4) << 3;
    unsigned aHiB = (unsigned)__cvta_generic_to_shared(sAhi + rA * PIT + kOff);
    unsigned aLoB = (unsigned)__cvta_generic_to_shared(sAlo + rA * PIT + kOff);
    int rB = lane & 15;
    unsigned bHiB = (unsigned)__cvta_generic_to_shared(sBhi + rB * PIT + kOff);
    unsigned bLoB = (unsigned)__cvta_generic_to_shared(sBlo + rB * PIT + kOff);

#pragma unroll 4
    for (int kc = 0; kc < 16; kc++) {
        unsigned ka = kc * 32;
        unsigned ah0, ah1, ah2, ah3, al0, al1, al2, al3;
        LDSM4(ah0, ah1, ah2, ah3, aHiB + ka);
        LDSM4(al0, al1, al2, al3, aLoB + ka);
        unsigned ahv[4] = {ah0, ah1, ah2, ah3};
        unsigned alv[4] = {al0, al1, al2, al3};
#pragma unroll
        for (int p = 0; p < 4; p++) {
            unsigned boff = (unsigned)(p * 16 * PIT * 2) + ka;
            unsigned bh0, bh1, bh2, bh3, bl0, bl1, bl2, bl3;
            LDSM4(bh0, bh1, bh2, bh3, bHiB + boff);
            LDSM4(bl0, bl1, bl2, bl3, bLoB + boff);
            MMA_BF16(c[2 * p],     ahv[0], ahv[1], ahv[2], ahv[3], bh0, bh2);
            MMA_BF16(c[2 * p],     alv[0], alv[1], alv[2], alv[3], bh0, bh2);
            MMA_BF16(c[2 * p],     ahv[0], ahv[1], ahv[2], ahv[3], bl0, bl2);
            MMA_BF16(c[2 * p + 1], ahv[0], ahv[1], ahv[2], ahv[3], bh1, bh3);
            MMA_BF16(c[2 * p + 1], alv[0], alv[1], alv[2], alv[3], bh1, bh3);
            MMA_BF16(c[2 * p + 1], ahv[0], ahv[1], ahv[2], ahv[3], bl1, bl3);
        }
    }

    // epilogue: fp16 h1 + fused attention dots (block slice = 4 whole heads)
    int row0 = m0 + warp * 16 + (lane >> 2);
    int row1 = row0 + 8;
    int cbase = (lane & 3) * 2;
    float vs0[4] = {0, 0, 0, 0}, vd0[4] = {0, 0, 0, 0};
    float vs1[4] = {0, 0, 0, 0}, vd1[4] = {0, 0, 0, 0};
#pragma unroll
    for (int t = 0; t < 8; t++) {
        int col = n0 + t * 8 + cbase;
        *(__half2*)&d_h1h[(size_t)row0 * 256 + col] = __floats2half2_rn(c[t][0], c[t][1]);
        *(__half2*)&d_h1h[(size_t)row1 * 256 + col] = __floats2half2_rn(c[t][2], c[t][3]);
        float2 a2 = *(const float2*)&as_[col];
        float2 d2 = *(const float2*)&ad_[col];
        int hh = t >> 1;
        vs0[hh] += c[t][0] * a2.x + c[t][1] * a2.y;
        vd0[hh] += c[t][0] * d2.x + c[t][1] * d2.y;
        vs1[hh] += c[t][2] * a2.x + c[t][3] * a2.y;
        vd1[hh] += c[t][2] * d2.x + c[t][3] * d2.y;
    }
#pragma unroll
    for (int hh = 0; hh < 4; hh++) {
        vs0[hh] += __shfl_down_sync(0xffffffffu, vs0[hh], 2, 4);
        vs0[hh] += __shfl_down_sync(0xffffffffu, vs0[hh], 1, 4);
        vd0[hh] += __shfl_down_sync(0xffffffffu, vd0[hh], 2, 4);
        vd0[hh] += __shfl_down_sync(0xffffffffu, vd0[hh], 1, 4);
        vs1[hh] += __shfl_down_sync(0xffffffffu, vs1[hh], 2, 4);
        vs1[hh] += __shfl_down_sync(0xffffffffu, vs1[hh], 1, 4);
        vd1[hh] += __shfl_down_sync(0xffffffffu, vd1[hh], 2, 4);
        vd1[hh] += __shfl_down_sync(0xffffffffu, vd1[hh], 1, 4);
    }
    if ((lane & 3) == 0) {
        int H0 = blockIdx.y * 4;
        if (row0 < NN) {
#pragma unroll
            for (int hh = 0; hh < 4; hh++) {
                d_sa[row0 * 16 + H0 + hh] = vs0[hh];
                d_da[row0 * 16 + H0 + hh] = vd0[hh];
            }
        }
        if (row1 < NN) {
#pragma unroll
            for (int hh = 0; hh < 4; hh++) {
                d_sa[row1 * 16 + H0 + hh] = vs1[hh];
                d_da[row1 * 16 + H0 + hh] = vd1[hh];
            }
        }
    }
}
#define SMEM_MMA ((2 * 128 * PIT + 2 * 64 * PIT) * 2)

// ---------------- GAT aggregation body: 4-edge branchless online softmax ----------------
template <bool SPLIT>
static __device__ __forceinline__ void gat_body(int n, int lane,
                                                const float* __restrict__ b,
                                                float* __restrict__ outf) {
    int hd = lane >> 1;
    float da_l = d_da[n * 16 + hd];
    int beg = d_rowoff[n], end = d_rowoff[n + 1];

    float m = -1e30f, z = 0.f;
    float acc[8];
#pragma unroll
    for (int i = 0; i < 8; i++) acc[i] = 0.f;

    int e = beg;
    for (; e + 3 < end; e += 4) {
        int s0 = d_csr[e], s1 = d_csr[e + 1], s2 = d_csr[e + 2], s3 = d_csr[e + 3];
        float l0 = d_sa[s0 * 16 + hd] + da_l;
        float l1 = d_sa[s1 * 16 + hd] + da_l;
        float l2 = d_sa[s2 * 16 + hd] + da_l;
        float l3 = d_sa[s3 * 16 + hd] + da_l;
        uint4 hv0 = *(const uint4*)(d_h1h + (size_t)s0 * 256 + lane * 8);
        uint4 hv1 = *(const uint4*)(d_h1h + (size_t)s1 * 256 + lane * 8);
        uint4 hv2 = *(const uint4*)(d_h1h + (size_t)s2 * 256 + lane * 8);
        uint4 hv3 = *(const uint4*)(d_h1h + (size_t)s3 * 256 + lane * 8);
        l0 = l0 > 0.f ? l0 : 0.2f * l0;
        l1 = l1 > 0.f ? l1 : 0.2f * l1;
        l2 = l2 > 0.f ? l2 : 0.2f * l2;
        l3 = l3 > 0.f ? l3 : 0.2f * l3;
        float nm = fmaxf(fmaxf(m, fmaxf(l0, l1)), fmaxf(l2, l3));
        float sc = __expf(m - nm);
        float e0 = __expf(l0 - nm), e1 = __expf(l1 - nm);
        float e2 = __expf(l2 - nm), e3 = __expf(l3 - nm);
        m = nm;
        z = z * sc + (e0 + e1) + (e2 + e3);
        float2 f0 = __half22float2(*(__half2*)&hv0.x), f1 = __half22float2(*(__half2*)&hv0.y);
        float2 f2 = __half22float2(*(__half2*)&hv0.z), f3 = __half22float2(*(__half2*)&hv0.w);
        float2 g0 = __half22float2(*(__half2*)&hv1.x), g1 = __half22float2(*(__half2*)&hv1.y);
        float2 g2 = __half22float2(*(__half2*)&hv1.z), g3 = __half22float2(*(__half2*)&hv1.w);
        float2 p0 = __half22float2(*(__half2*)&hv2.x), p1 = __half22float2(*(__half2*)&hv2.y);
        float2 p2 = __half22float2(*(__half2*)&hv2.z), p3 = __half22float2(*(__half2*)&hv2.w);
        float2 q0 = __half22float2(*(__half2*)&hv3.x), q1 = __half22float2(*(__half2*)&hv3.y);
        float2 q2 = __half22float2(*(__half2*)&hv3.z), q3 = __half22float2(*(__half2*)&hv3.w);
        acc[0] = acc[0] * sc + (e0 * f0.x + e1 * g0.x) + (e2 * p0.x + e3 * q0.x);
        acc[1] = acc[1] * sc + (e0 * f0.y + e1 * g0.y) + (e2 * p0.y + e3 * q0.y);
        acc[2] = acc[2] * sc + (e0 * f1.x + e1 * g1.x) + (e2 * p1.x + e3 * q1.x);
        acc[3] = acc[3] * sc + (e0 * f1.y + e1 * g1.y) + (e2 * p1.y + e3 * q1.y);
        acc[4] = acc[4] * sc + (e0 * f2.x + e1 * g2.x) + (e2 * p2.x + e3 * q2.x);
        acc[5] = acc[5] * sc + (e0 * f2.y + e1 * g2.y) + (e2 * p2.y + e3 * q2.y);
        acc[6] = acc[6] * sc + (e0 * f3.x + e1 * g3.x) + (e2 * p3.x + e3 * q3.x);
        acc[7] = acc[7] * sc + (e0 * f3.y + e1 * g3.y) + (e2 * p3.y + e3 * q3.y);
    }
    for (; e < end; e++) {
        int s0 = d_csr[e];
        float l0 = d_sa[s0 * 16 + hd] + da_l;
        uint4 hv0 = *(const uint4*)(d_h1h + (size_t)s0 * 256 + lane * 8);
        l0 = l0 > 0.f ? l0 : 0.2f * l0;
        float nm = fmaxf(m, l0);
        float sc = __expf(m - nm);
        float e0 = __expf(l0 - nm);
        m = nm;
        z = z * sc + e0;
        float2 f0 = __half22float2(*(__half2*)&hv0.x), f1 = __half22float2(*(__half2*)&hv0.y);
        float2 f2 = __half22float2(*(__half2*)&hv0.z), f3 = __half22float2(*(__half2*)&hv0.w);
        acc[0] = acc[0] * sc + e0 * f0.x;
        acc[1] = acc[1] * sc + e0 * f0.y;
        acc[2] = acc[2] * sc + e0 * f1.x;
        acc[3] = acc[3] * sc + e0 * f1.y;
        acc[4] = acc[4] * sc + e0 * f2.x;
        acc[5] = acc[5] * sc + e0 * f2.y;
        acc[6] = acc[6] * sc + e0 * f3.x;
        acc[7] = acc[7] * sc + e0 * f3.y;
    }

    float invz = 1.f / (z + 1e-16f);
    float vo[8];
#pragma unroll
    for (int i = 0; i < 8; i++) {
        float v = acc[i] * invz + b[lane * 8 + i];
        vo[i] = v > 0.f ? v : (__expf(v) - 1.f);
    }
    if (SPLIT) {
        unsigned hi[4], lo[4];
#pragma unroll
        for (int i = 0; i < 4; i++) {
            __nv_bfloat16 h0 = __float2bfloat16_rn(vo[2 * i]);
            __nv_bfloat16 h1 = __float2bfloat16_rn(vo[2 * i + 1]);
            hi[i] = pack2(h0, h1);
            lo[i] = pack2(__float2bfloat16_rn(vo[2 * i] - __bfloat162float(h0)),
                          __float2bfloat16_rn(vo[2 * i + 1] - __bfloat162float(h1)));
        }
        *(uint4*)&d_Ahi[(size_t)n * 256 + lane * 8] = make_uint4(hi[0], hi[1], hi[2], hi[3]);
        *(uint4*)&d_Alo[(size_t)n * 256 + lane * 8] = make_uint4(lo[0], lo[1], lo[2], lo[3]);
    } else {
        *(float4*)&outf[(size_t)n * 256 + lane * 8] = make_float4(vo[0], vo[1], vo[2], vo[3]);
        *(float4*)&outf[(size_t)n * 256 + lane * 8 + 4] = make_float4(vo[4], vo[5], vo[6], vo[7]);
    }
}

template <bool SPLIT>
__global__ void k_gat_agg(const float* __restrict__ b, float* __restrict__ outf) {
    int n = (blockIdx.x * blockDim.x + threadIdx.x) >> 5;
    if (n >= NN) return;
    gat_body<SPLIT>(n, threadIdx.x & 31, b, outf);
}

// layer-3: aggregate ONLY the nodes the output reads (user/item lists)
__global__ void k_gat_agg_list(const float* __restrict__ b, float* __restrict__ outf,
                               const int* __restrict__ ui, const int* __restrict__ ii,
                               int P) {
    int i = (blockIdx.x * blockDim.x + threadIdx.x) >> 5;
    if (i >= 2 * P) return;
    int n = (i < P) ? ui[i] : ii[i - P];
    gat_body<false>(n, threadIdx.x & 31, b, outf);
}

// ---------------- final ----------------
__global__ void k_final(const float* __restrict__ h, const int* __restrict__ ui,
                        const int* __restrict__ ii, const float* __restrict__ Wd,
                        float* __restrict__ out) {
    int p = (blockIdx.x * blockDim.x + threadIdx.x) >> 5;
    if (p >= 1024) return;
    int lane = threadIdx.x & 31;
    int u = ui[p], it = ii[p];
    float a0 = 0.f, a1 = 0.f;
    for (int k = lane; k < 256; k += 32) {
        float v = h[u * 256 + k];
        a0 += v * Wd[k * 2 + 0];
        a1 += v * Wd[k * 2 + 1];
        float w = h[it * 256 + k];
        a0 += w * Wd[(256 + k) * 2 + 0];
        a1 += w * Wd[(256 + k) * 2 + 1];
    }
#pragma unroll
    for (int off = 16; off >= 1; off >>= 1) {
        a0 += __shfl_down_sync(0xffffffffu, a0, off);
        a1 += __shfl_down_sync(0xffffffffu, a1, off);
    }
    if (lane == 0) {
        float mx = fmaxf(a0, a1);
        float lse = mx + __logf(__expf(a0 - mx) + __expf(a1 - mx));
        out[p * 2 + 0] = a0 - lse;
        out[p * 2 + 1] = a1 - lse;
    }
}

// ---------------- launcher ----------------
extern "C" void kernel_launch(void* const* d_in, const int* in_sizes, int n_in,
                              void* d_out, int out_size) {
    const float* x    = (const float*)d_in[0];
    const int*   ei   = (const int*)d_in[1];
    const float* Hd   = (const float*)d_in[2];
    const int*   ui   = (const int*)d_in[3];
    const int*   ii   = (const int*)d_in[4];
    const float* Wg   = (const float*)d_in[5];
    const float* bg   = (const float*)d_in[6];
    const float* W1   = (const float*)d_in[7];
    const float* a1s  = (const float*)d_in[8];
    const float* a1d  = (const float*)d_in[9];
    const float* b1   = (const float*)d_in[10];
    const float* W2   = (const float*)d_in[11];
    const float* a2s  = (const float*)d_in[12];
    const float* a2d  = (const float*)d_in[13];
    const float* b2   = (const float*)d_in[14];
    const float* W3   = (const float*)d_in[15];
    const float* a3s  = (const float*)d_in[16];
    const float* a3d  = (const float*)d_in[17];
    const float* b3   = (const float*)d_in[18];
    const float* wd   = (const float*)d_in[19];
    const float* wr   = (const float*)d_in[20];
    const float* wdnn = (const float*)d_in[21];
    float* out = (float*)d_out;

    int P = in_sizes[3];   // number of user/item pairs

    void *p_h0, *p_bufA, *p_w2hi, *p_w2lo, *p_w3hi, *p_w3lo;
    cudaGetSymbolAddress(&p_h0, d_h0);
    cudaGetSymbolAddress(&p_bufA, d_bufA);
    cudaGetSymbolAddress(&p_w2hi, d_W2hi);
    cudaGetSymbolAddress(&p_w2lo, d_W2lo);
    cudaGetSymbolAddress(&p_w3hi, d_W3hi);
    cudaGetSymbolAddress(&p_w3lo, d_W3lo);
    float* h0   = (float*)p_h0;
    float* bufA = (float*)p_bufA;

    cudaFuncSetAttribute(k_transform_mma,
                         cudaFuncAttributeMaxDynamicSharedMemorySize, SMEM_MMA);

    k_init<<<(NN + 255) / 256, 256>>>();
    k_prepW<<<(2 * 256 * 256 + 255) / 256, 256>>>(W2, W3);
    k_gemmA<<<(512 * 16 * 32 + 255) / 256, 256>>>(Hd, wr);
    k_gemmB<<<(128 * 16 * 32 + 255) / 256, 256>>>(wd);
    k_count<<<(EE / 4 + 255) / 256, 256>>>(ei + EE);
    k_scan<<<1, 1024>>>();
    k_scatter<<<(ET + 255) / 256, 256>>>(ei);

    k_xw_dual<<<NN / 16, 256>>>(x, Wg);
    k_gcn_agg<<<(NN * 16 + 255) / 256, 256>>>(bg);

    // GAT layer 1
    k_transform16<<<NN / 16, 128>>>(h0, W1, a1s, a1d);
    k_gat_agg<true><<<(NN * 32 + 255) / 256, 256>>>(b1, nullptr);

    // GAT layer 2 (tensor cores, fused att dots)
    k_transform_mma<<<dim3(NP / 128, 4), 256, SMEM_MMA>>>(
        (const __nv_bfloat16*)p_w2hi, (const __nv_bfloat16*)p_w2lo, a2s, a2d);
    k_gat_agg<true><<<(NN * 32 + 255) / 256, 256>>>(b2, nullptr);

    // GAT layer 3: transform for all nodes, aggregate only listed nodes
    k_transform_mma<<<dim3(NP / 128, 4), 256, SMEM_MMA>>>(
        (const __nv_bfloat16*)p_w3hi, (const __nv_bfloat16*)p_w3lo, a3s, a3d);
    k_gat_agg_list<<<(2 * P * 32 + 255) / 256, 256>>>(b3, bufA, ui, ii, P);

    k_final<<<(1024 * 32 + 255) / 256, 256>>>(bufA, ui, ii, wdnn, out);
}

// round 9
// speedup vs baseline: 2.4960x; 1.0669x over previous
#include <cuda_runtime.h>
#include <cuda_bf16.h>
#include <cuda_fp16.h>
#include <math.h>

#define NN 50000
#define NP 50048          // padded to 128
#define EE 800000
#define ET (EE + NN)      // edges + self loops
#define PIT 264           // smem row pitch (fp16): 33*16B -> LDSM conflict-free

// ---------------- scratch (device globals; no allocation allowed) ----------------
__device__ float d_T2[512 * 16];             // Hd @ Wr
__device__ float d_M[128 * 16];              // Wd @ T2
__device__ int   d_deg[NN];                  // starts 0; scan resets to 0 after use
__device__ int   d_rowoff[NN + 1];
__device__ int   d_cursor[NN];               // gcn_agg resets to 0 after scatter
__device__ float d_dis[NN];
__device__ int   d_csr[ET];
__device__ float d_xw[NN * 16];
__device__ float d_dual[NN * 16];
__device__ float d_h0[NN * 16];
__device__ __half d_h1h[NP * 256];           // fp16 transformed features (agg gather)
__device__ __half d_Ah[NP * 256];            // fp16 input activations for MMA
__device__ float d_bufA[NN * 256];
__device__ float d_sa[NN * 16];
__device__ float d_da[NN * 16];
__device__ __half d_W2hi[256 * 256];         // W2^T split [n][k]  fp16 hi
__device__ __half d_W2lo[256 * 256];
__device__ __half d_W3hi[256 * 256];
__device__ __half d_W3lo[256 * 256];

// ================= merged SETUP: prepW | count | gemmA =================
#define SB_PREPW 512
#define SB_COUNT 782
#define SB_GEMMA 1024
#define SB_TOTAL (SB_PREPW + SB_COUNT + SB_GEMMA)

__global__ void k_setup(const float* __restrict__ W2, const float* __restrict__ W3,
                        const int* __restrict__ dst,
                        const float* __restrict__ hd, const float* __restrict__ wr) {
    int bid = blockIdx.x, tid = threadIdx.x;
    if (bid < SB_PREPW) {
        // prepW: transpose + fp16 split for W2 and W3
        int idx = bid * 256 + tid;          // < 2*65536
        int sel = idx >> 16;
        int r = idx & 65535;
        int n = r >> 8, k = r & 255;
        float w = (sel ? W3 : W2)[k * 256 + n];
        __half h = __float2half_rn(w);
        __half l = __float2half_rn(w - __half2float(h));
        if (sel) { d_W3hi[r] = h; d_W3lo[r] = l; }
        else     { d_W2hi[r] = h; d_W2lo[r] = l; }
    } else if (bid < SB_PREPW + SB_COUNT) {
        // degree count (4 edges/thread); d_deg starts at 0
        int t = (bid - SB_PREPW) * 256 + tid;
        int e0 = t * 4;
        if (e0 + 3 < EE) {
            int4 d4 = *(const int4*)(dst + e0);
            atomicAdd(&d_deg[d4.x], 1);
            atomicAdd(&d_deg[d4.y], 1);
            atomicAdd(&d_deg[d4.z], 1);
            atomicAdd(&d_deg[d4.w], 1);
        } else {
            for (int e = e0; e < EE; e++) atomicAdd(&d_deg[dst[e]], 1);
        }
    } else {
        // gemmA: T2[512,16] = Hd @ Wr, warp per output
        int w = ((bid - SB_PREPW - SB_COUNT) * 256 + tid) >> 5;
        int lane = tid & 31;
        int i = w >> 4, j = w & 15;
        float a = 0.f;
#pragma unroll
        for (int kk = 0; kk < 16; kk++) {
            int k = lane + kk * 32;
            a += hd[i * 512 + k] * wr[k * 16 + j];
        }
#pragma unroll
        for (int off = 16; off >= 1; off >>= 1)
            a += __shfl_down_sync(0xffffffffu, a, off);
        if (lane == 0) d_T2[w] = a;
    }
}

// ================= merged PHASE2: scan (block 0) | gemmB =================
__global__ void __launch_bounds__(1024)
k_phase2(const float* __restrict__ wd) {
    if (blockIdx.x == 0) {
        // warp-shuffle scan, self-loop +1, fused rsqrt, deg reset
        __shared__ int warp_sums[32];
        int t = threadIdx.x;
        const int S = 49;
        int b0 = t * S;
        int sum = 0;
        for (int i = 0; i < S; i++) {
            int idx = b0 + i;
            if (idx < NN) sum += d_deg[idx] + 1;   // +1 self loop
        }
        int lane = t & 31, w = t >> 5;
        int v = sum;
#pragma unroll
        for (int off = 1; off < 32; off <<= 1) {
            int u = __shfl_up_sync(0xffffffffu, v, off);
            if (lane >= off) v += u;
        }
        if (lane == 31) warp_sums[w] = v;
        __syncthreads();
        if (w == 0) {
            int ws = warp_sums[lane];
#pragma unroll
            for (int off = 1; off < 32; off <<= 1) {
                int u = __shfl_up_sync(0xffffffffu, ws, off);
                if (lane >= off) ws += u;
            }
            warp_sums[lane] = ws;
        }
        __syncthreads();
        int ex = v - sum + (w > 0 ? warp_sums[w - 1] : 0);
        int run = ex;
        for (int i = 0; i < S; i++) {
            int idx = b0 + i;
            if (idx < NN) {
                int dg = d_deg[idx] + 1;
                d_deg[idx] = 0;                     // reset for next replay
                run += dg;
                d_rowoff[idx + 1] = run;
                d_dis[idx] = rsqrtf((float)dg);
            }
        }
        if (t == 0) d_rowoff[0] = 0;
    } else {
        // gemmB: M[128,16] = Wd @ T2, warp per output (32 warps/block)
        int w = (blockIdx.x - 1) * 32 + (threadIdx.x >> 5);
        int lane = threadIdx.x & 31;
        int i = w >> 4, j = w & 15;
        float a = 0.f;
#pragma unroll
        for (int kk = 0; kk < 16; kk++) {
            int k = lane + kk * 32;
            a += wd[i * 512 + k] * d_T2[k * 16 + j];
        }
#pragma unroll
        for (int off = 16; off >= 1; off >>= 1)
            a += __shfl_down_sync(0xffffffffu, a, off);
        if (lane == 0) d_M[w] = a;
    }
}

// ================= merged PHASE3: scatter | xw_dual =================
#define PB_SCAT ((ET + 255) / 256)
#define PB_XW (NN / 16)
#define PB_TOTAL (PB_SCAT + PB_XW)

__global__ void __launch_bounds__(256)
k_phase3(const int* __restrict__ ei, const float* __restrict__ x,
         const float* __restrict__ Wg) {
    int bid = blockIdx.x, tid = threadIdx.x;
    if (bid < PB_SCAT) {
        int e = bid * 256 + tid;
        if (e >= ET) return;
        int s, dd;
        if (e < EE) { s = ei[e]; dd = ei[EE + e]; }
        else        { s = dd = e - EE; }
        int p = atomicAdd(&d_cursor[dd], 1);
        d_csr[d_rowoff[dd] + p] = s;
    } else {
        __shared__ float sx[16][132];
        int nb = (bid - PB_SCAT) * 16;
        const float4* xs = (const float4*)(x + (size_t)nb * 128);
        for (int i = tid; i < 512; i += 256) {
            float4 v = xs[i];
            int r = i >> 5, c = (i & 31) * 4;
            sx[r][c] = v.x; sx[r][c + 1] = v.y; sx[r][c + 2] = v.z; sx[r][c + 3] = v.w;
        }
        __syncthreads();
        int nl = tid >> 4, j = tid & 15;
        float a = 0.f, b = 0.f;
#pragma unroll 4
        for (int k = 0; k < 128; k++) {
            float xv = sx[nl][k];
            a += xv * Wg[k * 16 + j];
            b += xv * d_M[k * 16 + j];
        }
        int n = nb + nl;
        d_xw[n * 16 + j] = a;
        d_dual[n * 16 + j] = b;
    }
}

// ---------------- GCN aggregation + dual + elu -> h0 (+ cursor reset) ----------------
__global__ void k_gcn_agg(const float* __restrict__ bg) {
    int g = (blockIdx.x * blockDim.x + threadIdx.x) >> 4;
    int j = threadIdx.x & 15;
    if (g >= NN) return;
    int beg = d_rowoff[g], end = d_rowoff[g + 1];
    float acc = 0.f;
    for (int e = beg; e < end; e++) {
        int s = d_csr[e];
        acc += d_dis[s] * d_xw[s * 16 + j];
    }
    float v = acc * d_dis[g] + bg[j] + d_dual[g * 16 + j];
    d_h0[g * 16 + j] = v > 0.f ? v : (__expf(v) - 1.f);
    if (j == 0) d_cursor[g] = 0;   // reset for next replay
}

// ---------------- GAT layer-1 transform (FIN=16, FFMA; writes fp16 h1) ----------------
__global__ void __launch_bounds__(128, 8)
k_transform16(const float* __restrict__ hin, const float* __restrict__ W,
              const float* __restrict__ asrc, const float* __restrict__ adst) {
    __shared__ float s[16][16];
    int tid = threadIdx.x;
    int nb = blockIdx.x * 16;
    const float4* hin4 = (const float4*)(hin + nb * 16);
    float4* s4 = (float4*)s;
    for (int t = tid; t < 16 * 16 / 4; t += 128) s4[t] = hin4[t];
    __syncthreads();

    int cg = tid & 63;
    int ng = tid >> 6;
    const float4* W4 = (const float4*)W;
    float4 acc[8];
#pragma unroll
    for (int r = 0; r < 8; r++) acc[r] = make_float4(0.f, 0.f, 0.f, 0.f);

#pragma unroll
    for (int k = 0; k < 16; k++) {
        float4 w = W4[k * 64 + cg];
#pragma unroll
        for (int r = 0; r < 8; r++) {
            float sv = s[ng * 8 + r][k];
            acc[r].x += sv * w.x; acc[r].y += sv * w.y;
            acc[r].z += sv * w.z; acc[r].w += sv * w.w;
        }
    }

    float4 as4 = ((const float4*)asrc)[cg];
    float4 ad4 = ((const float4*)adst)[cg];
#pragma unroll
    for (int r = 0; r < 8; r++) {
        int n = nb + ng * 8 + r;
        if (n >= NN) break;
        __half2 p0 = __floats2half2_rn(acc[r].x, acc[r].y);
        __half2 p1 = __floats2half2_rn(acc[r].z, acc[r].w);
        *(__half2*)&d_h1h[(size_t)n * 256 + cg * 4] = p0;
        *(__half2*)&d_h1h[(size_t)n * 256 + cg * 4 + 2] = p1;
        float vs = acc[r].x * as4.x + acc[r].y * as4.y + acc[r].z * as4.z + acc[r].w * as4.w;
        float vd = acc[r].x * ad4.x + acc[r].y * ad4.y + acc[r].z * ad4.z + acc[r].w * ad4.w;
        vs += __shfl_down_sync(0xffffffffu, vs, 2, 4);
        vs += __shfl_down_sync(0xffffffffu, vs, 1, 4);
        vd += __shfl_down_sync(0xffffffffu, vd, 2, 4);
        vd += __shfl_down_sync(0xffffffffu, vd, 1, 4);
        if ((cg & 3) == 0) {
            int h = cg >> 2;
            d_sa[n * 16 + h] = vs;
            d_da[n * 16 + h] = vd;
        }
    }
}

// ---------------- tensor-core transform (fp16 A x fp16-split W) + fused att dots ----------------
#define MMA_F16(C, A0, A1, A2, A3, B0, B1)                                   \
    asm volatile(                                                            \
        "mma.sync.aligned.m16n8k16.row.col.f32.f16.f16.f32 "                 \
        "{%0,%1,%2,%3}, {%4,%5,%6,%7}, {%8,%9}, {%0,%1,%2,%3};\n"            \
        : "+f"(C[0]), "+f"(C[1]), "+f"(C[2]), "+f"(C[3])                     \
        : "r"(A0), "r"(A1), "r"(A2), "r"(A3), "r"(B0), "r"(B1))

#define LDSM4(R0, R1, R2, R3, ADDR)                                          \
    asm volatile("ldmatrix.sync.aligned.m8n8.x4.shared.b16 {%0,%1,%2,%3}, [%4];" \
        : "=r"(R0), "=r"(R1), "=r"(R2), "=r"(R3) : "r"(ADDR))

__global__ void __launch_bounds__(256, 1)
k_transform_mma(const __half* __restrict__ Bhi, const __half* __restrict__ Blo,
                const float* __restrict__ as_, const float* __restrict__ ad_) {
    extern __shared__ __half sm[];
    __half* sA = sm;                          // 128 x PIT
    __half* sBhi = sA + 128 * PIT;            // 64 x PIT
    __half* sBlo = sBhi + 64 * PIT;

    int tid = threadIdx.x, lane = tid & 31, warp = tid >> 5;
    int m0 = blockIdx.x * 128;
    int n0 = blockIdx.y * 64;

    {
        const uint4* gA = (const uint4*)(d_Ah + (size_t)m0 * 256);
        for (int i = tid; i < 128 * 32; i += 256) {
            int r = i >> 5, c = i & 31;
            *(uint4*)(sA + r * PIT + c * 8) = gA[r * 32 + c];
        }
        const uint4* bH = (const uint4*)(Bhi + (size_t)n0 * 256);
        const uint4* bL = (const uint4*)(Blo + (size_t)n0 * 256);
        for (int i = tid; i < 64 * 32; i += 256) {
            int r = i >> 5, c = i & 31;
            *(uint4*)(sBhi + r * PIT + c * 8) = bH[r * 32 + c];
            *(uint4*)(sBlo + r * PIT + c * 8) = bL[r * 32 + c];
        }
    }
    __syncthreads();

    float c[8][4];
#pragma unroll
    for (int t = 0; t < 8; t++)
#pragma unroll
        for (int j = 0; j < 4; j++) c[t][j] = 0.f;

    int rA = warp * 16 + (lane & 15);
    int kOff = (lane >> 4) << 3;
    unsigned aB = (unsigned)__cvta_generic_to_shared(sA + rA * PIT + kOff);
    int rB = lane & 15;
    unsigned bHiB = (unsigned)__cvta_generic_to_shared(sBhi + rB * PIT + kOff);
    unsigned bLoB = (unsigned)__cvta_generic_to_shared(sBlo + rB * PIT + kOff);

#pragma unroll 4
    for (int kc = 0; kc < 16; kc++) {
        unsigned ka = kc * 32;
        unsigned a0, a1, a2, a3;
        LDSM4(a0, a1, a2, a3, aB + ka);
#pragma unroll
        for (int p = 0; p < 4; p++) {
            unsigned boff = (unsigned)(p * 16 * PIT * 2) + ka;
            unsigned bh0, bh1, bh2, bh3, bl0, bl1, bl2, bl3;
            LDSM4(bh0, bh1, bh2, bh3, bHiB + boff);
            LDSM4(bl0, bl1, bl2, bl3, bLoB + boff);
            MMA_F16(c[2 * p],     a0, a1, a2, a3, bh0, bh2);
            MMA_F16(c[2 * p],     a0, a1, a2, a3, bl0, bl2);
            MMA_F16(c[2 * p + 1], a0, a1, a2, a3, bh1, bh3);
            MMA_F16(c[2 * p + 1], a0, a1, a2, a3, bl1, bl3);
        }
    }

    // epilogue: fp16 h1 + fused attention dots (block slice = 4 whole heads)
    int row0 = m0 + warp * 16 + (lane >> 2);
    int row1 = row0 + 8;
    int cbase = (lane & 3) * 2;
    float vs0[4] = {0, 0, 0, 0}, vd0[4] = {0, 0, 0, 0};
    float vs1[4] = {0, 0, 0, 0}, vd1[4] = {0, 0, 0, 0};
#pragma unroll
    for (int t = 0; t < 8; t++) {
        int col = n0 + t * 8 + cbase;
        *(__half2*)&d_h1h[(size_t)row0 * 256 + col] = __floats2half2_rn(c[t][0], c[t][1]);
        *(__half2*)&d_h1h[(size_t)row1 * 256 + col] = __floats2half2_rn(c[t][2], c[t][3]);
        float2 a2 = *(const float2*)&as_[col];
        float2 d2 = *(const float2*)&ad_[col];
        int hh = t >> 1;
        vs0[hh] += c[t][0] * a2.x + c[t][1] * a2.y;
        vd0[hh] += c[t][0] * d2.x + c[t][1] * d2.y;
        vs1[hh] += c[t][2] * a2.x + c[t][3] * a2.y;
        vd1[hh] += c[t][2] * d2.x + c[t][3] * d2.y;
    }
#pragma unroll
    for (int hh = 0; hh < 4; hh++) {
        vs0[hh] += __shfl_down_sync(0xffffffffu, vs0[hh], 2, 4);
        vs0[hh] += __shfl_down_sync(0xffffffffu, vs0[hh], 1, 4);
        vd0[hh] += __shfl_down_sync(0xffffffffu, vd0[hh], 2, 4);
        vd0[hh] += __shfl_down_sync(0xffffffffu, vd0[hh], 1, 4);
        vs1[hh] += __shfl_down_sync(0xffffffffu, vs1[hh], 2, 4);
        vs1[hh] += __shfl_down_sync(0xffffffffu, vs1[hh], 1, 4);
        vd1[hh] += __shfl_down_sync(0xffffffffu, vd1[hh], 2, 4);
        vd1[hh] += __shfl_down_sync(0xffffffffu, vd1[hh], 1, 4);
    }
    if ((lane & 3) == 0) {
        int H0 = blockIdx.y * 4;
        if (row0 < NN) {
#pragma unroll
            for (int hh = 0; hh < 4; hh++) {
                d_sa[row0 * 16 + H0 + hh] = vs0[hh];
                d_da[row0 * 16 + H0 + hh] = vd0[hh];
            }
        }
        if (row1 < NN) {
#pragma unroll
            for (int hh = 0; hh < 4; hh++) {
                d_sa[row1 * 16 + H0 + hh] = vs1[hh];
                d_da[row1 * 16 + H0 + hh] = vd1[hh];
            }
        }
    }
}
#define SMEM_MMA ((128 * PIT + 2 * 64 * PIT) * 2)

// ---------------- GAT aggregation body: 4-edge branchless online softmax ----------------
template <bool SPLIT>
static __device__ __forceinline__ void gat_body(int n, int lane,
                                                const float* __restrict__ b,
                                                float* __restrict__ outf) {
    int hd = lane >> 1;
    float da_l = d_da[n * 16 + hd];
    int beg = d_rowoff[n], end = d_rowoff[n + 1];

    float m = -1e30f, z = 0.f;
    float acc[8];
#pragma unroll
    for (int i = 0; i < 8; i++) acc[i] = 0.f;

    int e = beg;
    for (; e + 3 < end; e += 4) {
        int s0 = d_csr[e], s1 = d_csr[e + 1], s2 = d_csr[e + 2], s3 = d_csr[e + 3];
        float l0 = d_sa[s0 * 16 + hd] + da_l;
        float l1 = d_sa[s1 * 16 + hd] + da_l;
        float l2 = d_sa[s2 * 16 + hd] + da_l;
        float l3 = d_sa[s3 * 16 + hd] + da_l;
        uint4 hv0 = *(const uint4*)(d_h1h + (size_t)s0 * 256 + lane * 8);
        uint4 hv1 = *(const uint4*)(d_h1h + (size_t)s1 * 256 + lane * 8);
        uint4 hv2 = *(const uint4*)(d_h1h + (size_t)s2 * 256 + lane * 8);
        uint4 hv3 = *(const uint4*)(d_h1h + (size_t)s3 * 256 + lane * 8);
        l0 = l0 > 0.f ? l0 : 0.2f * l0;
        l1 = l1 > 0.f ? l1 : 0.2f * l1;
        l2 = l2 > 0.f ? l2 : 0.2f * l2;
        l3 = l3 > 0.f ? l3 : 0.2f * l3;
        float nm = fmaxf(fmaxf(m, fmaxf(l0, l1)), fmaxf(l2, l3));
        float sc = __expf(m - nm);
        float e0 = __expf(l0 - nm), e1 = __expf(l1 - nm);
        float e2 = __expf(l2 - nm), e3 = __expf(l3 - nm);
        m = nm;
        z = z * sc + (e0 + e1) + (e2 + e3);
        float2 f0 = __half22float2(*(__half2*)&hv0.x), f1 = __half22float2(*(__half2*)&hv0.y);
        float2 f2 = __half22float2(*(__half2*)&hv0.z), f3 = __half22float2(*(__half2*)&hv0.w);
        float2 g0 = __half22float2(*(__half2*)&hv1.x), g1 = __half22float2(*(__half2*)&hv1.y);
        float2 g2 = __half22float2(*(__half2*)&hv1.z), g3 = __half22float2(*(__half2*)&hv1.w);
        float2 p0 = __half22float2(*(__half2*)&hv2.x), p1 = __half22float2(*(__half2*)&hv2.y);
        float2 p2 = __half22float2(*(__half2*)&hv2.z), p3 = __half22float2(*(__half2*)&hv2.w);
        float2 q0 = __half22float2(*(__half2*)&hv3.x), q1 = __half22float2(*(__half2*)&hv3.y);
        float2 q2 = __half22float2(*(__half2*)&hv3.z), q3 = __half22float2(*(__half2*)&hv3.w);
        acc[0] = acc[0] * sc + (e0 * f0.x + e1 * g0.x) + (e2 * p0.x + e3 * q0.x);
        acc[1] = acc[1] * sc + (e0 * f0.y + e1 * g0.y) + (e2 * p0.y + e3 * q0.y);
        acc[2] = acc[2] * sc + (e0 * f1.x + e1 * g1.x) + (e2 * p1.x + e3 * q1.x);
        acc[3] = acc[3] * sc + (e0 * f1.y + e1 * g1.y) + (e2 * p1.y + e3 * q1.y);
        acc[4] = acc[4] * sc + (e0 * f2.x + e1 * g2.x) + (e2 * p2.x + e3 * q2.x);
        acc[5] = acc[5] * sc + (e0 * f2.y + e1 * g2.y) + (e2 * p2.y + e3 * q2.y);
        acc[6] = acc[6] * sc + (e0 * f3.x + e1 * g3.x) + (e2 * p3.x + e3 * q3.x);
        acc[7] = acc[7] * sc + (e0 * f3.y + e1 * g3.y) + (e2 * p3.y + e3 * q3.y);
    }
    for (; e < end; e++) {
        int s0 = d_csr[e];
        float l0 = d_sa[s0 * 16 + hd] + da_l;
        uint4 hv0 = *(const uint4*)(d_h1h + (size_t)s0 * 256 + lane * 8);
        l0 = l0 > 0.f ? l0 : 0.2f * l0;
        float nm = fmaxf(m, l0);
        float sc = __expf(m - nm);
        float e0 = __expf(l0 - nm);
        m = nm;
        z = z * sc + e0;
        float2 f0 = __half22float2(*(__half2*)&hv0.x), f1 = __half22float2(*(__half2*)&hv0.y);
        float2 f2 = __half22float2(*(__half2*)&hv0.z), f3 = __half22float2(*(__half2*)&hv0.w);
        acc[0] = acc[0] * sc + e0 * f0.x;
        acc[1] = acc[1] * sc + e0 * f0.y;
        acc[2] = acc[2] * sc + e0 * f1.x;
        acc[3] = acc[3] * sc + e0 * f1.y;
        acc[4] = acc[4] * sc + e0 * f2.x;
        acc[5] = acc[5] * sc + e0 * f2.y;
        acc[6] = acc[6] * sc + e0 * f3.x;
        acc[7] = acc[7] * sc + e0 * f3.y;
    }

    float invz = 1.f / (z + 1e-16f);
    float vo[8];
#pragma unroll
    for (int i = 0; i < 8; i++) {
        float v = acc[i] * invz + b[lane * 8 + i];
        vo[i] = v > 0.f ? v : (__expf(v) - 1.f);
    }
    if (SPLIT) {
        __half2 h0 = __floats2half2_rn(vo[0], vo[1]);
        __half2 h1 = __floats2half2_rn(vo[2], vo[3]);
        __half2 h2 = __floats2half2_rn(vo[4], vo[5]);
        __half2 h3 = __floats2half2_rn(vo[6], vo[7]);
        uint4 pk;
        pk.x = *(unsigned*)&h0; pk.y = *(unsigned*)&h1;
        pk.z = *(unsigned*)&h2; pk.w = *(unsigned*)&h3;
        *(uint4*)&d_Ah[(size_t)n * 256 + lane * 8] = pk;
    } else {
        *(float4*)&outf[(size_t)n * 256 + lane * 8] = make_float4(vo[0], vo[1], vo[2], vo[3]);
        *(float4*)&outf[(size_t)n * 256 + lane * 8 + 4] = make_float4(vo[4], vo[5], vo[6], vo[7]);
    }
}

template <bool SPLIT>
__global__ void k_gat_agg(const float* __restrict__ b, float* __restrict__ outf) {
    int n = (blockIdx.x * blockDim.x + threadIdx.x) >> 5;
    if (n >= NN) return;
    gat_body<SPLIT>(n, threadIdx.x & 31, b, outf);
}

// layer-3: aggregate ONLY the nodes the output reads (user/item lists)
__global__ void k_gat_agg_list(const float* __restrict__ b, float* __restrict__ outf,
                               const int* __restrict__ ui, const int* __restrict__ ii,
                               int P) {
    int i = (blockIdx.x * blockDim.x + threadIdx.x) >> 5;
    if (i >= 2 * P) return;
    int n = (i < P) ? ui[i] : ii[i - P];
    gat_body<false>(n, threadIdx.x & 31, b, outf);
}

// ---------------- final ----------------
__global__ void k_final(const float* __restrict__ h, const int* __restrict__ ui,
                        const int* __restrict__ ii, const float* __restrict__ Wd,
                        float* __restrict__ out) {
    int p = (blockIdx.x * blockDim.x + threadIdx.x) >> 5;
    if (p >= 1024) return;
    int lane = threadIdx.x & 31;
    int u = ui[p], it = ii[p];
    float a0 = 0.f, a1 = 0.f;
    for (int k = lane; k < 256; k += 32) {
        float v = h[u * 256 + k];
        a0 += v * Wd[k * 2 + 0];
        a1 += v * Wd[k * 2 + 1];
        float w = h[it * 256 + k];
        a0 += w * Wd[(256 + k) * 2 + 0];
        a1 += w * Wd[(256 + k) * 2 + 1];
    }
#pragma unroll
    for (int off = 16; off >= 1; off >>= 1) {
        a0 += __shfl_down_sync(0xffffffffu, a0, off);
        a1 += __shfl_down_sync(0xffffffffu, a1, off);
    }
    if (lane == 0) {
        float mx = fmaxf(a0, a1);
        float lse = mx + __logf(__expf(a0 - mx) + __expf(a1 - mx));
        out[p * 2 + 0] = a0 - lse;
        out[p * 2 + 1] = a1 - lse;
    }
}

// ---------------- launcher ----------------
extern "C" void kernel_launch(void* const* d_in, const int* in_sizes, int n_in,
                              void* d_out, int out_size) {
    const float* x    = (const float*)d_in[0];
    const int*   ei   = (const int*)d_in[1];
    const float* Hd   = (const float*)d_in[2];
    const int*   ui   = (const int*)d_in[3];
    const int*   ii   = (const int*)d_in[4];
    const float* Wg   = (const float*)d_in[5];
    const float* bg   = (const float*)d_in[6];
    const float* W1   = (const float*)d_in[7];
    const float* a1s  = (const float*)d_in[8];
    const float* a1d  = (const float*)d_in[9];
    const float* b1   = (const float*)d_in[10];
    const float* W2   = (const float*)d_in[11];
    const float* a2s  = (const float*)d_in[12];
    const float* a2d  = (const float*)d_in[13];
    const float* b2   = (const float*)d_in[14];
    const float* W3   = (const float*)d_in[15];
    const float* a3s  = (const float*)d_in[16];
    const float* a3d  = (const float*)d_in[17];
    const float* b3   = (const float*)d_in[18];
    const float* wd   = (const float*)d_in[19];
    const float* wr   = (const float*)d_in[20];
    const float* wdnn = (const float*)d_in[21];
    float* out = (float*)d_out;

    int P = in_sizes[3];   // number of user/item pairs

    void *p_h0, *p_bufA, *p_w2hi, *p_w2lo, *p_w3hi, *p_w3lo;
    cudaGetSymbolAddress(&p_h0, d_h0);
    cudaGetSymbolAddress(&p_bufA, d_bufA);
    cudaGetSymbolAddress(&p_w2hi, d_W2hi);
    cudaGetSymbolAddress(&p_w2lo, d_W2lo);
    cudaGetSymbolAddress(&p_w3hi, d_W3hi);
    cudaGetSymbolAddress(&p_w3lo, d_W3lo);
    float* h0   = (float*)p_h0;
    float* bufA = (float*)p_bufA;

    cudaFuncSetAttribute(k_transform_mma,
                         cudaFuncAttributeMaxDynamicSharedMemorySize, SMEM_MMA);

    k_setup<<<SB_TOTAL, 256>>>(W2, W3, ei + EE, Hd, wr);
    k_phase2<<<65, 1024>>>(wd);
    k_phase3<<<PB_TOTAL, 256>>>(ei, x, Wg);
    k_gcn_agg<<<(NN * 16 + 255) / 256, 256>>>(bg);

    // GAT layer 1
    k_transform16<<<NN / 16, 128>>>(h0, W1, a1s, a1d);
    k_gat_agg<true><<<(NN * 32 + 255) / 256, 256>>>(b1, nullptr);

    // GAT layer 2 (tensor cores, fused att dots)
    k_transform_mma<<<dim3(NP / 128, 4), 256, SMEM_MMA>>>(
        (const __half*)p_w2hi, (const __half*)p_w2lo, a2s, a2d);
    k_gat_agg<true><<<(NN * 32 + 255) / 256, 256>>>(b2, nullptr);

    // GAT layer 3: transform for all nodes, aggregate only listed nodes
    k_transform_mma<<<dim3(NP / 128, 4), 256, SMEM_MMA>>>(
        (const __half*)p_w3hi, (const __half*)p_w3lo, a3s, a3d);
    k_gat_agg_list<<<(2 * P * 32 + 255) / 256, 256>>>(b3, bufA, ui, ii, P);

    k_final<<<(1024 * 32 + 255) / 256, 256>>>(bufA, ui, ii, wdnn, out);
}

// round 10
// speedup vs baseline: 2.7329x; 1.0949x over previous
#include <cuda_runtime.h>
#include <cuda_bf16.h>
#include <cuda_fp16.h>
#include <math.h>

#define NN 50000
#define NP 50048          // padded to 128
#define EE 800000
#define ET (EE + NN)      // edges + self loops
#define PIT 264           // smem row pitch (fp16): 33*16B -> LDSM conflict-free

// ---------------- scratch (device globals; no allocation allowed) ----------------
__device__ float d_T2[512 * 16];             // Hd @ Wr
__device__ float d_M[128 * 16];              // Wd @ T2
__device__ int   d_deg[NN];                  // starts 0; scan resets to 0 after use
__device__ int   d_rowoff[NN + 1];
__device__ int   d_cursor[NN];               // gcn_agg resets to 0 after scatter
__device__ float d_dis[NN];
__device__ int   d_csr[ET];
__device__ float d_xw[NN * 16];
__device__ float d_dual[NN * 16];
__device__ float d_h0[NN * 16];
__device__ __half d_h1h[NP * 256];           // fp16 transformed features (agg gather)
__device__ __half d_Ah[NP * 256];            // fp16 input activations for MMA (pads stay 0)
__device__ float d_bufA[NN * 256];
__device__ float d_sa[NN * 16];
__device__ float d_da[NN * 16];
__device__ __half d_W2hi[256 * 256];         // W2^T split [n][k]  fp16 hi
__device__ __half d_W2lo[256 * 256];
__device__ __half d_W3hi[256 * 256];
__device__ __half d_W3lo[256 * 256];
__device__ int   d_mark[NN];                 // zero-init; compact resets to 0
__device__ int   d_list[NN];
__device__ int   d_listcnt;

// ================= merged SETUP: prepW | count | gemmA =================
#define SB_PREPW 512
#define SB_COUNT 782
#define SB_GEMMA 1024
#define SB_TOTAL (SB_PREPW + SB_COUNT + SB_GEMMA)

__global__ void k_setup(const float* __restrict__ W2, const float* __restrict__ W3,
                        const int* __restrict__ dst,
                        const float* __restrict__ hd, const float* __restrict__ wr) {
    int bid = blockIdx.x, tid = threadIdx.x;
    if (bid < SB_PREPW) {
        int idx = bid * 256 + tid;
        int sel = idx >> 16;
        int r = idx & 65535;
        int n = r >> 8, k = r & 255;
        float w = (sel ? W3 : W2)[k * 256 + n];
        __half h = __float2half_rn(w);
        __half l = __float2half_rn(w - __half2float(h));
        if (sel) { d_W3hi[r] = h; d_W3lo[r] = l; }
        else     { d_W2hi[r] = h; d_W2lo[r] = l; }
    } else if (bid < SB_PREPW + SB_COUNT) {
        int t = (bid - SB_PREPW) * 256 + tid;
        int e0 = t * 4;
        if (e0 + 3 < EE) {
            int4 d4 = *(const int4*)(dst + e0);
            atomicAdd(&d_deg[d4.x], 1);
            atomicAdd(&d_deg[d4.y], 1);
            atomicAdd(&d_deg[d4.z], 1);
            atomicAdd(&d_deg[d4.w], 1);
        } else {
            for (int e = e0; e < EE; e++) atomicAdd(&d_deg[dst[e]], 1);
        }
    } else {
        int w = ((bid - SB_PREPW - SB_COUNT) * 256 + tid) >> 5;
        int lane = tid & 31;
        int i = w >> 4, j = w & 15;
        float a = 0.f;
#pragma unroll
        for (int kk = 0; kk < 16; kk++) {
            int k = lane + kk * 32;
            a += hd[i * 512 + k] * wr[k * 16 + j];
        }
#pragma unroll
        for (int off = 16; off >= 1; off >>= 1)
            a += __shfl_down_sync(0xffffffffu, a, off);
        if (lane == 0) d_T2[w] = a;
    }
}

// ================= merged PHASE2: scan (block 0) | gemmB =================
__global__ void __launch_bounds__(1024)
k_phase2(const float* __restrict__ wd) {
    if (blockIdx.x == 0) {
        __shared__ int warp_sums[32];
        int t = threadIdx.x;
        const int S = 49;
        int b0 = t * S;
        int sum = 0;
        for (int i = 0; i < S; i++) {
            int idx = b0 + i;
            if (idx < NN) sum += d_deg[idx] + 1;
        }
        int lane = t & 31, w = t >> 5;
        int v = sum;
#pragma unroll
        for (int off = 1; off < 32; off <<= 1) {
            int u = __shfl_up_sync(0xffffffffu, v, off);
            if (lane >= off) v += u;
        }
        if (lane == 31) warp_sums[w] = v;
        __syncthreads();
        if (w == 0) {
            int ws = warp_sums[lane];
#pragma unroll
            for (int off = 1; off < 32; off <<= 1) {
                int u = __shfl_up_sync(0xffffffffu, ws, off);
                if (lane >= off) ws += u;
            }
            warp_sums[lane] = ws;
        }
        __syncthreads();
        int ex = v - sum + (w > 0 ? warp_sums[w - 1] : 0);
        int run = ex;
        for (int i = 0; i < S; i++) {
            int idx = b0 + i;
            if (idx < NN) {
                int dg = d_deg[idx] + 1;
                d_deg[idx] = 0;
                run += dg;
                d_rowoff[idx + 1] = run;
                d_dis[idx] = rsqrtf((float)dg);
            }
        }
        if (t == 0) d_rowoff[0] = 0;
    } else {
        int w = (blockIdx.x - 1) * 32 + (threadIdx.x >> 5);
        int lane = threadIdx.x & 31;
        int i = w >> 4, j = w & 15;
        float a = 0.f;
#pragma unroll
        for (int kk = 0; kk < 16; kk++) {
            int k = lane + kk * 32;
            a += wd[i * 512 + k] * d_T2[k * 16 + j];
        }
#pragma unroll
        for (int off = 16; off >= 1; off >>= 1)
            a += __shfl_down_sync(0xffffffffu, a, off);
        if (lane == 0) d_M[w] = a;
    }
}

// ================= merged PHASE3: scatter | xw_dual =================
#define PB_SCAT ((ET + 255) / 256)
#define PB_XW (NN / 16)
#define PB_TOTAL (PB_SCAT + PB_XW)

__global__ void __launch_bounds__(256)
k_phase3(const int* __restrict__ ei, const float* __restrict__ x,
         const float* __restrict__ Wg) {
    int bid = blockIdx.x, tid = threadIdx.x;
    if (bid < PB_SCAT) {
        int e = bid * 256 + tid;
        if (e >= ET) return;
        int s, dd;
        if (e < EE) { s = ei[e]; dd = ei[EE + e]; }
        else        { s = dd = e - EE; }
        int p = atomicAdd(&d_cursor[dd], 1);
        d_csr[d_rowoff[dd] + p] = s;
    } else {
        __shared__ float sx[16][132];
        int nb = (bid - PB_SCAT) * 16;
        const float4* xs = (const float4*)(x + (size_t)nb * 128);
        for (int i = tid; i < 512; i += 256) {
            float4 v = xs[i];
            int r = i >> 5, c = (i & 31) * 4;
            sx[r][c] = v.x; sx[r][c + 1] = v.y; sx[r][c + 2] = v.z; sx[r][c + 3] = v.w;
        }
        __syncthreads();
        int nl = tid >> 4, j = tid & 15;
        float a = 0.f, b = 0.f;
#pragma unroll 4
        for (int k = 0; k < 128; k++) {
            float xv = sx[nl][k];
            a += xv * Wg[k * 16 + j];
            b += xv * d_M[k * 16 + j];
        }
        int n = nb + nl;
        d_xw[n * 16 + j] = a;
        d_dual[n * 16 + j] = b;
    }
}

// ======= merged: GCN aggregation (float4 channels) | mark layer-3 needed set =======
#define GB_GCN ((NN * 4 + 255) / 256)

__global__ void k_gcn_agg(const float* __restrict__ bg,
                          const int* __restrict__ ui, const int* __restrict__ ii,
                          int P) {
    int bid = blockIdx.x, tid = threadIdx.x;
    if (bid < GB_GCN) {
        int t = bid * 256 + tid;
        int g = t >> 2, c4 = t & 3;
        if (g >= NN) return;
        int beg = d_rowoff[g], end = d_rowoff[g + 1];
        float4 acc = make_float4(0.f, 0.f, 0.f, 0.f);
        for (int e = beg; e < end; e++) {
            int s = d_csr[e];
            float ds = d_dis[s];
            float4 xw = ((const float4*)(d_xw + s * 16))[c4];
            acc.x += ds * xw.x; acc.y += ds * xw.y;
            acc.z += ds * xw.z; acc.w += ds * xw.w;
        }
        float dg = d_dis[g];
        float4 du = ((const float4*)(d_dual + g * 16))[c4];
        float4 vo;
        vo.x = acc.x * dg + bg[c4 * 4 + 0] + du.x;
        vo.y = acc.y * dg + bg[c4 * 4 + 1] + du.y;
        vo.z = acc.z * dg + bg[c4 * 4 + 2] + du.z;
        vo.w = acc.w * dg + bg[c4 * 4 + 3] + du.w;
        vo.x = vo.x > 0.f ? vo.x : (__expf(vo.x) - 1.f);
        vo.y = vo.y > 0.f ? vo.y : (__expf(vo.y) - 1.f);
        vo.z = vo.z > 0.f ? vo.z : (__expf(vo.z) - 1.f);
        vo.w = vo.w > 0.f ? vo.w : (__expf(vo.w) - 1.f);
        ((float4*)(d_h0 + g * 16))[c4] = vo;
        if (c4 == 0) d_cursor[g] = 0;   // reset for next replay
    } else {
        // mark: list nodes + their CSR sources
        int i = (bid - GB_GCN) * 256 + tid;
        if (i == 0) d_listcnt = 0;
        if (i < 2 * P) {
            int n = (i < P) ? ui[i] : ii[i - P];
            d_mark[n] = 1;
            int beg = d_rowoff[n], end = d_rowoff[n + 1];
            for (int e = beg; e < end; e++) d_mark[d_csr[e]] = 1;
        }
    }
}

// ---------------- GAT layer-1 transform (FIN=16, FFMA; writes fp16 h1) ----------------
__global__ void __launch_bounds__(128, 8)
k_transform16(const float* __restrict__ hin, const float* __restrict__ W,
              const float* __restrict__ asrc, const float* __restrict__ adst) {
    __shared__ float s[16][16];
    int tid = threadIdx.x;
    int nb = blockIdx.x * 16;
    const float4* hin4 = (const float4*)(hin + nb * 16);
    float4* s4 = (float4*)s;
    for (int t = tid; t < 16 * 16 / 4; t += 128) s4[t] = hin4[t];
    __syncthreads();

    int cg = tid & 63;
    int ng = tid >> 6;
    const float4* W4 = (const float4*)W;
    float4 acc[8];
#pragma unroll
    for (int r = 0; r < 8; r++) acc[r] = make_float4(0.f, 0.f, 0.f, 0.f);

#pragma unroll
    for (int k = 0; k < 16; k++) {
        float4 w = W4[k * 64 + cg];
#pragma unroll
        for (int r = 0; r < 8; r++) {
            float sv = s[ng * 8 + r][k];
            acc[r].x += sv * w.x; acc[r].y += sv * w.y;
            acc[r].z += sv * w.z; acc[r].w += sv * w.w;
        }
    }

    float4 as4 = ((const float4*)asrc)[cg];
    float4 ad4 = ((const float4*)adst)[cg];
#pragma unroll
    for (int r = 0; r < 8; r++) {
        int n = nb + ng * 8 + r;
        if (n >= NN) break;
        __half2 p0 = __floats2half2_rn(acc[r].x, acc[r].y);
        __half2 p1 = __floats2half2_rn(acc[r].z, acc[r].w);
        *(__half2*)&d_h1h[(size_t)n * 256 + cg * 4] = p0;
        *(__half2*)&d_h1h[(size_t)n * 256 + cg * 4 + 2] = p1;
        float vs = acc[r].x * as4.x + acc[r].y * as4.y + acc[r].z * as4.z + acc[r].w * as4.w;
        float vd = acc[r].x * ad4.x + acc[r].y * ad4.y + acc[r].z * ad4.z + acc[r].w * ad4.w;
        vs += __shfl_down_sync(0xffffffffu, vs, 2, 4);
        vs += __shfl_down_sync(0xffffffffu, vs, 1, 4);
        vd += __shfl_down_sync(0xffffffffu, vd, 2, 4);
        vd += __shfl_down_sync(0xffffffffu, vd, 1, 4);
        if ((cg & 3) == 0) {
            int h = cg >> 2;
            d_sa[n * 16 + h] = vs;
            d_da[n * 16 + h] = vd;
        }
    }
}

// ---------------- MMA helpers ----------------
#define MMA_F16(C, A0, A1, A2, A3, B0, B1)                                   \
    asm volatile(                                                            \
        "mma.sync.aligned.m16n8k16.row.col.f32.f16.f16.f32 "                 \
        "{%0,%1,%2,%3}, {%4,%5,%6,%7}, {%8,%9}, {%0,%1,%2,%3};\n"            \
        : "+f"(C[0]), "+f"(C[1]), "+f"(C[2]), "+f"(C[3])                     \
        : "r"(A0), "r"(A1), "r"(A2), "r"(A3), "r"(B0), "r"(B1))

#define LDSM4(R0, R1, R2, R3, ADDR)                                          \
    asm volatile("ldmatrix.sync.aligned.m8n8.x4.shared.b16 {%0,%1,%2,%3}, [%4];" \
        : "=r"(R0), "=r"(R1), "=r"(R2), "=r"(R3) : "r"(ADDR))

#define SMEM_MMA ((128 * PIT + 2 * 64 * PIT) * 2)

// shared mainloop + epilogue given staged smem; writes h1/sa/da for rows g0,g1 (-1 = skip)
static __device__ __forceinline__ void mma_core(__half* sA, __half* sBhi, __half* sBlo,
                                                int lane, int warp, int n0,
                                                const float* __restrict__ as_,
                                                const float* __restrict__ ad_,
                                                int g0, int g1, int H0) {
    float c[8][4];
#pragma unroll
    for (int t = 0; t < 8; t++)
#pragma unroll
        for (int j = 0; j < 4; j++) c[t][j] = 0.f;

    int rA = warp * 16 + (lane & 15);
    int kOff = (lane >> 4) << 3;
    unsigned aB = (unsigned)__cvta_generic_to_shared(sA + rA * PIT + kOff);
    int rB = lane & 15;
    unsigned bHiB = (unsigned)__cvta_generic_to_shared(sBhi + rB * PIT + kOff);
    unsigned bLoB = (unsigned)__cvta_generic_to_shared(sBlo + rB * PIT + kOff);

#pragma unroll 4
    for (int kc = 0; kc < 16; kc++) {
        unsigned ka = kc * 32;
        unsigned a0, a1, a2, a3;
        LDSM4(a0, a1, a2, a3, aB + ka);
#pragma unroll
        for (int p = 0; p < 4; p++) {
            unsigned boff = (unsigned)(p * 16 * PIT * 2) + ka;
            unsigned bh0, bh1, bh2, bh3, bl0, bl1, bl2, bl3;
            LDSM4(bh0, bh1, bh2, bh3, bHiB + boff);
            LDSM4(bl0, bl1, bl2, bl3, bLoB + boff);
            MMA_F16(c[2 * p],     a0, a1, a2, a3, bh0, bh2);
            MMA_F16(c[2 * p],     a0, a1, a2, a3, bl0, bl2);
            MMA_F16(c[2 * p + 1], a0, a1, a2, a3, bh1, bh3);
            MMA_F16(c[2 * p + 1], a0, a1, a2, a3, bl1, bl3);
        }
    }

    int cbase = (lane & 3) * 2;
    float vs0[4] = {0, 0, 0, 0}, vd0[4] = {0, 0, 0, 0};
    float vs1[4] = {0, 0, 0, 0}, vd1[4] = {0, 0, 0, 0};
#pragma unroll
    for (int t = 0; t < 8; t++) {
        int col = n0 + t * 8 + cbase;
        if (g0 >= 0)
            *(__half2*)&d_h1h[(size_t)g0 * 256 + col] = __floats2half2_rn(c[t][0], c[t][1]);
        if (g1 >= 0)
            *(__half2*)&d_h1h[(size_t)g1 * 256 + col] = __floats2half2_rn(c[t][2], c[t][3]);
        float2 a2 = *(const float2*)&as_[col];
        float2 d2 = *(const float2*)&ad_[col];
        int hh = t >> 1;
        vs0[hh] += c[t][0] * a2.x + c[t][1] * a2.y;
        vd0[hh] += c[t][0] * d2.x + c[t][1] * d2.y;
        vs1[hh] += c[t][2] * a2.x + c[t][3] * a2.y;
        vd1[hh] += c[t][2] * d2.x + c[t][3] * d2.y;
    }
#pragma unroll
    for (int hh = 0; hh < 4; hh++) {
        vs0[hh] += __shfl_down_sync(0xffffffffu, vs0[hh], 2, 4);
        vs0[hh] += __shfl_down_sync(0xffffffffu, vs0[hh], 1, 4);
        vd0[hh] += __shfl_down_sync(0xffffffffu, vd0[hh], 2, 4);
        vd0[hh] += __shfl_down_sync(0xffffffffu, vd0[hh], 1, 4);
        vs1[hh] += __shfl_down_sync(0xffffffffu, vs1[hh], 2, 4);
        vs1[hh] += __shfl_down_sync(0xffffffffu, vs1[hh], 1, 4);
        vd1[hh] += __shfl_down_sync(0xffffffffu, vd1[hh], 2, 4);
        vd1[hh] += __shfl_down_sync(0xffffffffu, vd1[hh], 1, 4);
    }
    if ((lane & 3) == 0) {
        if (g0 >= 0 && g0 < NN) {
#pragma unroll
            for (int hh = 0; hh < 4; hh++) {
                d_sa[g0 * 16 + H0 + hh] = vs0[hh];
                d_da[g0 * 16 + H0 + hh] = vd0[hh];
            }
        }
        if (g1 >= 0 && g1 < NN) {
#pragma unroll
            for (int hh = 0; hh < 4; hh++) {
                d_sa[g1 * 16 + H0 + hh] = vs1[hh];
                d_da[g1 * 16 + H0 + hh] = vd1[hh];
            }
        }
    }
}

// layer-2: all rows
__global__ void __launch_bounds__(256, 1)
k_transform_mma(const __half* __restrict__ Bhi, const __half* __restrict__ Blo,
                const float* __restrict__ as_, const float* __restrict__ ad_) {
    extern __shared__ __half sm[];
    __half* sA = sm;
    __half* sBhi = sA + 128 * PIT;
    __half* sBlo = sBhi + 64 * PIT;
    int tid = threadIdx.x, lane = tid & 31, warp = tid >> 5;
    int m0 = blockIdx.x * 128;
    int n0 = blockIdx.y * 64;
    {
        const uint4* gA = (const uint4*)(d_Ah + (size_t)m0 * 256);
        for (int i = tid; i < 128 * 32; i += 256) {
            int r = i >> 5, c = i & 31;
            *(uint4*)(sA + r * PIT + c * 8) = gA[r * 32 + c];
        }
        const uint4* bH = (const uint4*)(Bhi + (size_t)n0 * 256);
        const uint4* bL = (const uint4*)(Blo + (size_t)n0 * 256);
        for (int i = tid; i < 64 * 32; i += 256) {
            int r = i >> 5, c = i & 31;
            *(uint4*)(sBhi + r * PIT + c * 8) = bH[r * 32 + c];
            *(uint4*)(sBlo + r * PIT + c * 8) = bL[r * 32 + c];
        }
    }
    __syncthreads();
    int g0 = m0 + warp * 16 + (lane >> 2);
    mma_core(sA, sBhi, sBlo, lane, warp, n0, as_, ad_, g0, g0 + 8, blockIdx.y * 4);
}

// layer-3: only listed rows (gather A by index, scatter outputs)
__global__ void __launch_bounds__(256, 1)
k_transform_mma_idx(const __half* __restrict__ Bhi, const __half* __restrict__ Blo,
                    const float* __restrict__ as_, const float* __restrict__ ad_) {
    extern __shared__ __half sm[];
    __shared__ int snode[128];
    __half* sA = sm;
    __half* sBhi = sA + 128 * PIT;
    __half* sBlo = sBhi + 64 * PIT;
    int tid = threadIdx.x, lane = tid & 31, warp = tid >> 5;
    int m0 = blockIdx.x * 128;
    int n0 = blockIdx.y * 64;
    int cnt = d_listcnt;
    if (m0 >= cnt) return;
    for (int i = tid; i < 128; i += 256) {
        int r = m0 + i;
        snode[i] = (r < cnt) ? d_list[r] : -1;
    }
    __syncthreads();
    {
        for (int i = tid; i < 128 * 32; i += 256) {
            int r = i >> 5, c = i & 31;
            int nd = snode[r];
            uint4 v = make_uint4(0, 0, 0, 0);
            if (nd >= 0) v = ((const uint4*)(d_Ah + (size_t)nd * 256))[c];
            *(uint4*)(sA + r * PIT + c * 8) = v;
        }
        const uint4* bH = (const uint4*)(Bhi + (size_t)n0 * 256);
        const uint4* bL = (const uint4*)(Blo + (size_t)n0 * 256);
        for (int i = tid; i < 64 * 32; i += 256) {
            int r = i >> 5, c = i & 31;
            *(uint4*)(sBhi + r * PIT + c * 8) = bH[r * 32 + c];
            *(uint4*)(sBlo + r * PIT + c * 8) = bL[r * 32 + c];
        }
    }
    __syncthreads();
    int r0 = warp * 16 + (lane >> 2);
    mma_core(sA, sBhi, sBlo, lane, warp, n0, as_, ad_, snode[r0], snode[r0 + 8], blockIdx.y * 4);
}

// ---------------- GAT aggregation body: 4-edge branchless online softmax ----------------
template <bool SPLIT>
static __device__ __forceinline__ void gat_body(int n, int lane,
                                                const float* __restrict__ b,
                                                float* __restrict__ outf) {
    int hd = lane >> 1;
    float da_l = d_da[n * 16 + hd];
    int beg = d_rowoff[n], end = d_rowoff[n + 1];

    float m = -1e30f, z = 0.f;
    float acc[8];
#pragma unroll
    for (int i = 0; i < 8; i++) acc[i] = 0.f;

    int e = beg;
    for (; e + 3 < end; e += 4) {
        int s0 = d_csr[e], s1 = d_csr[e + 1], s2 = d_csr[e + 2], s3 = d_csr[e + 3];
        float l0 = d_sa[s0 * 16 + hd] + da_l;
        float l1 = d_sa[s1 * 16 + hd] + da_l;
        float l2 = d_sa[s2 * 16 + hd] + da_l;
        float l3 = d_sa[s3 * 16 + hd] + da_l;
        uint4 hv0 = *(const uint4*)(d_h1h + (size_t)s0 * 256 + lane * 8);
        uint4 hv1 = *(const uint4*)(d_h1h + (size_t)s1 * 256 + lane * 8);
        uint4 hv2 = *(const uint4*)(d_h1h + (size_t)s2 * 256 + lane * 8);
        uint4 hv3 = *(const uint4*)(d_h1h + (size_t)s3 * 256 + lane * 8);
        l0 = l0 > 0.f ? l0 : 0.2f * l0;
        l1 = l1 > 0.f ? l1 : 0.2f * l1;
        l2 = l2 > 0.f ? l2 : 0.2f * l2;
        l3 = l3 > 0.f ? l3 : 0.2f * l3;
        float nm = fmaxf(fmaxf(m, fmaxf(l0, l1)), fmaxf(l2, l3));
        float sc = __expf(m - nm);
        float e0 = __expf(l0 - nm), e1 = __expf(l1 - nm);
        float e2 = __expf(l2 - nm), e3 = __expf(l3 - nm);
        m = nm;
        z = z * sc + (e0 + e1) + (e2 + e3);
        float2 f0 = __half22float2(*(__half2*)&hv0.x), f1 = __half22float2(*(__half2*)&hv0.y);
        float2 f2 = __half22float2(*(__half2*)&hv0.z), f3 = __half22float2(*(__half2*)&hv0.w);
        float2 g0 = __half22float2(*(__half2*)&hv1.x), g1 = __half22float2(*(__half2*)&hv1.y);
        float2 g2 = __half22float2(*(__half2*)&hv1.z), g3 = __half22float2(*(__half2*)&hv1.w);
        float2 p0 = __half22float2(*(__half2*)&hv2.x), p1 = __half22float2(*(__half2*)&hv2.y);
        float2 p2 = __half22float2(*(__half2*)&hv2.z), p3 = __half22float2(*(__half2*)&hv2.w);
        float2 q0 = __half22float2(*(__half2*)&hv3.x), q1 = __half22float2(*(__half2*)&hv3.y);
        float2 q2 = __half22float2(*(__half2*)&hv3.z), q3 = __half22float2(*(__half2*)&hv3.w);
        acc[0] = acc[0] * sc + (e0 * f0.x + e1 * g0.x) + (e2 * p0.x + e3 * q0.x);
        acc[1] = acc[1] * sc + (e0 * f0.y + e1 * g0.y) + (e2 * p0.y + e3 * q0.y);
        acc[2] = acc[2] * sc + (e0 * f1.x + e1 * g1.x) + (e2 * p1.x + e3 * q1.x);
        acc[3] = acc[3] * sc + (e0 * f1.y + e1 * g1.y) + (e2 * p1.y + e3 * q1.y);
        acc[4] = acc[4] * sc + (e0 * f2.x + e1 * g2.x) + (e2 * p2.x + e3 * q2.x);
        acc[5] = acc[5] * sc + (e0 * f2.y + e1 * g2.y) + (e2 * p2.y + e3 * q2.y);
        acc[6] = acc[6] * sc + (e0 * f3.x + e1 * g3.x) + (e2 * p3.x + e3 * q3.x);
        acc[7] = acc[7] * sc + (e0 * f3.y + e1 * g3.y) + (e2 * p3.y + e3 * q3.y);
    }
    for (; e < end; e++) {
        int s0 = d_csr[e];
        float l0 = d_sa[s0 * 16 + hd] + da_l;
        uint4 hv0 = *(const uint4*)(d_h1h + (size_t)s0 * 256 + lane * 8);
        l0 = l0 > 0.f ? l0 : 0.2f * l0;
        float nm = fmaxf(m, l0);
        float sc = __expf(m - nm);
        float e0 = __expf(l0 - nm);
        m = nm;
        z = z * sc + e0;
        float2 f0 = __half22float2(*(__half2*)&hv0.x), f1 = __half22float2(*(__half2*)&hv0.y);
        float2 f2 = __half22float2(*(__half2*)&hv0.z), f3 = __half22float2(*(__half2*)&hv0.w);
        acc[0] = acc[0] * sc + e0 * f0.x;
        acc[1] = acc[1] * sc + e0 * f0.y;
        acc[2] = acc[2] * sc + e0 * f1.x;
        acc[3] = acc[3] * sc + e0 * f1.y;
        acc[4] = acc[4] * sc + e0 * f2.x;
        acc[5] = acc[5] * sc + e0 * f2.y;
        acc[6] = acc[6] * sc + e0 * f3.x;
        acc[7] = acc[7] * sc + e0 * f3.y;
    }

    float invz = 1.f / (z + 1e-16f);
    float vo[8];
#pragma unroll
    for (int i = 0; i < 8; i++) {
        float v = acc[i] * invz + b[lane * 8 + i];
        vo[i] = v > 0.f ? v : (__expf(v) - 1.f);
    }
    if (SPLIT) {
        __half2 h0 = __floats2half2_rn(vo[0], vo[1]);
        __half2 h1 = __floats2half2_rn(vo[2], vo[3]);
        __half2 h2 = __floats2half2_rn(vo[4], vo[5]);
        __half2 h3 = __floats2half2_rn(vo[6], vo[7]);
        uint4 pk;
        pk.x = *(unsigned*)&h0; pk.y = *(unsigned*)&h1;
        pk.z = *(unsigned*)&h2; pk.w = *(unsigned*)&h3;
        *(uint4*)&d_Ah[(size_t)n * 256 + lane * 8] = pk;
    } else {
        *(float4*)&outf[(size_t)n * 256 + lane * 8] = make_float4(vo[0], vo[1], vo[2], vo[3]);
        *(float4*)&outf[(size_t)n * 256 + lane * 8 + 4] = make_float4(vo[4], vo[5], vo[6], vo[7]);
    }
}

// layer-1 agg (all nodes) | compact tail blocks
#define AB_AGG ((NN * 32) / 256)
#define AB_CMP ((NN + 255) / 256)

__global__ void k_agg1(const float* __restrict__ b) {
    int bid = blockIdx.x;
    if (bid < AB_AGG) {
        int n = (bid * 256 + threadIdx.x) >> 5;
        if (n >= NN) return;
        gat_body<true>(n, threadIdx.x & 31, b, nullptr);
    } else {
        int i = (bid - AB_AGG) * 256 + threadIdx.x;
        if (i < NN && d_mark[i]) {
            int pos = atomicAdd(&d_listcnt, 1);
            d_list[pos] = i;
            d_mark[i] = 0;
        }
    }
}

// layer-2 agg: only listed nodes
__global__ void k_agg2_idx(const float* __restrict__ b) {
    int i = (blockIdx.x * blockDim.x + threadIdx.x) >> 5;
    if (i >= d_listcnt) return;
    gat_body<true>(d_list[i], threadIdx.x & 31, b, nullptr);
}

// layer-3: aggregate ONLY the user/item nodes
__global__ void k_gat_agg_list(const float* __restrict__ b, float* __restrict__ outf,
                               const int* __restrict__ ui, const int* __restrict__ ii,
                               int P) {
    int i = (blockIdx.x * blockDim.x + threadIdx.x) >> 5;
    if (i >= 2 * P) return;
    int n = (i < P) ? ui[i] : ii[i - P];
    gat_body<false>(n, threadIdx.x & 31, b, outf);
}

// ---------------- final ----------------
__global__ void k_final(const float* __restrict__ h, const int* __restrict__ ui,
                        const int* __restrict__ ii, const float* __restrict__ Wd,
                        float* __restrict__ out) {
    int p = (blockIdx.x * blockDim.x + threadIdx.x) >> 5;
    if (p >= 1024) return;
    int lane = threadIdx.x & 31;
    int u = ui[p], it = ii[p];
    float a0 = 0.f, a1 = 0.f;
    for (int k = lane; k < 256; k += 32) {
        float v = h[u * 256 + k];
        a0 += v * Wd[k * 2 + 0];
        a1 += v * Wd[k * 2 + 1];
        float w = h[it * 256 + k];
        a0 += w * Wd[(256 + k) * 2 + 0];
        a1 += w * Wd[(256 + k) * 2 + 1];
    }
#pragma unroll
    for (int off = 16; off >= 1; off >>= 1) {
        a0 += __shfl_down_sync(0xffffffffu, a0, off);
        a1 += __shfl_down_sync(0xffffffffu, a1, off);
    }
    if (lane == 0) {
        float mx = fmaxf(a0, a1);
        float lse = mx + __logf(__expf(a0 - mx) + __expf(a1 - mx));
        out[p * 2 + 0] = a0 - lse;
        out[p * 2 + 1] = a1 - lse;
    }
}

// ---------------- launcher ----------------
extern "C" void kernel_launch(void* const* d_in, const int* in_sizes, int n_in,
                              void* d_out, int out_size) {
    const float* x    = (const float*)d_in[0];
    const int*   ei   = (const int*)d_in[1];
    const float* Hd   = (const float*)d_in[2];
    const int*   ui   = (const int*)d_in[3];
    const int*   ii   = (const int*)d_in[4];
    const float* Wg   = (const float*)d_in[5];
    const float* bg   = (const float*)d_in[6];
    const float* W1   = (const float*)d_in[7];
    const float* a1s  = (const float*)d_in[8];
    const float* a1d  = (const float*)d_in[9];
    const float* b1   = (const float*)d_in[10];
    const float* W2   = (const float*)d_in[11];
    const float* a2s  = (const float*)d_in[12];
    const float* a2d  = (const float*)d_in[13];
    const float* b2   = (const float*)d_in[14];
    const float* W3   = (const float*)d_in[15];
    const float* a3s  = (const float*)d_in[16];
    const float* a3d  = (const float*)d_in[17];
    const float* b3   = (const float*)d_in[18];
    const float* wd   = (const float*)d_in[19];
    const float* wr   = (const float*)d_in[20];
    const float* wdnn = (const float*)d_in[21];
    float* out = (float*)d_out;

    int P = in_sizes[3];   // number of user/item pairs

    void *p_h0, *p_bufA, *p_w2hi, *p_w2lo, *p_w3hi, *p_w3lo;
    cudaGetSymbolAddress(&p_h0, d_h0);
    cudaGetSymbolAddress(&p_bufA, d_bufA);
    cudaGetSymbolAddress(&p_w2hi, d_W2hi);
    cudaGetSymbolAddress(&p_w2lo, d_W2lo);
    cudaGetSymbolAddress(&p_w3hi, d_W3hi);
    cudaGetSymbolAddress(&p_w3lo, d_W3lo);
    float* h0   = (float*)p_h0;
    float* bufA = (float*)p_bufA;

    cudaFuncSetAttribute(k_transform_mma,
                         cudaFuncAttributeMaxDynamicSharedMemorySize, SMEM_MMA);
    cudaFuncSetAttribute(k_transform_mma_idx,
                         cudaFuncAttributeMaxDynamicSharedMemorySize, SMEM_MMA);

    k_setup<<<SB_TOTAL, 256>>>(W2, W3, ei + EE, Hd, wr);
    k_phase2<<<65, 1024>>>(wd);
    k_phase3<<<PB_TOTAL, 256>>>(ei, x, Wg);
    k_gcn_agg<<<GB_GCN + (2 * P + 255) / 256, 256>>>(bg, ui, ii, P);

    // GAT layer 1 (all nodes) + compact tail
    k_transform16<<<NN / 16, 128>>>(h0, W1, a1s, a1d);
    k_agg1<<<AB_AGG + AB_CMP, 256>>>(b1);

    // GAT layer 2: transform all nodes, aggregate only marked set
    k_transform_mma<<<dim3(NP / 128, 4), 256, SMEM_MMA>>>(
        (const __half*)p_w2hi, (const __half*)p_w2lo, a2s, a2d);
    k_agg2_idx<<<AB_AGG, 256>>>(b2);

    // GAT layer 3: transform only marked set (indexed), aggregate only listed nodes
    k_transform_mma_idx<<<dim3(NP / 128, 4), 256, SMEM_MMA>>>(
        (const __half*)p_w3hi, (const __half*)p_w3lo, a3s, a3d);
    k_gat_agg_list<<<(2 * P * 32 + 255) / 256, 256>>>(b3, bufA, ui, ii, P);

    k_final<<<(1024 * 32 + 255) / 256, 256>>>(bufA, ui, ii, wdnn, out);
}

// round 11
// speedup vs baseline: 3.0640x; 1.1212x over previous
#include <cuda_runtime.h>
#include <cuda_bf16.h>
#include <cuda_fp16.h>
#include <math.h>

#define NN 50000
#define NP 50048          // padded to 128
#define EE 800000
#define ET (EE + NN)      // edges + self loops
#define PIT 264           // smem row pitch (fp16): 33*16B -> LDSM conflict-free

// ---------------- scratch (device globals; no allocation allowed) ----------------
__device__ float d_T2[512 * 16];             // Hd @ Wr
__device__ float d_M[128 * 16];              // Wd @ T2
__device__ int   d_deg[NN];                  // starts 0; scan resets to 0 after use
__device__ int   d_rowoff[NN + 1];
__device__ int   d_cursor[NN];               // gcn_agg resets to 0 after scatter
__device__ float d_dis[NN];
__device__ int   d_csr[ET];
__device__ float d_xw[NN * 16];
__device__ float d_dual[NN * 16];
__device__ float d_h0[NN * 16];
__device__ __half d_h1h[NP * 256];           // fp16 transformed features (agg gather)
__device__ __half d_Ah[NP * 256];            // fp16 input activations for MMA (pads stay 0)
__device__ float d_bufA[NN * 256];
__device__ float d_sa[NN * 16];
__device__ float d_da[NN * 16];
__device__ __half d_W2hi[256 * 256];         // W2^T split [n][k]  fp16 hi
__device__ __half d_W2lo[256 * 256];
__device__ __half d_W3hi[256 * 256];
__device__ __half d_W3lo[256 * 256];
__device__ int   d_mark[NN];                 // zero-init; compact resets to 0
__device__ int   d_list[NN];
__device__ int   d_listcnt;

// ================= merged SETUP: prepW | count | gemmA =================
#define SB_PREPW 512
#define SB_COUNT 782
#define SB_GEMMA 1024
#define SB_TOTAL (SB_PREPW + SB_COUNT + SB_GEMMA)

__global__ void k_setup(const float* __restrict__ W2, const float* __restrict__ W3,
                        const int* __restrict__ dst,
                        const float* __restrict__ hd, const float* __restrict__ wr) {
    int bid = blockIdx.x, tid = threadIdx.x;
    if (bid < SB_PREPW) {
        int idx = bid * 256 + tid;
        int sel = idx >> 16;
        int r = idx & 65535;
        int n = r >> 8, k = r & 255;
        float w = (sel ? W3 : W2)[k * 256 + n];
        __half h = __float2half_rn(w);
        __half l = __float2half_rn(w - __half2float(h));
        if (sel) { d_W3hi[r] = h; d_W3lo[r] = l; }
        else     { d_W2hi[r] = h; d_W2lo[r] = l; }
    } else if (bid < SB_PREPW + SB_COUNT) {
        int t = (bid - SB_PREPW) * 256 + tid;
        int e0 = t * 4;
        if (e0 + 3 < EE) {
            int4 d4 = *(const int4*)(dst + e0);
            atomicAdd(&d_deg[d4.x], 1);
            atomicAdd(&d_deg[d4.y], 1);
            atomicAdd(&d_deg[d4.z], 1);
            atomicAdd(&d_deg[d4.w], 1);
        } else {
            for (int e = e0; e < EE; e++) atomicAdd(&d_deg[dst[e]], 1);
        }
    } else {
        int w = ((bid - SB_PREPW - SB_COUNT) * 256 + tid) >> 5;
        int lane = tid & 31;
        int i = w >> 4, j = w & 15;
        float a = 0.f;
#pragma unroll
        for (int kk = 0; kk < 16; kk++) {
            int k = lane + kk * 32;
            a += hd[i * 512 + k] * wr[k * 16 + j];
        }
#pragma unroll
        for (int off = 16; off >= 1; off >>= 1)
            a += __shfl_down_sync(0xffffffffu, a, off);
        if (lane == 0) d_T2[w] = a;
    }
}

// ================= merged PHASE2: scan (block 0) | gemmB =================
__global__ void __launch_bounds__(1024)
k_phase2(const float* __restrict__ wd) {
    if (blockIdx.x == 0) {
        __shared__ int warp_sums[32];
        int t = threadIdx.x;
        const int S = 49;
        int b0 = t * S;
        int sum = 0;
        for (int i = 0; i < S; i++) {
            int idx = b0 + i;
            if (idx < NN) sum += d_deg[idx] + 1;
        }
        int lane = t & 31, w = t >> 5;
        int v = sum;
#pragma unroll
        for (int off = 1; off < 32; off <<= 1) {
            int u = __shfl_up_sync(0xffffffffu, v, off);
            if (lane >= off) v += u;
        }
        if (lane == 31) warp_sums[w] = v;
        __syncthreads();
        if (w == 0) {
            int ws = warp_sums[lane];
#pragma unroll
            for (int off = 1; off < 32; off <<= 1) {
                int u = __shfl_up_sync(0xffffffffu, ws, off);
                if (lane >= off) ws += u;
            }
            warp_sums[lane] = ws;
        }
        __syncthreads();
        int ex = v - sum + (w > 0 ? warp_sums[w - 1] : 0);
        int run = ex;
        for (int i = 0; i < S; i++) {
            int idx = b0 + i;
            if (idx < NN) {
                int dg = d_deg[idx] + 1;
                d_deg[idx] = 0;
                run += dg;
                d_rowoff[idx + 1] = run;
                d_dis[idx] = rsqrtf((float)dg);
            }
        }
        if (t == 0) d_rowoff[0] = 0;
    } else {
        int w = (blockIdx.x - 1) * 32 + (threadIdx.x >> 5);
        int lane = threadIdx.x & 31;
        int i = w >> 4, j = w & 15;
        float a = 0.f;
#pragma unroll
        for (int kk = 0; kk < 16; kk++) {
            int k = lane + kk * 32;
            a += wd[i * 512 + k] * d_T2[k * 16 + j];
        }
#pragma unroll
        for (int off = 16; off >= 1; off >>= 1)
            a += __shfl_down_sync(0xffffffffu, a, off);
        if (lane == 0) d_M[w] = a;
    }
}

// ================= merged PHASE3: scatter | xw_dual =================
#define PB_SCAT ((ET + 255) / 256)
#define PB_XW (NN / 16)
#define PB_TOTAL (PB_SCAT + PB_XW)

__global__ void __launch_bounds__(256)
k_phase3(const int* __restrict__ ei, const float* __restrict__ x,
         const float* __restrict__ Wg) {
    int bid = blockIdx.x, tid = threadIdx.x;
    if (bid < PB_SCAT) {
        int e = bid * 256 + tid;
        if (e >= ET) return;
        int s, dd;
        if (e < EE) { s = ei[e]; dd = ei[EE + e]; }
        else        { s = dd = e - EE; }
        int p = atomicAdd(&d_cursor[dd], 1);
        d_csr[d_rowoff[dd] + p] = s;
    } else {
        __shared__ float sx[16][132];
        int nb = (bid - PB_SCAT) * 16;
        const float4* xs = (const float4*)(x + (size_t)nb * 128);
        for (int i = tid; i < 512; i += 256) {
            float4 v = xs[i];
            int r = i >> 5, c = (i & 31) * 4;
            sx[r][c] = v.x; sx[r][c + 1] = v.y; sx[r][c + 2] = v.z; sx[r][c + 3] = v.w;
        }
        __syncthreads();
        int nl = tid >> 4, j = tid & 15;
        float a = 0.f, b = 0.f;
#pragma unroll 4
        for (int k = 0; k < 128; k++) {
            float xv = sx[nl][k];
            a += xv * Wg[k * 16 + j];
            b += xv * d_M[k * 16 + j];
        }
        int n = nb + nl;
        d_xw[n * 16 + j] = a;
        d_dual[n * 16 + j] = b;
    }
}

// ======= merged: GCN aggregation (float4 channels, 4-edge unroll) | mark set =======
#define GB_GCN ((NN * 4 + 255) / 256)

__global__ void k_gcn_agg(const float* __restrict__ bg,
                          const int* __restrict__ ui, const int* __restrict__ ii,
                          int P) {
    int bid = blockIdx.x, tid = threadIdx.x;
    if (bid < GB_GCN) {
        int t = bid * 256 + tid;
        int g = t >> 2, c4 = t & 3;
        if (g >= NN) return;
        int beg = d_rowoff[g], end = d_rowoff[g + 1];
        float4 acc = make_float4(0.f, 0.f, 0.f, 0.f);
        int e = beg;
        for (; e + 3 < end; e += 4) {
            int s0 = d_csr[e], s1 = d_csr[e + 1], s2 = d_csr[e + 2], s3 = d_csr[e + 3];
            float ds0 = d_dis[s0], ds1 = d_dis[s1], ds2 = d_dis[s2], ds3 = d_dis[s3];
            float4 x0 = ((const float4*)(d_xw + s0 * 16))[c4];
            float4 x1 = ((const float4*)(d_xw + s1 * 16))[c4];
            float4 x2 = ((const float4*)(d_xw + s2 * 16))[c4];
            float4 x3 = ((const float4*)(d_xw + s3 * 16))[c4];
            acc.x += ds0 * x0.x + ds1 * x1.x + ds2 * x2.x + ds3 * x3.x;
            acc.y += ds0 * x0.y + ds1 * x1.y + ds2 * x2.y + ds3 * x3.y;
            acc.z += ds0 * x0.z + ds1 * x1.z + ds2 * x2.z + ds3 * x3.z;
            acc.w += ds0 * x0.w + ds1 * x1.w + ds2 * x2.w + ds3 * x3.w;
        }
        for (; e < end; e++) {
            int s = d_csr[e];
            float ds = d_dis[s];
            float4 xw = ((const float4*)(d_xw + s * 16))[c4];
            acc.x += ds * xw.x; acc.y += ds * xw.y;
            acc.z += ds * xw.z; acc.w += ds * xw.w;
        }
        float dg = d_dis[g];
        float4 du = ((const float4*)(d_dual + g * 16))[c4];
        float4 vo;
        vo.x = acc.x * dg + bg[c4 * 4 + 0] + du.x;
        vo.y = acc.y * dg + bg[c4 * 4 + 1] + du.y;
        vo.z = acc.z * dg + bg[c4 * 4 + 2] + du.z;
        vo.w = acc.w * dg + bg[c4 * 4 + 3] + du.w;
        vo.x = vo.x > 0.f ? vo.x : (__expf(vo.x) - 1.f);
        vo.y = vo.y > 0.f ? vo.y : (__expf(vo.y) - 1.f);
        vo.z = vo.z > 0.f ? vo.z : (__expf(vo.z) - 1.f);
        vo.w = vo.w > 0.f ? vo.w : (__expf(vo.w) - 1.f);
        ((float4*)(d_h0 + g * 16))[c4] = vo;
        if (c4 == 0) d_cursor[g] = 0;   // reset for next replay
    } else {
        int i = (bid - GB_GCN) * 256 + tid;
        if (i == 0) d_listcnt = 0;
        if (i < 2 * P) {
            int n = (i < P) ? ui[i] : ii[i - P];
            d_mark[n] = 1;
            int beg = d_rowoff[n], end = d_rowoff[n + 1];
            for (int e = beg; e < end; e++) d_mark[d_csr[e]] = 1;
        }
    }
}

// ---------------- GAT layer-1 transform (FIN=16, FFMA; writes fp16 h1) ----------------
__global__ void __launch_bounds__(128, 8)
k_transform16(const float* __restrict__ hin, const float* __restrict__ W,
              const float* __restrict__ asrc, const float* __restrict__ adst) {
    __shared__ float s[16][16];
    int tid = threadIdx.x;
    int nb = blockIdx.x * 16;
    const float4* hin4 = (const float4*)(hin + nb * 16);
    float4* s4 = (float4*)s;
    for (int t = tid; t < 16 * 16 / 4; t += 128) s4[t] = hin4[t];
    __syncthreads();

    int cg = tid & 63;
    int ng = tid >> 6;
    const float4* W4 = (const float4*)W;
    float4 acc[8];
#pragma unroll
    for (int r = 0; r < 8; r++) acc[r] = make_float4(0.f, 0.f, 0.f, 0.f);

#pragma unroll
    for (int k = 0; k < 16; k++) {
        float4 w = W4[k * 64 + cg];
#pragma unroll
        for (int r = 0; r < 8; r++) {
            float sv = s[ng * 8 + r][k];
            acc[r].x += sv * w.x; acc[r].y += sv * w.y;
            acc[r].z += sv * w.z; acc[r].w += sv * w.w;
        }
    }

    float4 as4 = ((const float4*)asrc)[cg];
    float4 ad4 = ((const float4*)adst)[cg];
#pragma unroll
    for (int r = 0; r < 8; r++) {
        int n = nb + ng * 8 + r;
        if (n >= NN) break;
        __half2 p0 = __floats2half2_rn(acc[r].x, acc[r].y);
        __half2 p1 = __floats2half2_rn(acc[r].z, acc[r].w);
        *(__half2*)&d_h1h[(size_t)n * 256 + cg * 4] = p0;
        *(__half2*)&d_h1h[(size_t)n * 256 + cg * 4 + 2] = p1;
        float vs = acc[r].x * as4.x + acc[r].y * as4.y + acc[r].z * as4.z + acc[r].w * as4.w;
        float vd = acc[r].x * ad4.x + acc[r].y * ad4.y + acc[r].z * ad4.z + acc[r].w * ad4.w;
        vs += __shfl_down_sync(0xffffffffu, vs, 2, 4);
        vs += __shfl_down_sync(0xffffffffu, vs, 1, 4);
        vd += __shfl_down_sync(0xffffffffu, vd, 2, 4);
        vd += __shfl_down_sync(0xffffffffu, vd, 1, 4);
        if ((cg & 3) == 0) {
            int h = cg >> 2;
            d_sa[n * 16 + h] = vs;
            d_da[n * 16 + h] = vd;
        }
    }
}

// ---------------- MMA helpers ----------------
#define MMA_F16(C, A0, A1, A2, A3, B0, B1)                                   \
    asm volatile(                                                            \
        "mma.sync.aligned.m16n8k16.row.col.f32.f16.f16.f32 "                 \
        "{%0,%1,%2,%3}, {%4,%5,%6,%7}, {%8,%9}, {%0,%1,%2,%3};\n"            \
        : "+f"(C[0]), "+f"(C[1]), "+f"(C[2]), "+f"(C[3])                     \
        : "r"(A0), "r"(A1), "r"(A2), "r"(A3), "r"(B0), "r"(B1))

#define LDSM4(R0, R1, R2, R3, ADDR)                                          \
    asm volatile("ldmatrix.sync.aligned.m8n8.x4.shared.b16 {%0,%1,%2,%3}, [%4];" \
        : "=r"(R0), "=r"(R1), "=r"(R2), "=r"(R3) : "r"(ADDR))

#define SMEM_MMA ((128 * PIT + 2 * 64 * PIT) * 2)

// mainloop + epilogue over one 64-col B slice; writes rows g0,g1 (-1 = skip)
static __device__ __forceinline__ void mma_core(__half* sA, __half* sBhi, __half* sBlo,
                                                int lane, int warp, int n0,
                                                const float* __restrict__ as_,
                                                const float* __restrict__ ad_,
                                                int g0, int g1) {
    float c[8][4];
#pragma unroll
    for (int t = 0; t < 8; t++)
#pragma unroll
        for (int j = 0; j < 4; j++) c[t][j] = 0.f;

    int rA = warp * 16 + (lane & 15);
    int kOff = (lane >> 4) << 3;
    unsigned aB = (unsigned)__cvta_generic_to_shared(sA + rA * PIT + kOff);
    int rB = lane & 15;
    unsigned bHiB = (unsigned)__cvta_generic_to_shared(sBhi + rB * PIT + kOff);
    unsigned bLoB = (unsigned)__cvta_generic_to_shared(sBlo + rB * PIT + kOff);

#pragma unroll 4
    for (int kc = 0; kc < 16; kc++) {
        unsigned ka = kc * 32;
        unsigned a0, a1, a2, a3;
        LDSM4(a0, a1, a2, a3, aB + ka);
#pragma unroll
        for (int p = 0; p < 4; p++) {
            unsigned boff = (unsigned)(p * 16 * PIT * 2) + ka;
            unsigned bh0, bh1, bh2, bh3, bl0, bl1, bl2, bl3;
            LDSM4(bh0, bh1, bh2, bh3, bHiB + boff);
            LDSM4(bl0, bl1, bl2, bl3, bLoB + boff);
            MMA_F16(c[2 * p],     a0, a1, a2, a3, bh0, bh2);
            MMA_F16(c[2 * p],     a0, a1, a2, a3, bl0, bl2);
            MMA_F16(c[2 * p + 1], a0, a1, a2, a3, bh1, bh3);
            MMA_F16(c[2 * p + 1], a0, a1, a2, a3, bl1, bl3);
        }
    }

    int H0 = n0 >> 4;
    int cbase = (lane & 3) * 2;
    float vs0[4] = {0, 0, 0, 0}, vd0[4] = {0, 0, 0, 0};
    float vs1[4] = {0, 0, 0, 0}, vd1[4] = {0, 0, 0, 0};
#pragma unroll
    for (int t = 0; t < 8; t++) {
        int col = n0 + t * 8 + cbase;
        if (g0 >= 0)
            *(__half2*)&d_h1h[(size_t)g0 * 256 + col] = __floats2half2_rn(c[t][0], c[t][1]);
        if (g1 >= 0)
            *(__half2*)&d_h1h[(size_t)g1 * 256 + col] = __floats2half2_rn(c[t][2], c[t][3]);
        float2 a2 = *(const float2*)&as_[col];
        float2 d2 = *(const float2*)&ad_[col];
        int hh = t >> 1;
        vs0[hh] += c[t][0] * a2.x + c[t][1] * a2.y;
        vd0[hh] += c[t][0] * d2.x + c[t][1] * d2.y;
        vs1[hh] += c[t][2] * a2.x + c[t][3] * a2.y;
        vd1[hh] += c[t][2] * d2.x + c[t][3] * d2.y;
    }
#pragma unroll
    for (int hh = 0; hh < 4; hh++) {
        vs0[hh] += __shfl_down_sync(0xffffffffu, vs0[hh], 2, 4);
        vs0[hh] += __shfl_down_sync(0xffffffffu, vs0[hh], 1, 4);
        vd0[hh] += __shfl_down_sync(0xffffffffu, vd0[hh], 2, 4);
        vd0[hh] += __shfl_down_sync(0xffffffffu, vd0[hh], 1, 4);
        vs1[hh] += __shfl_down_sync(0xffffffffu, vs1[hh], 2, 4);
        vs1[hh] += __shfl_down_sync(0xffffffffu, vs1[hh], 1, 4);
        vd1[hh] += __shfl_down_sync(0xffffffffu, vd1[hh], 2, 4);
        vd1[hh] += __shfl_down_sync(0xffffffffu, vd1[hh], 1, 4);
    }
    if ((lane & 3) == 0) {
        if (g0 >= 0 && g0 < NN) {
#pragma unroll
            for (int hh = 0; hh < 4; hh++) {
                d_sa[g0 * 16 + H0 + hh] = vs0[hh];
                d_da[g0 * 16 + H0 + hh] = vd0[hh];
            }
        }
        if (g1 >= 0 && g1 < NN) {
#pragma unroll
            for (int hh = 0; hh < 4; hh++) {
                d_sa[g1 * 16 + H0 + hh] = vs1[hh];
                d_da[g1 * 16 + H0 + hh] = vd1[hh];
            }
        }
    }
}

static __device__ __forceinline__ void stage_B(__half* sBhi, __half* sBlo,
                                               const __half* __restrict__ Bhi,
                                               const __half* __restrict__ Blo,
                                               int n0, int tid) {
    const uint4* bH = (const uint4*)(Bhi + (size_t)n0 * 256);
    const uint4* bL = (const uint4*)(Blo + (size_t)n0 * 256);
    for (int i = tid; i < 64 * 32; i += 256) {
        int r = i >> 5, c = i & 31;
        *(uint4*)(sBhi + r * PIT + c * 8) = bH[r * 32 + c];
        *(uint4*)(sBlo + r * PIT + c * 8) = bL[r * 32 + c];
    }
}

// layer-2: all rows; 2 sequential 64-col slices per block (A staged once)
__global__ void __launch_bounds__(256, 1)
k_transform_mma(const __half* __restrict__ Bhi, const __half* __restrict__ Blo,
                const float* __restrict__ as_, const float* __restrict__ ad_) {
    extern __shared__ __half sm[];
    __half* sA = sm;
    __half* sBhi = sA + 128 * PIT;
    __half* sBlo = sBhi + 64 * PIT;
    int tid = threadIdx.x, lane = tid & 31, warp = tid >> 5;
    int m0 = blockIdx.x * 128;
    {
        const uint4* gA = (const uint4*)(d_Ah + (size_t)m0 * 256);
        for (int i = tid; i < 128 * 32; i += 256) {
            int r = i >> 5, c = i & 31;
            *(uint4*)(sA + r * PIT + c * 8) = gA[r * 32 + c];
        }
    }
    int g0 = m0 + warp * 16 + (lane >> 2);
#pragma unroll
    for (int s = 0; s < 2; s++) {
        int n0 = blockIdx.y * 128 + s * 64;
        stage_B(sBhi, sBlo, Bhi, Blo, n0, tid);
        __syncthreads();
        mma_core(sA, sBhi, sBlo, lane, warp, n0, as_, ad_, g0, g0 + 8);
        __syncthreads();
    }
}

// layer-3: only listed rows (gather A by index, scatter outputs)
__global__ void __launch_bounds__(256, 1)
k_transform_mma_idx(const __half* __restrict__ Bhi, const __half* __restrict__ Blo,
                    const float* __restrict__ as_, const float* __restrict__ ad_) {
    extern __shared__ __half sm[];
    __shared__ int snode[128];
    __half* sA = sm;
    __half* sBhi = sA + 128 * PIT;
    __half* sBlo = sBhi + 64 * PIT;
    int tid = threadIdx.x, lane = tid & 31, warp = tid >> 5;
    int m0 = blockIdx.x * 128;
    int cnt = d_listcnt;
    if (m0 >= cnt) return;
    for (int i = tid; i < 128; i += 256) {
        int r = m0 + i;
        snode[i] = (r < cnt) ? d_list[r] : -1;
    }
    __syncthreads();
    for (int i = tid; i < 128 * 32; i += 256) {
        int r = i >> 5, c = i & 31;
        int nd = snode[r];
        uint4 v = make_uint4(0, 0, 0, 0);
        if (nd >= 0) v = ((const uint4*)(d_Ah + (size_t)nd * 256))[c];
        *(uint4*)(sA + r * PIT + c * 8) = v;
    }
    int r0 = warp * 16 + (lane >> 2);
#pragma unroll
    for (int s = 0; s < 2; s++) {
        int n0 = blockIdx.y * 128 + s * 64;
        stage_B(sBhi, sBlo, Bhi, Blo, n0, tid);
        __syncthreads();
        mma_core(sA, sBhi, sBlo, lane, warp, n0, as_, ad_, snode[r0], snode[r0 + 8]);
        __syncthreads();
    }
}

// ---------------- GAT aggregation body: 4-edge branchless online softmax ----------------
template <bool SPLIT>
static __device__ __forceinline__ void gat_body(int n, int lane,
                                                const float* __restrict__ b,
                                                float* __restrict__ outf) {
    int hd = lane >> 1;
    float da_l = d_da[n * 16 + hd];
    int beg = d_rowoff[n], end = d_rowoff[n + 1];

    float m = -1e30f, z = 0.f;
    float acc[8];
#pragma unroll
    for (int i = 0; i < 8; i++) acc[i] = 0.f;

    int e = beg;
    for (; e + 3 < end; e += 4) {
        int s0 = d_csr[e], s1 = d_csr[e + 1], s2 = d_csr[e + 2], s3 = d_csr[e + 3];
        float l0 = d_sa[s0 * 16 + hd] + da_l;
        float l1 = d_sa[s1 * 16 + hd] + da_l;
        float l2 = d_sa[s2 * 16 + hd] + da_l;
        float l3 = d_sa[s3 * 16 + hd] + da_l;
        uint4 hv0 = *(const uint4*)(d_h1h + (size_t)s0 * 256 + lane * 8);
        uint4 hv1 = *(const uint4*)(d_h1h + (size_t)s1 * 256 + lane * 8);
        uint4 hv2 = *(const uint4*)(d_h1h + (size_t)s2 * 256 + lane * 8);
        uint4 hv3 = *(const uint4*)(d_h1h + (size_t)s3 * 256 + lane * 8);
        l0 = l0 > 0.f ? l0 : 0.2f * l0;
        l1 = l1 > 0.f ? l1 : 0.2f * l1;
        l2 = l2 > 0.f ? l2 : 0.2f * l2;
        l3 = l3 > 0.f ? l3 : 0.2f * l3;
        float nm = fmaxf(fmaxf(m, fmaxf(l0, l1)), fmaxf(l2, l3));
        float sc = __expf(m - nm);
        float e0 = __expf(l0 - nm), e1 = __expf(l1 - nm);
        float e2 = __expf(l2 - nm), e3 = __expf(l3 - nm);
        m = nm;
        z = z * sc + (e0 + e1) + (e2 + e3);
        float2 f0 = __half22float2(*(__half2*)&hv0.x), f1 = __half22float2(*(__half2*)&hv0.y);
        float2 f2 = __half22float2(*(__half2*)&hv0.z), f3 = __half22float2(*(__half2*)&hv0.w);
        float2 g0 = __half22float2(*(__half2*)&hv1.x), g1 = __half22float2(*(__half2*)&hv1.y);
        float2 g2 = __half22float2(*(__half2*)&hv1.z), g3 = __half22float2(*(__half2*)&hv1.w);
        float2 p0 = __half22float2(*(__half2*)&hv2.x), p1 = __half22float2(*(__half2*)&hv2.y);
        float2 p2 = __half22float2(*(__half2*)&hv2.z), p3 = __half22float2(*(__half2*)&hv2.w);
        float2 q0 = __half22float2(*(__half2*)&hv3.x), q1 = __half22float2(*(__half2*)&hv3.y);
        float2 q2 = __half22float2(*(__half2*)&hv3.z), q3 = __half22float2(*(__half2*)&hv3.w);
        acc[0] = acc[0] * sc + (e0 * f0.x + e1 * g0.x) + (e2 * p0.x + e3 * q0.x);
        acc[1] = acc[1] * sc + (e0 * f0.y + e1 * g0.y) + (e2 * p0.y + e3 * q0.y);
        acc[2] = acc[2] * sc + (e0 * f1.x + e1 * g1.x) + (e2 * p1.x + e3 * q1.x);
        acc[3] = acc[3] * sc + (e0 * f1.y + e1 * g1.y) + (e2 * p1.y + e3 * q1.y);
        acc[4] = acc[4] * sc + (e0 * f2.x + e1 * g2.x) + (e2 * p2.x + e3 * q2.x);
        acc[5] = acc[5] * sc + (e0 * f2.y + e1 * g2.y) + (e2 * p2.y + e3 * q2.y);
        acc[6] = acc[6] * sc + (e0 * f3.x + e1 * g3.x) + (e2 * p3.x + e3 * q3.x);
        acc[7] = acc[7] * sc + (e0 * f3.y + e1 * g3.y) + (e2 * p3.y + e3 * q3.y);
    }
    for (; e < end; e++) {
        int s0 = d_csr[e];
        float l0 = d_sa[s0 * 16 + hd] + da_l;
        uint4 hv0 = *(const uint4*)(d_h1h + (size_t)s0 * 256 + lane * 8);
        l0 = l0 > 0.f ? l0 : 0.2f * l0;
        float nm = fmaxf(m, l0);
        float sc = __expf(m - nm);
        float e0 = __expf(l0 - nm);
        m = nm;
        z = z * sc + e0;
        float2 f0 = __half22float2(*(__half2*)&hv0.x), f1 = __half22float2(*(__half2*)&hv0.y);
        float2 f2 = __half22float2(*(__half2*)&hv0.z), f3 = __half22float2(*(__half2*)&hv0.w);
        acc[0] = acc[0] * sc + e0 * f0.x;
        acc[1] = acc[1] * sc + e0 * f0.y;
        acc[2] = acc[2] * sc + e0 * f1.x;
        acc[3] = acc[3] * sc + e0 * f1.y;
        acc[4] = acc[4] * sc + e0 * f2.x;
        acc[5] = acc[5] * sc + e0 * f2.y;
        acc[6] = acc[6] * sc + e0 * f3.x;
        acc[7] = acc[7] * sc + e0 * f3.y;
    }

    float invz = 1.f / (z + 1e-16f);
    float vo[8];
#pragma unroll
    for (int i = 0; i < 8; i++) {
        float v = acc[i] * invz + b[lane * 8 + i];
        vo[i] = v > 0.f ? v : (__expf(v) - 1.f);
    }
    if (SPLIT) {
        __half2 h0 = __floats2half2_rn(vo[0], vo[1]);
        __half2 h1 = __floats2half2_rn(vo[2], vo[3]);
        __half2 h2 = __floats2half2_rn(vo[4], vo[5]);
        __half2 h3 = __floats2half2_rn(vo[6], vo[7]);
        uint4 pk;
        pk.x = *(unsigned*)&h0; pk.y = *(unsigned*)&h1;
        pk.z = *(unsigned*)&h2; pk.w = *(unsigned*)&h3;
        *(uint4*)&d_Ah[(size_t)n * 256 + lane * 8] = pk;
    } else {
        *(float4*)&outf[(size_t)n * 256 + lane * 8] = make_float4(vo[0], vo[1], vo[2], vo[3]);
        *(float4*)&outf[(size_t)n * 256 + lane * 8 + 4] = make_float4(vo[4], vo[5], vo[6], vo[7]);
    }
}

// layer-1 agg (all nodes) | compact tail blocks
#define AB_AGG ((NN * 32) / 256)
#define AB_CMP ((NN + 255) / 256)

__global__ void k_agg1(const float* __restrict__ b) {
    int bid = blockIdx.x;
    if (bid < AB_AGG) {
        int n = (bid * 256 + threadIdx.x) >> 5;
        if (n >= NN) return;
        gat_body<true>(n, threadIdx.x & 31, b, nullptr);
    } else {
        int i = (bid - AB_AGG) * 256 + threadIdx.x;
        if (i < NN && d_mark[i]) {
            int pos = atomicAdd(&d_listcnt, 1);
            d_list[pos] = i;
            d_mark[i] = 0;
        }
    }
}

// layer-2 agg: only listed nodes
__global__ void k_agg2_idx(const float* __restrict__ b) {
    int i = (blockIdx.x * blockDim.x + threadIdx.x) >> 5;
    if (i >= d_listcnt) return;
    gat_body<true>(d_list[i], threadIdx.x & 31, b, nullptr);
}

// layer-3: aggregate ONLY the user/item nodes
__global__ void k_gat_agg_list(const float* __restrict__ b, float* __restrict__ outf,
                               const int* __restrict__ ui, const int* __restrict__ ii,
                               int P) {
    int i = (blockIdx.x * blockDim.x + threadIdx.x) >> 5;
    if (i >= 2 * P) return;
    int n = (i < P) ? ui[i] : ii[i - P];
    gat_body<false>(n, threadIdx.x & 31, b, outf);
}

// ---------------- final ----------------
__global__ void k_final(const float* __restrict__ h, const int* __restrict__ ui,
                        const int* __restrict__ ii, const float* __restrict__ Wd,
                        float* __restrict__ out) {
    int p = (blockIdx.x * blockDim.x + threadIdx.x) >> 5;
    if (p >= 1024) return;
    int lane = threadIdx.x & 31;
    int u = ui[p], it = ii[p];
    float a0 = 0.f, a1 = 0.f;
    for (int k = lane; k < 256; k += 32) {
        float v = h[u * 256 + k];
        a0 += v * Wd[k * 2 + 0];
        a1 += v * Wd[k * 2 + 1];
        float w = h[it * 256 + k];
        a0 += w * Wd[(256 + k) * 2 + 0];
        a1 += w * Wd[(256 + k) * 2 + 1];
    }
#pragma unroll
    for (int off = 16; off >= 1; off >>= 1) {
        a0 += __shfl_down_sync(0xffffffffu, a0, off);
        a1 += __shfl_down_sync(0xffffffffu, a1, off);
    }
    if (lane == 0) {
        float mx = fmaxf(a0, a1);
        float lse = mx + __logf(__expf(a0 - mx) + __expf(a1 - mx));
        out[p * 2 + 0] = a0 - lse;
        out[p * 2 + 1] = a1 - lse;
    }
}

// ---------------- launcher ----------------
extern "C" void kernel_launch(void* const* d_in, const int* in_sizes, int n_in,
                              void* d_out, int out_size) {
    const float* x    = (const float*)d_in[0];
    const int*   ei   = (const int*)d_in[1];
    const float* Hd   = (const float*)d_in[2];
    const int*   ui   = (const int*)d_in[3];
    const int*   ii   = (const int*)d_in[4];
    const float* Wg   = (const float*)d_in[5];
    const float* bg   = (const float*)d_in[6];
    const float* W1   = (const float*)d_in[7];
    const float* a1s  = (const float*)d_in[8];
    const float* a1d  = (const float*)d_in[9];
    const float* b1   = (const float*)d_in[10];
    const float* W2   = (const float*)d_in[11];
    const float* a2s  = (const float*)d_in[12];
    const float* a2d  = (const float*)d_in[13];
    const float* b2   = (const float*)d_in[14];
    const float* W3   = (const float*)d_in[15];
    const float* a3s  = (const float*)d_in[16];
    const float* a3d  = (const float*)d_in[17];
    const float* b3   = (const float*)d_in[18];
    const float* wd   = (const float*)d_in[19];
    const float* wr   = (const float*)d_in[20];
    const float* wdnn = (const float*)d_in[21];
    float* out = (float*)d_out;

    int P = in_sizes[3];   // number of user/item pairs

    void *p_h0, *p_bufA, *p_w2hi, *p_w2lo, *p_w3hi, *p_w3lo;
    cudaGetSymbolAddress(&p_h0, d_h0);
    cudaGetSymbolAddress(&p_bufA, d_bufA);
    cudaGetSymbolAddress(&p_w2hi, d_W2hi);
    cudaGetSymbolAddress(&p_w2lo, d_W2lo);
    cudaGetSymbolAddress(&p_w3hi, d_W3hi);
    cudaGetSymbolAddress(&p_w3lo, d_W3lo);
    float* h0   = (float*)p_h0;
    float* bufA = (float*)p_bufA;

    cudaFuncSetAttribute(k_transform_mma,
                         cudaFuncAttributeMaxDynamicSharedMemorySize, SMEM_MMA);
    cudaFuncSetAttribute(k_transform_mma_idx,
                         cudaFuncAttributeMaxDynamicSharedMemorySize, SMEM_MMA);

    k_setup<<<SB_TOTAL, 256>>>(W2, W3, ei + EE, Hd, wr);
    k_phase2<<<65, 1024>>>(wd);
    k_phase3<<<PB_TOTAL, 256>>>(ei, x, Wg);
    k_gcn_agg<<<GB_GCN + (2 * P + 255) / 256, 256>>>(bg, ui, ii, P);

    // GAT layer 1 (all nodes) + compact tail
    k_transform16<<<NN / 16, 128>>>(h0, W1, a1s, a1d);
    k_agg1<<<AB_AGG + AB_CMP, 256>>>(b1);

    // GAT layer 2: transform all nodes (A staged once per block, 2 B slices)
    k_transform_mma<<<dim3(NP / 128, 2), 256, SMEM_MMA>>>(
        (const __half*)p_w2hi, (const __half*)p_w2lo, a2s, a2d);
    k_agg2_idx<<<AB_AGG, 256>>>(b2);

    // GAT layer 3: transform only marked set (indexed), aggregate only listed nodes
    k_transform_mma_idx<<<dim3(NP / 128, 2), 256, SMEM_MMA>>>(
        (const __half*)p_w3hi, (const __half*)p_w3lo, a3s, a3d);
    k_gat_agg_list<<<(2 * P * 32 + 255) / 256, 256>>>(b3, bufA, ui, ii, P);

    k_final<<<(1024 * 32 + 255) / 256, 256>>>(bufA, ui, ii, wdnn, out);
}